// round 8
// baseline (speedup 1.0000x reference)
#include <cuda_runtime.h>
#include <cuda_bf16.h>
#include <math.h>
#include <stdint.h>

#define NN   65536
#define GG   1024
#define NPG  64
#define VV   32
#define HH   128
#define EE   1048576
#define NOUT 10

// ---------------- scratch (device globals; no allocation allowed) ----------------
__device__ float d_h2  [NN*HH];
__device__ int   d_cntm[GG*NPG*NPG];
__device__ float d_vn  [GG*VV*HH];
__device__ float d_vn2 [GG*VV*HH];
__device__ float d_gf2 [GG*HH];
__device__ float d_wc  [HH*HH];
__device__ float d_bc  [HH];
__device__ __nv_bfloat16 d_wt0[6*HH*HH];
__device__ __nv_bfloat16 d_wt1[6*HH*HH];

// ================= helpers =================
__device__ __forceinline__ uint32_t smem_u32(const void* p) {
    uint32_t a;
    asm("{ .reg .u64 t; cvta.to.shared.u64 t, %1; cvt.u32.u64 %0, t; }" : "=r"(a) : "l"(p));
    return a;
}
__device__ __forceinline__ uint32_t pack_bf16x2(__nv_bfloat16 lo, __nv_bfloat16 hi) {
    return (uint32_t)__bfloat16_as_ushort(lo) | ((uint32_t)__bfloat16_as_ushort(hi) << 16);
}
__device__ __forceinline__ uint32_t tile_off(int r, int k) {
    uint32_t base = ((((uint32_t)k >> 6) * 16u + ((uint32_t)r >> 3)) << 10)
                  + (((uint32_t)r & 7) << 7) + (((uint32_t)k & 63) << 1);
    return base ^ ((base >> 3) & 0x70);
}
__device__ __forceinline__ uint32_t frag_addr(uint32_t base, int r, int k) {
    return base + (((uint32_t)k >> 6) << 14) + (((uint32_t)r >> 3) << 10)
         + (((uint32_t)r & 7) << 7) + ((((uint32_t)k & 63) << 1) ^ (((uint32_t)r & 7) << 4));
}
__device__ __forceinline__ void ldsm4(uint32_t* r, uint32_t addr) {
    asm volatile("ldmatrix.sync.aligned.m8n8.x4.shared.b16 {%0,%1,%2,%3}, [%4];"
        : "=r"(r[0]), "=r"(r[1]), "=r"(r[2]), "=r"(r[3]) : "r"(addr));
}
__device__ __forceinline__ void mma16816(float* c, const uint32_t* a, const uint32_t* b) {
    asm volatile("mma.sync.aligned.m16n8k16.row.col.f32.bf16.bf16.f32 "
        "{%0,%1,%2,%3}, {%4,%5,%6,%7}, {%8,%9}, {%0,%1,%2,%3};"
        : "+f"(c[0]), "+f"(c[1]), "+f"(c[2]), "+f"(c[3])
        : "r"(a[0]), "r"(a[1]), "r"(a[2]), "r"(a[3]), "r"(b[0]), "r"(b[1]));
}

#define SA0 0
#define SA1 32768
#define SB0 65536
#define SB1 98304
#define GSM_TOTAL 131072
#define SC  131072
#define SINV 163840
#define XGCN_SMEM 164352
// fused aff-mlp + attention kernel
#define H2F  131072               // fp32 h2 tile, 64 KB
#define VEMT 65536                // vembT (2 graphs x 128 x 33 fp32 = 33792 B) in dead SB
#define SEW  99328                // ew (128 x 32 fp32 = 16384 B)
#define AFAT_SMEM 196608
#define NT 512

// stage fp32 A tile (128x128) -> bf16 hi/lo split, swizzled
__device__ __forceinline__ void stage_A(char* smem, const float* __restrict__ A,
                                        int row0, int tid) {
    const float4* A4 = (const float4*)(A + (size_t)row0 * 128);
#pragma unroll
    for (int i = tid; i < 4096; i += NT) {
        int r = i >> 5, k = (i & 31) << 2;
        float4 a = A4[i];
        __nv_bfloat16 hx = __float2bfloat16(a.x), hy = __float2bfloat16(a.y);
        __nv_bfloat16 hz = __float2bfloat16(a.z), hw = __float2bfloat16(a.w);
        __nv_bfloat16 lx = __float2bfloat16(a.x - __bfloat162float(hx));
        __nv_bfloat16 ly = __float2bfloat16(a.y - __bfloat162float(hy));
        __nv_bfloat16 lz = __float2bfloat16(a.z - __bfloat162float(hz));
        __nv_bfloat16 lw = __float2bfloat16(a.w - __bfloat162float(hw));
        uint32_t sw = tile_off(r, k);
        *(uint2*)(smem + SA0 + sw) = make_uint2(pack_bf16x2(hx, hy), pack_bf16x2(hz, hw));
        *(uint2*)(smem + SA1 + sw) = make_uint2(pack_bf16x2(lx, ly), pack_bf16x2(lz, lw));
    }
}
__device__ __forceinline__ void stage_W(char* smem, const __nv_bfloat16* __restrict__ Wh,
                                        const __nv_bfloat16* __restrict__ Wl, int tid) {
    const uint2* H = (const uint2*)Wh;
    const uint2* L = (const uint2*)Wl;
#pragma unroll
    for (int i = tid; i < 4096; i += NT) {
        int n = i >> 5, k = (i & 31) << 2;
        uint32_t sw = tile_off(n, k);
        *(uint2*)(smem + SB0 + sw) = H[i];
        *(uint2*)(smem + SB1 + sw) = L[i];
    }
}
// NP-pass HMMA: warp grid 4(M) x 4(N), warp tile 32x32 -> acc[2][4][4]
template<int NP>
__device__ __forceinline__ void mma_passes(const uint32_t* al, const uint32_t* bl,
                                           int wid, int lid, float acc[2][4][4]) {
    const int m0w = (wid >> 2) * 32;
    const int n0w = (wid & 3) * 32;
    const int arow = m0w + (lid & 7) + ((lid >> 3) & 1) * 8;
    const int akad = (lid >> 4) * 8;
    const int brow0 = n0w + (lid & 7) + (lid >> 4) * 8;
    const int bkad = ((lid >> 3) & 1) * 8;
#pragma unroll
    for (int mf = 0; mf < 2; mf++)
#pragma unroll
        for (int nf = 0; nf < 4; nf++)
#pragma unroll
            for (int j = 0; j < 4; j++) acc[mf][nf][j] = 0.f;
#pragma unroll
    for (int p = 0; p < NP; p++) {
        const uint32_t ab = al[p], bb = bl[p];
#pragma unroll
        for (int k0 = 0; k0 < 128; k0 += 16) {
            uint32_t a[2][4], b[2][4];
            ldsm4(a[0], frag_addr(ab, arow,      k0 + akad));
            ldsm4(a[1], frag_addr(ab, arow + 16, k0 + akad));
            ldsm4(b[0], frag_addr(bb, brow0,      k0 + bkad));
            ldsm4(b[1], frag_addr(bb, brow0 + 16, k0 + bkad));
#pragma unroll
            for (int mf = 0; mf < 2; mf++)
#pragma unroll
                for (int nf = 0; nf < 4; nf++)
                    mma16816(acc[mf][nf], a[mf], &b[nf >> 1][(nf & 1) * 2]);
        }
    }
}

// ---------------- weight combine: Wc = W_emb @ W_gcn, bc = b_emb @ W_gcn ----------------
__global__ void __launch_bounds__(256) k_combine(const float* __restrict__ We,
                                                 const float* __restrict__ Wg,
                                                 const float* __restrict__ be,
                                                 float* __restrict__ Wc,
                                                 float* __restrict__ bc) {
    const int col = threadIdx.x & 127;
    const int rr  = threadIdx.x >> 7;
    for (int p = 0; p < 4; p++) {
        int row = blockIdx.x * 8 + p * 2 + rr;
        float s = 0.f;
#pragma unroll 8
        for (int k = 0; k < 128; k++) s += We[row * 128 + k] * Wg[k * 128 + col];
        Wc[row * 128 + col] = s;
    }
    if (blockIdx.x == 0 && threadIdx.x < 128) {
        float s = 0.f;
        for (int k = 0; k < 128; k++) s += be[k] * Wg[k * 128 + col];
        bc[col] = s;
    }
}

// ---------------- weight prep: transpose + bf16 hi/lo split ----------------
__global__ void __launch_bounds__(128) k_split(
    const float* W0, const float* W1, const float* W2, const float* W3,
    const float* W4, const float* W5,
    __nv_bfloat16* wt0, __nv_bfloat16* wt1)
{
    extern __shared__ float s[];
    const float* Ws[6] = {W0, W1, W2, W3, W4, W5};
    const float* W = Ws[blockIdx.x];
    for (int i = threadIdx.x; i < 16384; i += 128) s[i] = W[i];
    __syncthreads();
    const int n = threadIdx.x;
    uint32_t* o0 = (uint32_t*)(wt0 + (size_t)blockIdx.x * 16384 + n * 128);
    uint32_t* o1 = (uint32_t*)(wt1 + (size_t)blockIdx.x * 16384 + n * 128);
    for (int k = 0; k < 128; k += 2) {
        float v0 = s[k * 128 + n], v1 = s[(k + 1) * 128 + n];
        __nv_bfloat16 h0 = __float2bfloat16(v0), h1 = __float2bfloat16(v1);
        __nv_bfloat16 l0 = __float2bfloat16(v0 - __bfloat162float(h0));
        __nv_bfloat16 l1 = __float2bfloat16(v1 - __bfloat162float(h1));
        o0[k >> 1] = pack_bf16x2(h0, h1);
        o1[k >> 1] = pack_bf16x2(l0, l1);
    }
}

// ---------------- fused x-GEMM + GCN: h2 = relu(D^-1/2 (A+I) D^-1/2 (x@Wc+bc) + bg) ------
__global__ void __launch_bounds__(NT) k_xgcn(
    const float* __restrict__ x,
    const __nv_bfloat16* __restrict__ Wch, const __nv_bfloat16* __restrict__ Wcl,
    const float* __restrict__ bc, const float* __restrict__ b_gcn,
    const int* __restrict__ cntm,
    float* __restrict__ h2)
{
    extern __shared__ char smem[];
    const uint32_t sb = smem_u32(smem);
    const int tid = threadIdx.x, wid = tid >> 5, lid = tid & 31;
    const int row0 = blockIdx.x * 128;
    const int g0 = row0 >> 6;
    const int* cg = cntm + ((size_t)g0 << 12);
    float* sinv = (float*)(smem + SINV);

    for (int i = tid; i < 8192; i += NT) ((uint32_t*)(smem + SC))[i] = 0;

    stage_A(smem, x, row0, tid);
    stage_W(smem, Wch, Wcl, tid);
    __syncthreads();

    for (int i = tid; i < 8192; i += NT) {
        int gl = i >> 12;
        int s = (i >> 6) & 63, d = i & 63;
        float v = (float)cg[(gl << 12) + (s << 6) + d] + (s == d ? 1.f : 0.f);
        *(__nv_bfloat16*)(smem + SC + tile_off(gl * 64 + d, gl * 64 + s)) = __float2bfloat16(v);
    }
    if (tid < 128) {
        int gl = tid >> 6, dl = tid & 63;
        const int* cgg = cg + (gl << 12);
        int deg = 0;
#pragma unroll 8
        for (int s = 0; s < 64; s++) deg += cgg[(s << 6) + dl];
        sinv[tid] = rsqrtf((float)deg + 1.f);
    }

    const uint32_t al1[3] = {sb + SA0, sb + SA0, sb + SA1};
    const uint32_t bl1[3] = {sb + SB0, sb + SB1, sb + SB0};
    float acc[2][4][4];
    mma_passes<3>(al1, bl1, wid, lid, acc);

    const int m0w = (wid >> 2) * 32;
    const int n0w = (wid & 3) * 32;
    const int crow = lid >> 2;
    const int ccol = (lid & 3) * 2;

    __syncthreads();

#pragma unroll
    for (int mf = 0; mf < 2; mf++) {
        int r = m0w + mf * 16 + crow;
        float iv0 = sinv[r], iv1 = sinv[r + 8];
#pragma unroll
        for (int nf = 0; nf < 4; nf++) {
            int cn = n0w + nf * 8 + ccol;
            float2 bv = *(const float2*)(bc + cn);
            float v00 = (acc[mf][nf][0] + bv.x) * iv0;
            float v01 = (acc[mf][nf][1] + bv.y) * iv0;
            float v10 = (acc[mf][nf][2] + bv.x) * iv1;
            float v11 = (acc[mf][nf][3] + bv.y) * iv1;
            __nv_bfloat16 h00 = __float2bfloat16(v00), h01 = __float2bfloat16(v01);
            __nv_bfloat16 h10 = __float2bfloat16(v10), h11 = __float2bfloat16(v11);
            *(__nv_bfloat16*)(smem + SB0 + tile_off(cn,     r))     = h00;
            *(__nv_bfloat16*)(smem + SB0 + tile_off(cn + 1, r))     = h01;
            *(__nv_bfloat16*)(smem + SB0 + tile_off(cn,     r + 8)) = h10;
            *(__nv_bfloat16*)(smem + SB0 + tile_off(cn + 1, r + 8)) = h11;
            *(__nv_bfloat16*)(smem + SB1 + tile_off(cn,     r))     =
                __float2bfloat16(v00 - __bfloat162float(h00));
            *(__nv_bfloat16*)(smem + SB1 + tile_off(cn + 1, r))     =
                __float2bfloat16(v01 - __bfloat162float(h01));
            *(__nv_bfloat16*)(smem + SB1 + tile_off(cn,     r + 8)) =
                __float2bfloat16(v10 - __bfloat162float(h10));
            *(__nv_bfloat16*)(smem + SB1 + tile_off(cn + 1, r + 8)) =
                __float2bfloat16(v11 - __bfloat162float(h11));
        }
    }
    __syncthreads();

    const uint32_t al2[2] = {sb + SC, sb + SC};
    const uint32_t bl2[2] = {sb + SB0, sb + SB1};
    mma_passes<2>(al2, bl2, wid, lid, acc);

#pragma unroll
    for (int mf = 0; mf < 2; mf++) {
        int r = m0w + mf * 16 + crow;
        float iv0 = sinv[r], iv1 = sinv[r + 8];
        float* C0 = h2 + (size_t)(row0 + r) * 128;
#pragma unroll
        for (int nf = 0; nf < 4; nf++) {
            int cn = n0w + nf * 8 + ccol;
            float2 bg = *(const float2*)(b_gcn + cn);
            float2 v0 = make_float2(fmaxf(acc[mf][nf][0] * iv0 + bg.x, 0.f),
                                    fmaxf(acc[mf][nf][1] * iv0 + bg.y, 0.f));
            float2 v1 = make_float2(fmaxf(acc[mf][nf][2] * iv1 + bg.x, 0.f),
                                    fmaxf(acc[mf][nf][3] * iv1 + bg.y, 0.f));
            *(float2*)(C0 + cn)           = v0;
            *(float2*)(C0 + 8 * 128 + cn) = v1;
        }
    }
}

// ---------------- single GEMM: C[M,128] = [relu](A @ W + b) ----------------
template<int RELU, int BIAS, int MEANV>
__global__ void __launch_bounds__(NT) k_mma_gemm(
    const float* __restrict__ A,
    const __nv_bfloat16* __restrict__ Wt0,
    const __nv_bfloat16* __restrict__ Wt1,
    const float* __restrict__ bias,
    float* __restrict__ C)
{
    extern __shared__ char smem[];
    const uint32_t sb = smem_u32(smem);
    const int tid = threadIdx.x, wid = tid >> 5, lid = tid & 31;
    const int row0 = blockIdx.x * 128;

    if (MEANV) {
        for (int i = tid; i < 4096; i += NT) {
            int r = i >> 5, kq = i & 31;
            const float4* src = (const float4*)A + (size_t)(row0 + r) * VV * 32 + kq;
            float4 a = make_float4(0.f, 0.f, 0.f, 0.f);
#pragma unroll 8
            for (int v = 0; v < VV; v++) {
                float4 t = src[v * 32];
                a.x += t.x; a.y += t.y; a.z += t.z; a.w += t.w;
            }
            a.x *= (1.f/32.f); a.y *= (1.f/32.f); a.z *= (1.f/32.f); a.w *= (1.f/32.f);
            __nv_bfloat16 hx = __float2bfloat16(a.x), hy = __float2bfloat16(a.y);
            __nv_bfloat16 hz = __float2bfloat16(a.z), hw = __float2bfloat16(a.w);
            __nv_bfloat16 lx = __float2bfloat16(a.x - __bfloat162float(hx));
            __nv_bfloat16 ly = __float2bfloat16(a.y - __bfloat162float(hy));
            __nv_bfloat16 lz = __float2bfloat16(a.z - __bfloat162float(hz));
            __nv_bfloat16 lw = __float2bfloat16(a.w - __bfloat162float(hw));
            uint32_t sw = tile_off(r, kq << 2);
            *(uint2*)(smem + SA0 + sw) = make_uint2(pack_bf16x2(hx, hy), pack_bf16x2(hz, hw));
            *(uint2*)(smem + SA1 + sw) = make_uint2(pack_bf16x2(lx, ly), pack_bf16x2(lz, lw));
        }
    } else {
        stage_A(smem, A, row0, tid);
    }
    stage_W(smem, Wt0, Wt1, tid);
    __syncthreads();

    const uint32_t al[3] = {sb + SA0, sb + SA0, sb + SA1};
    const uint32_t bl[3] = {sb + SB0, sb + SB1, sb + SB0};
    float acc[2][4][4];
    mma_passes<3>(al, bl, wid, lid, acc);

    const int m0w = (wid >> 2) * 32;
    const int n0w = (wid & 3) * 32;
    const int crow = lid >> 2;
    const int ccol = (lid & 3) * 2;
#pragma unroll
    for (int mf = 0; mf < 2; mf++) {
        int gr = row0 + m0w + mf * 16 + crow;
        float* C0 = C + (size_t)gr * 128;
#pragma unroll
        for (int nf = 0; nf < 4; nf++) {
            int cn = n0w + nf * 8 + ccol;
            float2 bv = make_float2(0.f, 0.f);
            if (BIAS) bv = *(const float2*)(bias + cn);
            float2 v0 = make_float2(acc[mf][nf][0] + bv.x, acc[mf][nf][1] + bv.y);
            float2 v1 = make_float2(acc[mf][nf][2] + bv.x, acc[mf][nf][3] + bv.y);
            if (RELU) {
                v0.x = fmaxf(v0.x, 0.f); v0.y = fmaxf(v0.y, 0.f);
                v1.x = fmaxf(v1.x, 0.f); v1.y = fmaxf(v1.y, 0.f);
            }
            *(float2*)(C0 + cn)           = v0;
            *(float2*)(C0 + 8 * 128 + cn) = v1;
        }
    }
}

// ---------------- fused 2-layer MLP: Out = (relu(A@W1+b1))@W2 + b2 ----------------
__global__ void __launch_bounds__(NT) k_mlp2(
    const float* __restrict__ A,
    const __nv_bfloat16* __restrict__ W1h, const __nv_bfloat16* __restrict__ W1l,
    const float* __restrict__ b1,
    const __nv_bfloat16* __restrict__ W2h, const __nv_bfloat16* __restrict__ W2l,
    const float* __restrict__ b2,
    float* __restrict__ Out)
{
    extern __shared__ char smem[];
    const uint32_t sb = smem_u32(smem);
    const int tid = threadIdx.x, wid = tid >> 5, lid = tid & 31;
    const int row0 = blockIdx.x * 128;

    stage_A(smem, A, row0, tid);
    stage_W(smem, W1h, W1l, tid);
    __syncthreads();

    const uint32_t al[3] = {sb + SA0, sb + SA0, sb + SA1};
    const uint32_t bl[3] = {sb + SB0, sb + SB1, sb + SB0};
    float acc[2][4][4];
    mma_passes<3>(al, bl, wid, lid, acc);

    const int m0w = (wid >> 2) * 32;
    const int n0w = (wid & 3) * 32;
    const int crow = lid >> 2;
    const int ccol = (lid & 3) * 2;

    __syncthreads();

#pragma unroll
    for (int mf = 0; mf < 2; mf++) {
        int r = m0w + mf * 16 + crow;
#pragma unroll
        for (int nf = 0; nf < 4; nf++) {
            int cn = n0w + nf * 8 + ccol;
            float2 bv = *(const float2*)(b1 + cn);
            float tx = fmaxf(acc[mf][nf][0] + bv.x, 0.f);
            float ty = fmaxf(acc[mf][nf][1] + bv.y, 0.f);
            float ux = fmaxf(acc[mf][nf][2] + bv.x, 0.f);
            float uy = fmaxf(acc[mf][nf][3] + bv.y, 0.f);
            __nv_bfloat16 htx = __float2bfloat16(tx), hty = __float2bfloat16(ty);
            __nv_bfloat16 hux = __float2bfloat16(ux), huy = __float2bfloat16(uy);
            uint32_t sw0 = tile_off(r, cn);
            uint32_t sw1 = tile_off(r + 8, cn);
            *(uint32_t*)(smem + SA0 + sw0) = pack_bf16x2(htx, hty);
            *(uint32_t*)(smem + SA0 + sw1) = pack_bf16x2(hux, huy);
            *(uint32_t*)(smem + SA1 + sw0) = pack_bf16x2(
                __float2bfloat16(tx - __bfloat162float(htx)),
                __float2bfloat16(ty - __bfloat162float(hty)));
            *(uint32_t*)(smem + SA1 + sw1) = pack_bf16x2(
                __float2bfloat16(ux - __bfloat162float(hux)),
                __float2bfloat16(uy - __bfloat162float(huy)));
        }
    }
    stage_W(smem, W2h, W2l, tid);
    __syncthreads();

    mma_passes<3>(al, bl, wid, lid, acc);

#pragma unroll
    for (int mf = 0; mf < 2; mf++) {
        int gr = row0 + m0w + mf * 16 + crow;
        float* C0 = Out + (size_t)gr * 128;
#pragma unroll
        for (int nf = 0; nf < 4; nf++) {
            int cn = n0w + nf * 8 + ccol;
            float2 bv = *(const float2*)(b2 + cn);
            *(float2*)(C0 + cn) = make_float2(acc[mf][nf][0] + bv.x, acc[mf][nf][1] + bv.y);
            *(float2*)(C0 + 8 * 128 + cn) = make_float2(acc[mf][nf][2] + bv.x,
                                                        acc[mf][nf][3] + bv.y);
        }
    }
}

// ------ fused affinity MLP + attention + weighted pool (per block: 2 graphs) ------
__global__ void __launch_bounds__(NT) k_afat(
    const float* __restrict__ h2,
    const __nv_bfloat16* __restrict__ W1h, const __nv_bfloat16* __restrict__ W1l,
    const float* __restrict__ b1,
    const __nv_bfloat16* __restrict__ W2h, const __nv_bfloat16* __restrict__ W2l,
    const float* __restrict__ b2,
    const float* __restrict__ vemb,
    const float* __restrict__ eweights,
    float* __restrict__ vn_out)
{
    extern __shared__ char smem[];
    const uint32_t sb = smem_u32(smem);
    const int tid = threadIdx.x, wid = tid >> 5, lid = tid & 31;
    const int row0 = blockIdx.x * 128;
    const int g0 = row0 >> 6;

    // stage h2: bf16 split into SA + fp32 copy into H2F
    {
        const float4* A4 = (const float4*)(h2 + (size_t)row0 * 128);
        float4* h2f4 = (float4*)(smem + H2F);
#pragma unroll
        for (int i = tid; i < 4096; i += NT) {
            int r = i >> 5, k = (i & 31) << 2;
            float4 a = A4[i];
            h2f4[i] = a;
            __nv_bfloat16 hx = __float2bfloat16(a.x), hy = __float2bfloat16(a.y);
            __nv_bfloat16 hz = __float2bfloat16(a.z), hw = __float2bfloat16(a.w);
            __nv_bfloat16 lx = __float2bfloat16(a.x - __bfloat162float(hx));
            __nv_bfloat16 ly = __float2bfloat16(a.y - __bfloat162float(hy));
            __nv_bfloat16 lz = __float2bfloat16(a.z - __bfloat162float(hz));
            __nv_bfloat16 lw = __float2bfloat16(a.w - __bfloat162float(hw));
            uint32_t sw = tile_off(r, k);
            *(uint2*)(smem + SA0 + sw) = make_uint2(pack_bf16x2(hx, hy), pack_bf16x2(hz, hw));
            *(uint2*)(smem + SA1 + sw) = make_uint2(pack_bf16x2(lx, ly), pack_bf16x2(lz, lw));
        }
    }
    stage_W(smem, W1h, W1l, tid);
    __syncthreads();

    const uint32_t al[3] = {sb + SA0, sb + SA0, sb + SA1};
    const uint32_t bl[3] = {sb + SB0, sb + SB1, sb + SB0};
    float acc[2][4][4];
    mma_passes<3>(al, bl, wid, lid, acc);

    const int m0w = (wid >> 2) * 32;
    const int n0w = (wid & 3) * 32;
    const int crow = lid >> 2;
    const int ccol = (lid & 3) * 2;

    __syncthreads();

    // relu(t1) restage into SA
#pragma unroll
    for (int mf = 0; mf < 2; mf++) {
        int r = m0w + mf * 16 + crow;
#pragma unroll
        for (int nf = 0; nf < 4; nf++) {
            int cn = n0w + nf * 8 + ccol;
            float2 bv = *(const float2*)(b1 + cn);
            float tx = fmaxf(acc[mf][nf][0] + bv.x, 0.f);
            float ty = fmaxf(acc[mf][nf][1] + bv.y, 0.f);
            float ux = fmaxf(acc[mf][nf][2] + bv.x, 0.f);
            float uy = fmaxf(acc[mf][nf][3] + bv.y, 0.f);
            __nv_bfloat16 htx = __float2bfloat16(tx), hty = __float2bfloat16(ty);
            __nv_bfloat16 hux = __float2bfloat16(ux), huy = __float2bfloat16(uy);
            uint32_t sw0 = tile_off(r, cn);
            uint32_t sw1 = tile_off(r + 8, cn);
            *(uint32_t*)(smem + SA0 + sw0) = pack_bf16x2(htx, hty);
            *(uint32_t*)(smem + SA0 + sw1) = pack_bf16x2(hux, huy);
            *(uint32_t*)(smem + SA1 + sw0) = pack_bf16x2(
                __float2bfloat16(tx - __bfloat162float(htx)),
                __float2bfloat16(ty - __bfloat162float(hty)));
            *(uint32_t*)(smem + SA1 + sw1) = pack_bf16x2(
                __float2bfloat16(ux - __bfloat162float(hux)),
                __float2bfloat16(uy - __bfloat162float(huy)));
        }
    }
    stage_W(smem, W2h, W2l, tid);
    __syncthreads();

    mma_passes<3>(al, bl, wid, lid, acc);
    __syncthreads();   // done reading SA/SB; now repurpose them

    // aff fp32 -> [0, 64KB) (over SA0+SA1); stride 128 floats
    {
        float* affs = (float*)smem;
#pragma unroll
        for (int mf = 0; mf < 2; mf++) {
            int r = m0w + mf * 16 + crow;
            float* A0 = affs + r * 128;
            float* A8 = affs + (r + 8) * 128;
#pragma unroll
            for (int nf = 0; nf < 4; nf++) {
                int cn = n0w + nf * 8 + ccol;
                float2 bv = *(const float2*)(b2 + cn);
                A0[cn]     = acc[mf][nf][0] + bv.x;
                A0[cn + 1] = acc[mf][nf][1] + bv.y;
                A8[cn]     = acc[mf][nf][2] + bv.x;
                A8[cn + 1] = acc[mf][nf][3] + bv.y;
            }
        }
    }
    // vembT (2 graphs, [k][v] padded 33) into dead SB region
    {
        float* vembT = (float*)(smem + VEMT);
        const float* vg = vemb + (size_t)g0 * VV * HH;
        for (int i = tid; i < 2 * VV * HH; i += NT) {
            int gl = i >> 12;
            int v = (i >> 7) & 31, k = i & 127;
            vembT[gl * 4224 + k * 33 + v] = vg[i];
        }
    }
    __syncthreads();

    // attention scores + ew = eweights * (1 + sigmoid(att))
    {
        const float4* affs4 = (const float4*)smem;
        const float* vembT = (const float*)(smem + VEMT);
        float* sew = (float*)(smem + SEW);
        const int v  = tid & 31;
        const int ng = tid >> 5;            // 0..15
        const int gl = ng >> 3;             // graph within pair
        const int sub = ng & 7;
        const float* vT = vembT + gl * 4224;
        const float* ew_g = eweights + (size_t)(g0 + gl) * NPG * VV;
        const float scale = 0.08838834764831845f;
        for (int c = 0; c < 2; c++) {
            int nl0 = sub * 8 + c * 4;              // local n
            int n0g = gl * 64 + nl0;                // global row
            float acc0 = 0.f, acc1 = 0.f, acc2 = 0.f, acc3 = 0.f;
#pragma unroll 4
            for (int kq = 0; kq < 32; kq++) {
                float4 a0 = affs4[(n0g+0)*32 + kq];
                float4 a1 = affs4[(n0g+1)*32 + kq];
                float4 a2 = affs4[(n0g+2)*32 + kq];
                float4 a3 = affs4[(n0g+3)*32 + kq];
                float w0 = vT[(kq*4+0)*33 + v];
                float w1 = vT[(kq*4+1)*33 + v];
                float w2 = vT[(kq*4+2)*33 + v];
                float w3 = vT[(kq*4+3)*33 + v];
                acc0 += a0.x*w0 + a0.y*w1 + a0.z*w2 + a0.w*w3;
                acc1 += a1.x*w0 + a1.y*w1 + a1.z*w2 + a1.w*w3;
                acc2 += a2.x*w0 + a2.y*w1 + a2.z*w2 + a2.w*w3;
                acc3 += a3.x*w0 + a3.y*w1 + a3.z*w2 + a3.w*w3;
            }
            float accs[4] = {acc0, acc1, acc2, acc3};
#pragma unroll
            for (int j = 0; j < 4; j++) {
                float att = accs[j] * scale;
                float sg = 1.f / (1.f + expf(-att));
                sew[(n0g + j)*32 + v] = ew_g[(nl0 + j)*32 + v] * (1.f + sg);
            }
        }
    }
    __syncthreads();

    // row-normalize ew (128 global rows)
    {
        float* sew = (float*)(smem + SEW);
        if (tid < 128) {
            float rs = 0.f;
            for (int v2 = 0; v2 < VV; v2++) rs += sew[tid*32 + v2];
            float denom = (rs == 0.f) ? 1.f : rs;
            float ivr = 1.f / denom;
            for (int v2 = 0; v2 < VV; v2++) sew[tid*32 + v2] *= ivr;
        }
    }
    __syncthreads();

    // pooling: vn[g][v][h] = sum_n ew[n][v] * h2[n][h]
    {
        const float* sew = (const float*)(smem + SEW);
        const float4* h2f4 = (const float4*)(smem + H2F);
        const int c4  = tid & 31;
        const int grp = tid >> 5;          // 0..15
        const int gl  = grp >> 3;
        const int vb  = (grp & 7) * 4;
        float4 pacc[4];
#pragma unroll
        for (int u = 0; u < 4; u++) pacc[u] = make_float4(0.f, 0.f, 0.f, 0.f);
        for (int n = 0; n < NPG; n++) {
            int ng2 = gl * 64 + n;
            float4 hv = h2f4[ng2*32 + c4];
#pragma unroll
            for (int u = 0; u < 4; u++) {
                float w = sew[ng2*32 + vb + u];
                pacc[u].x += w*hv.x; pacc[u].y += w*hv.y;
                pacc[u].z += w*hv.z; pacc[u].w += w*hv.w;
            }
        }
#pragma unroll
        for (int u = 0; u < 4; u++)
            ((float4*)(vn_out + (size_t)((g0 + gl)*VV + vb + u)*HH))[c4] = pacc[u];
    }
}

// ---------------- edge count matrix ----------------
__global__ void k_edges(const int* __restrict__ ei, int* __restrict__ cntm) {
    int e = blockIdx.x * blockDim.x + threadIdx.x;
    int s = ei[e];
    int d = ei[EE + e];
    if ((unsigned)s >= NN || (unsigned)d >= NN) return;
    int g = s >> 6;
    atomicAdd(&cntm[(g << 12) | ((s & 63) << 6) | (d & 63)], 1);
}

// ---------------- output head (128 -> 10) ----------------
__global__ void __launch_bounds__(128) k_head(const float* __restrict__ gf2,
                                              const float* __restrict__ W,
                                              const float* __restrict__ b,
                                              float* __restrict__ out) {
    __shared__ float row[HH];
    int g = blockIdx.x;
    row[threadIdx.x] = gf2[(size_t)g*HH + threadIdx.x];
    __syncthreads();
    if (threadIdx.x < NOUT) {
        float acc = b[threadIdx.x];
        for (int k = 0; k < HH; k++) acc += row[k] * W[k*NOUT + threadIdx.x];
        out[g*NOUT + threadIdx.x] = acc;
    }
}

// ---------------- launcher ----------------
extern "C" void kernel_launch(void* const* d_in, const int* in_sizes, int n_in,
                              void* d_out, int out_size)
{
    (void)in_sizes; (void)n_in; (void)out_size;
    const float* x        = (const float*)d_in[0];
    const int*   ei       = (const int*)d_in[1];
    const float* eweights = (const float*)d_in[3];
    const float* vemb     = (const float*)d_in[4];
    const float* W_emb  = (const float*)d_in[5];  const float* b_emb  = (const float*)d_in[6];
    const float* W_gcn  = (const float*)d_in[7];  const float* b_gcn  = (const float*)d_in[8];
    const float* aff_W1 = (const float*)d_in[9];  const float* aff_b1 = (const float*)d_in[10];
    const float* aff_W2 = (const float*)d_in[11]; const float* aff_b2 = (const float*)d_in[12];
    const float* vn_W1  = (const float*)d_in[13]; const float* vn_b1  = (const float*)d_in[14];
    const float* vn_W2  = (const float*)d_in[15]; const float* vn_b2  = (const float*)d_in[16];
    const float* mlp_W1 = (const float*)d_in[17]; const float* mlp_b1 = (const float*)d_in[18];
    const float* mlp_W2 = (const float*)d_in[19]; const float* mlp_b2 = (const float*)d_in[20];
    float* out = (float*)d_out;

    float *p_h2, *p_vn, *p_vn2, *p_gf2, *p_wc, *p_bc;
    int *p_cntm;
    __nv_bfloat16 *p_wt0, *p_wt1;
    cudaGetSymbolAddress((void**)&p_h2,   d_h2);
    cudaGetSymbolAddress((void**)&p_cntm, d_cntm);
    cudaGetSymbolAddress((void**)&p_vn,   d_vn);
    cudaGetSymbolAddress((void**)&p_vn2,  d_vn2);
    cudaGetSymbolAddress((void**)&p_gf2,  d_gf2);
    cudaGetSymbolAddress((void**)&p_wc,   d_wc);
    cudaGetSymbolAddress((void**)&p_bc,   d_bc);
    cudaGetSymbolAddress((void**)&p_wt0,  d_wt0);
    cudaGetSymbolAddress((void**)&p_wt1,  d_wt1);

    cudaFuncSetAttribute(k_split,           cudaFuncAttributeMaxDynamicSharedMemorySize, 65536);
    cudaFuncSetAttribute(k_xgcn,            cudaFuncAttributeMaxDynamicSharedMemorySize, XGCN_SMEM);
    cudaFuncSetAttribute(k_mma_gemm<1,1,1>, cudaFuncAttributeMaxDynamicSharedMemorySize, GSM_TOTAL);
    cudaFuncSetAttribute(k_mlp2,            cudaFuncAttributeMaxDynamicSharedMemorySize, GSM_TOTAL);
    cudaFuncSetAttribute(k_afat,            cudaFuncAttributeMaxDynamicSharedMemorySize, AFAT_SMEM);

    #define WT0(i) (p_wt0 + (size_t)(i) * 16384)
    #define WT1(i) (p_wt1 + (size_t)(i) * 16384)

    // 0) combined weight + splits (slots: 0=Wc, 1=aff1, 2=aff2, 3=vn1, 4=vn2, 5=mlp1)
    k_combine<<<16, 256>>>(W_emb, W_gcn, b_emb, p_wc, p_bc);
    k_split<<<6, 128, 65536>>>(p_wc, aff_W1, aff_W2, vn_W1, vn_W2, mlp_W1, p_wt0, p_wt1);

    // 1) edge count matrix
    cudaMemsetAsync(p_cntm, 0, (size_t)GG * NPG * NPG * sizeof(int));
    k_edges<<<EE/256, 256>>>(ei, p_cntm);

    // 2) fused x-GEMM + GCN -> h2
    k_xgcn<<<NN/128, NT, XGCN_SMEM>>>(x, WT0(0), WT1(0), p_bc, b_gcn, p_cntm, p_h2);

    // 3) fused affinity MLP + attention + pool -> vn
    k_afat<<<NN/128, NT, AFAT_SMEM>>>(p_h2, WT0(1), WT1(1), aff_b1,
                                      WT0(2), WT1(2), aff_b2,
                                      vemb, eweights, p_vn);

    // 4) virtual-node MLP (fused 2-layer)
    k_mlp2<<<GG*VV/128, NT, GSM_TOTAL>>>(p_vn, WT0(3), WT1(3), vn_b1,
                                         WT0(4), WT1(4), vn_b2, p_vn2);

    // 5) gf = mean over V (fused into A-load) -> relu(gf@mlp_W1+b1) -> head
    k_mma_gemm<1,1,1><<<GG/128, NT, GSM_TOTAL>>>(p_vn2, WT0(5), WT1(5), mlp_b1, p_gf2);
    k_head<<<GG, 128>>>(p_gf2, mlp_W2, mlp_b2, out);
}

// round 10
// speedup vs baseline: 1.1033x; 1.1033x over previous
#include <cuda_runtime.h>
#include <cuda_bf16.h>
#include <math.h>
#include <stdint.h>

#define NN   65536
#define GG   1024
#define NPG  64
#define VV   32
#define HH   128
#define EE   1048576
#define NOUT 10

// ---------------- scratch ----------------
__device__ float d_h2  [NN*HH];
__device__ float d_aff [NN*HH];
__device__ int   d_cntm[GG*NPG*NPG];
__device__ float d_vn  [GG*VV*HH];
__device__ float d_vn2 [GG*VV*HH];
__device__ float d_gf2 [GG*HH];
__device__ float d_wc  [HH*HH];
__device__ float d_bc  [HH];
__device__ __nv_bfloat16 d_wt0[6*HH*HH];
__device__ __nv_bfloat16 d_wt1[6*HH*HH];

// ================= helpers =================
__device__ __forceinline__ uint32_t smem_u32(const void* p) {
    uint32_t a;
    asm("{ .reg .u64 t; cvta.to.shared.u64 t, %1; cvt.u32.u64 %0, t; }" : "=r"(a) : "l"(p));
    return a;
}
__device__ __forceinline__ uint32_t pack_bf16x2(__nv_bfloat16 lo, __nv_bfloat16 hi) {
    return (uint32_t)__bfloat16_as_ushort(lo) | ((uint32_t)__bfloat16_as_ushort(hi) << 16);
}
// compact blocked K-major tile, AR = atom-rows (rows/8); atom = 8r x 64 bf16 (1KB), SW128
__device__ __forceinline__ uint32_t toff(int r, int k, int AR) {
    uint32_t base = ((((uint32_t)k >> 6) * (uint32_t)AR + ((uint32_t)r >> 3)) << 10)
                  + (((uint32_t)r & 7) << 7) + (((uint32_t)k & 63) << 1);
    return base ^ ((base >> 3) & 0x70);
}
__device__ __forceinline__ uint32_t faddr(uint32_t base, int r, int k, int AR) {
    return base + ((((uint32_t)k >> 6) * (uint32_t)AR + ((uint32_t)r >> 3)) << 10)
         + (((uint32_t)r & 7) << 7) + ((((uint32_t)k & 63) << 1) ^ (((uint32_t)r & 7) << 4));
}
__device__ __forceinline__ void ldsm4(uint32_t* r, uint32_t addr) {
    asm volatile("ldmatrix.sync.aligned.m8n8.x4.shared.b16 {%0,%1,%2,%3}, [%4];"
        : "=r"(r[0]), "=r"(r[1]), "=r"(r[2]), "=r"(r[3]) : "r"(addr));
}
__device__ __forceinline__ void mma16816(float* c, const uint32_t* a, const uint32_t* b) {
    asm volatile("mma.sync.aligned.m16n8k16.row.col.f32.bf16.bf16.f32 "
        "{%0,%1,%2,%3}, {%4,%5,%6,%7}, {%8,%9}, {%0,%1,%2,%3};"
        : "+f"(c[0]), "+f"(c[1]), "+f"(c[2]), "+f"(c[3])
        : "r"(a[0]), "r"(a[1]), "r"(a[2]), "r"(a[3]), "r"(b[0]), "r"(b[1]));
}

// smem layout: A tiles 16KB (64x128), B tiles 32KB (128x128)
#define S_A0 0
#define S_A1 16384
#define S_B0 32768
#define S_B1 65536
#define MLP_SMEM 98304
#define XG_SINV 98304
#define XG_SMEM 98560
#define NT2 256

// stage fp32 64x128 A tile -> bf16 hi/lo split (AR=8)
__device__ __forceinline__ void stage_A64(char* smem, const float* __restrict__ A,
                                          int row0, int tid) {
    const float4* A4 = (const float4*)(A + (size_t)row0 * 128);
#pragma unroll
    for (int i = tid; i < 2048; i += NT2) {
        int r = i >> 5, k = (i & 31) << 2;
        float4 a = A4[i];
        __nv_bfloat16 hx = __float2bfloat16(a.x), hy = __float2bfloat16(a.y);
        __nv_bfloat16 hz = __float2bfloat16(a.z), hw = __float2bfloat16(a.w);
        __nv_bfloat16 lx = __float2bfloat16(a.x - __bfloat162float(hx));
        __nv_bfloat16 ly = __float2bfloat16(a.y - __bfloat162float(hy));
        __nv_bfloat16 lz = __float2bfloat16(a.z - __bfloat162float(hz));
        __nv_bfloat16 lw = __float2bfloat16(a.w - __bfloat162float(hw));
        uint32_t sw = toff(r, k, 8);
        *(uint2*)(smem + S_A0 + sw) = make_uint2(pack_bf16x2(hx, hy), pack_bf16x2(hz, hw));
        *(uint2*)(smem + S_A1 + sw) = make_uint2(pack_bf16x2(lx, ly), pack_bf16x2(lz, lw));
    }
}
// stage pre-split 128x128 weights into B0/B1 (AR=16)
__device__ __forceinline__ void stage_W(char* smem, const __nv_bfloat16* __restrict__ Wh,
                                        const __nv_bfloat16* __restrict__ Wl, int tid) {
    const uint2* H = (const uint2*)Wh;
    const uint2* L = (const uint2*)Wl;
#pragma unroll
    for (int i = tid; i < 4096; i += NT2) {
        int n = i >> 5, k = (i & 31) << 2;
        uint32_t sw = toff(n, k, 16);
        *(uint2*)(smem + S_B0 + sw) = H[i];
        *(uint2*)(smem + S_B1 + sw) = L[i];
    }
}
// one accumulating MMA pass; 8 warps: grid 2(M,32) x 4(N,32)
template<int KMAX, int ARA, int ARB>
__device__ __forceinline__ void mma_pass(uint32_t ab, uint32_t bb, int wid, int lid,
                                         float acc[2][4][4]) {
    const int m0w = (wid >> 2) * 32;
    const int n0w = (wid & 3) * 32;
    const int arow = m0w + (lid & 7) + ((lid >> 3) & 1) * 8;
    const int akad = (lid >> 4) * 8;
    const int brow0 = n0w + (lid & 7) + (lid >> 4) * 8;
    const int bkad = ((lid >> 3) & 1) * 8;
#pragma unroll
    for (int k0 = 0; k0 < KMAX; k0 += 16) {
        uint32_t a[2][4], b[2][4];
        ldsm4(a[0], faddr(ab, arow,      k0 + akad, ARA));
        ldsm4(a[1], faddr(ab, arow + 16, k0 + akad, ARA));
        ldsm4(b[0], faddr(bb, brow0,      k0 + bkad, ARB));
        ldsm4(b[1], faddr(bb, brow0 + 16, k0 + bkad, ARB));
#pragma unroll
        for (int mf = 0; mf < 2; mf++)
#pragma unroll
            for (int nf = 0; nf < 4; nf++)
                mma16816(acc[mf][nf], a[mf], &b[nf >> 1][(nf & 1) * 2]);
    }
}
__device__ __forceinline__ void zero_acc(float acc[2][4][4]) {
#pragma unroll
    for (int mf = 0; mf < 2; mf++)
#pragma unroll
        for (int nf = 0; nf < 4; nf++)
#pragma unroll
            for (int j = 0; j < 4; j++) acc[mf][nf][j] = 0.f;
}

// ---------------- weight combine ----------------
__global__ void __launch_bounds__(256) k_combine(const float* __restrict__ We,
                                                 const float* __restrict__ Wg,
                                                 const float* __restrict__ be,
                                                 float* __restrict__ Wc,
                                                 float* __restrict__ bc) {
    const int col = threadIdx.x & 127;
    const int rr  = threadIdx.x >> 7;
    for (int p = 0; p < 4; p++) {
        int row = blockIdx.x * 8 + p * 2 + rr;
        float s = 0.f;
#pragma unroll 8
        for (int k = 0; k < 128; k++) s += We[row * 128 + k] * Wg[k * 128 + col];
        Wc[row * 128 + col] = s;
    }
    if (blockIdx.x == 0 && threadIdx.x < 128) {
        float s = 0.f;
        for (int k = 0; k < 128; k++) s += be[k] * Wg[k * 128 + col];
        bc[col] = s;
    }
}

// ---------------- weight prep: transpose + bf16 hi/lo split ----------------
__global__ void __launch_bounds__(128) k_split(
    const float* W0, const float* W1, const float* W2, const float* W3,
    const float* W4, const float* W5,
    __nv_bfloat16* wt0, __nv_bfloat16* wt1)
{
    extern __shared__ float s[];
    const float* Ws[6] = {W0, W1, W2, W3, W4, W5};
    const float* W = Ws[blockIdx.x];
    for (int i = threadIdx.x; i < 16384; i += 128) s[i] = W[i];
    __syncthreads();
    const int n = threadIdx.x;
    uint32_t* o0 = (uint32_t*)(wt0 + (size_t)blockIdx.x * 16384 + n * 128);
    uint32_t* o1 = (uint32_t*)(wt1 + (size_t)blockIdx.x * 16384 + n * 128);
    for (int k = 0; k < 128; k += 2) {
        float v0 = s[k * 128 + n], v1 = s[(k + 1) * 128 + n];
        __nv_bfloat16 h0 = __float2bfloat16(v0), h1 = __float2bfloat16(v1);
        __nv_bfloat16 l0 = __float2bfloat16(v0 - __bfloat162float(h0));
        __nv_bfloat16 l1 = __float2bfloat16(v1 - __bfloat162float(h1));
        o0[k >> 1] = pack_bf16x2(h0, h1);
        o1[k >> 1] = pack_bf16x2(l0, l1);
    }
}

// ------------- fused x-GEMM + GCN (1 graph per block, 64 rows) -------------
__global__ void __launch_bounds__(NT2, 2) k_xgcn(
    const float* __restrict__ x,
    const __nv_bfloat16* __restrict__ Wch, const __nv_bfloat16* __restrict__ Wcl,
    const float* __restrict__ bc, const float* __restrict__ b_gcn,
    const int* __restrict__ cntm,
    float* __restrict__ h2)
{
    extern __shared__ char smem[];
    const uint32_t sb = smem_u32(smem);
    const int tid = threadIdx.x, wid = tid >> 5, lid = tid & 31;
    const int g = blockIdx.x;
    const int row0 = g * 64;
    const int* cg = cntm + ((size_t)g << 12);
    float* sinv = (float*)(smem + XG_SINV);

    stage_A64(smem, x, row0, tid);
    stage_W(smem, Wch, Wcl, tid);
    // deg -> sinv (independent of tile buffers)
    if (tid < 64) {
        int deg = 0;
#pragma unroll 8
        for (int s = 0; s < 64; s++) deg += cg[(s << 6) + tid];
        sinv[tid] = rsqrtf((float)deg + 1.f);
    }
    __syncthreads();

    // phase 1: hw = x @ Wc (3-pass split)
    float acc[2][4][4];
    zero_acc(acc);
    mma_pass<128, 8, 16>(sb + S_A0, sb + S_B0, wid, lid, acc);
    mma_pass<128, 8, 16>(sb + S_A0, sb + S_B1, wid, lid, acc);
    mma_pass<128, 8, 16>(sb + S_A1, sb + S_B0, wid, lid, acc);

    const int m0w = (wid >> 2) * 32;
    const int n0w = (wid & 3) * 32;
    const int crow = lid >> 2;
    const int ccol = (lid & 3) * 2;

    __syncthreads();   // all reads of A/B done

    // restage ssrc^T = ((hw+bc)*inv[s])^T as [h][s], hi->B0, lo->B0+16K (16KB each, AR=16)
#pragma unroll
    for (int mf = 0; mf < 2; mf++) {
        int r = m0w + mf * 16 + crow;
        float iv0 = sinv[r], iv1 = sinv[r + 8];
#pragma unroll
        for (int nf = 0; nf < 4; nf++) {
            int cn = n0w + nf * 8 + ccol;
            float2 bv = *(const float2*)(bc + cn);
            float v00 = (acc[mf][nf][0] + bv.x) * iv0;
            float v01 = (acc[mf][nf][1] + bv.y) * iv0;
            float v10 = (acc[mf][nf][2] + bv.x) * iv1;
            float v11 = (acc[mf][nf][3] + bv.y) * iv1;
            __nv_bfloat16 h00 = __float2bfloat16(v00), h01 = __float2bfloat16(v01);
            __nv_bfloat16 h10 = __float2bfloat16(v10), h11 = __float2bfloat16(v11);
            *(__nv_bfloat16*)(smem + S_B0 + toff(cn,     r,     16)) = h00;
            *(__nv_bfloat16*)(smem + S_B0 + toff(cn + 1, r,     16)) = h01;
            *(__nv_bfloat16*)(smem + S_B0 + toff(cn,     r + 8, 16)) = h10;
            *(__nv_bfloat16*)(smem + S_B0 + toff(cn + 1, r + 8, 16)) = h11;
            *(__nv_bfloat16*)(smem + S_B0 + 16384 + toff(cn,     r,     16)) =
                __float2bfloat16(v00 - __bfloat162float(h00));
            *(__nv_bfloat16*)(smem + S_B0 + 16384 + toff(cn + 1, r,     16)) =
                __float2bfloat16(v01 - __bfloat162float(h01));
            *(__nv_bfloat16*)(smem + S_B0 + 16384 + toff(cn,     r + 8, 16)) =
                __float2bfloat16(v10 - __bfloat162float(h10));
            *(__nv_bfloat16*)(smem + S_B0 + 16384 + toff(cn + 1, r + 8, 16)) =
                __float2bfloat16(v11 - __bfloat162float(h11));
        }
    }
    // cnt tile (64x64, AR=8, 8KB) -> A0 slot; A[d][s] = cg[s][d] + diag
    for (int i = tid; i < 4096; i += NT2) {
        int s = i >> 6, d = i & 63;
        float v = (float)cg[i] + (s == d ? 1.f : 0.f);
        *(__nv_bfloat16*)(smem + S_A0 + toff(d, s, 8)) = __float2bfloat16(v);
    }
    __syncthreads();

    // phase 2: agg = cnt @ ssrc (2-pass hi/lo, K=64)
    zero_acc(acc);
    mma_pass<64, 8, 16>(sb + S_A0, sb + S_B0,         wid, lid, acc);
    mma_pass<64, 8, 16>(sb + S_A0, sb + S_B0 + 16384, wid, lid, acc);

    // epilogue: h2 = relu(inv[d]*agg + b_gcn)
#pragma unroll
    for (int mf = 0; mf < 2; mf++) {
        int r = m0w + mf * 16 + crow;
        float iv0 = sinv[r], iv1 = sinv[r + 8];
        float* C0 = h2 + (size_t)(row0 + r) * 128;
#pragma unroll
        for (int nf = 0; nf < 4; nf++) {
            int cn = n0w + nf * 8 + ccol;
            float2 bg = *(const float2*)(b_gcn + cn);
            float2 v0 = make_float2(fmaxf(acc[mf][nf][0] * iv0 + bg.x, 0.f),
                                    fmaxf(acc[mf][nf][1] * iv0 + bg.y, 0.f));
            float2 v1 = make_float2(fmaxf(acc[mf][nf][2] * iv1 + bg.x, 0.f),
                                    fmaxf(acc[mf][nf][3] * iv1 + bg.y, 0.f));
            *(float2*)(C0 + cn)           = v0;
            *(float2*)(C0 + 8 * 128 + cn) = v1;
        }
    }
}

// ---------------- single GEMM (64-row tiles): C = [relu](A @ W + b) ----------------
template<int RELU, int BIAS, int MEANV>
__global__ void __launch_bounds__(NT2, 2) k_mma_gemm(
    const float* __restrict__ A,
    const __nv_bfloat16* __restrict__ Wt0,
    const __nv_bfloat16* __restrict__ Wt1,
    const float* __restrict__ bias,
    float* __restrict__ C)
{
    extern __shared__ char smem[];
    const uint32_t sb = smem_u32(smem);
    const int tid = threadIdx.x, wid = tid >> 5, lid = tid & 31;
    const int row0 = blockIdx.x * 64;

    if (MEANV) {
        for (int i = tid; i < 2048; i += NT2) {
            int r = i >> 5, kq = i & 31;
            const float4* src = (const float4*)A + (size_t)(row0 + r) * VV * 32 + kq;
            float4 a = make_float4(0.f, 0.f, 0.f, 0.f);
#pragma unroll 8
            for (int v = 0; v < VV; v++) {
                float4 t = src[v * 32];
                a.x += t.x; a.y += t.y; a.z += t.z; a.w += t.w;
            }
            a.x *= (1.f/32.f); a.y *= (1.f/32.f); a.z *= (1.f/32.f); a.w *= (1.f/32.f);
            __nv_bfloat16 hx = __float2bfloat16(a.x), hy = __float2bfloat16(a.y);
            __nv_bfloat16 hz = __float2bfloat16(a.z), hw = __float2bfloat16(a.w);
            __nv_bfloat16 lx = __float2bfloat16(a.x - __bfloat162float(hx));
            __nv_bfloat16 ly = __float2bfloat16(a.y - __bfloat162float(hy));
            __nv_bfloat16 lz = __float2bfloat16(a.z - __bfloat162float(hz));
            __nv_bfloat16 lw = __float2bfloat16(a.w - __bfloat162float(hw));
            uint32_t sw = toff(r, kq << 2, 8);
            *(uint2*)(smem + S_A0 + sw) = make_uint2(pack_bf16x2(hx, hy), pack_bf16x2(hz, hw));
            *(uint2*)(smem + S_A1 + sw) = make_uint2(pack_bf16x2(lx, ly), pack_bf16x2(lz, lw));
        }
    } else {
        stage_A64(smem, A, row0, tid);
    }
    stage_W(smem, Wt0, Wt1, tid);
    __syncthreads();

    float acc[2][4][4];
    zero_acc(acc);
    mma_pass<128, 8, 16>(sb + S_A0, sb + S_B0, wid, lid, acc);
    mma_pass<128, 8, 16>(sb + S_A0, sb + S_B1, wid, lid, acc);
    mma_pass<128, 8, 16>(sb + S_A1, sb + S_B0, wid, lid, acc);

    const int m0w = (wid >> 2) * 32;
    const int n0w = (wid & 3) * 32;
    const int crow = lid >> 2;
    const int ccol = (lid & 3) * 2;
#pragma unroll
    for (int mf = 0; mf < 2; mf++) {
        int gr = row0 + m0w + mf * 16 + crow;
        float* C0 = C + (size_t)gr * 128;
#pragma unroll
        for (int nf = 0; nf < 4; nf++) {
            int cn = n0w + nf * 8 + ccol;
            float2 bv = make_float2(0.f, 0.f);
            if (BIAS) bv = *(const float2*)(bias + cn);
            float2 v0 = make_float2(acc[mf][nf][0] + bv.x, acc[mf][nf][1] + bv.y);
            float2 v1 = make_float2(acc[mf][nf][2] + bv.x, acc[mf][nf][3] + bv.y);
            if (RELU) {
                v0.x = fmaxf(v0.x, 0.f); v0.y = fmaxf(v0.y, 0.f);
                v1.x = fmaxf(v1.x, 0.f); v1.y = fmaxf(v1.y, 0.f);
            }
            *(float2*)(C0 + cn)           = v0;
            *(float2*)(C0 + 8 * 128 + cn) = v1;
        }
    }
}

// ---------------- fused 2-layer MLP (64-row tiles) ----------------
__global__ void __launch_bounds__(NT2, 2) k_mlp2(
    const float* __restrict__ A,
    const __nv_bfloat16* __restrict__ W1h, const __nv_bfloat16* __restrict__ W1l,
    const float* __restrict__ b1,
    const __nv_bfloat16* __restrict__ W2h, const __nv_bfloat16* __restrict__ W2l,
    const float* __restrict__ b2,
    float* __restrict__ Out)
{
    extern __shared__ char smem[];
    const uint32_t sb = smem_u32(smem);
    const int tid = threadIdx.x, wid = tid >> 5, lid = tid & 31;
    const int row0 = blockIdx.x * 64;

    stage_A64(smem, A, row0, tid);
    stage_W(smem, W1h, W1l, tid);
    __syncthreads();

    float acc[2][4][4];
    zero_acc(acc);
    mma_pass<128, 8, 16>(sb + S_A0, sb + S_B0, wid, lid, acc);
    mma_pass<128, 8, 16>(sb + S_A0, sb + S_B1, wid, lid, acc);
    mma_pass<128, 8, 16>(sb + S_A1, sb + S_B0, wid, lid, acc);

    const int m0w = (wid >> 2) * 32;
    const int n0w = (wid & 3) * 32;
    const int crow = lid >> 2;
    const int ccol = (lid & 3) * 2;

    __syncthreads();

    // t = relu(acc + b1) -> restage hi/lo into A0/A1
#pragma unroll
    for (int mf = 0; mf < 2; mf++) {
        int r = m0w + mf * 16 + crow;
#pragma unroll
        for (int nf = 0; nf < 4; nf++) {
            int cn = n0w + nf * 8 + ccol;
            float2 bv = *(const float2*)(b1 + cn);
            float tx = fmaxf(acc[mf][nf][0] + bv.x, 0.f);
            float ty = fmaxf(acc[mf][nf][1] + bv.y, 0.f);
            float ux = fmaxf(acc[mf][nf][2] + bv.x, 0.f);
            float uy = fmaxf(acc[mf][nf][3] + bv.y, 0.f);
            __nv_bfloat16 htx = __float2bfloat16(tx), hty = __float2bfloat16(ty);
            __nv_bfloat16 hux = __float2bfloat16(ux), huy = __float2bfloat16(uy);
            uint32_t sw0 = toff(r,     cn, 8);
            uint32_t sw1 = toff(r + 8, cn, 8);
            *(uint32_t*)(smem + S_A0 + sw0) = pack_bf16x2(htx, hty);
            *(uint32_t*)(smem + S_A0 + sw1) = pack_bf16x2(hux, huy);
            *(uint32_t*)(smem + S_A1 + sw0) = pack_bf16x2(
                __float2bfloat16(tx - __bfloat162float(htx)),
                __float2bfloat16(ty - __bfloat162float(hty)));
            *(uint32_t*)(smem + S_A1 + sw1) = pack_bf16x2(
                __float2bfloat16(ux - __bfloat162float(hux)),
                __float2bfloat16(uy - __bfloat162float(huy)));
        }
    }
    stage_W(smem, W2h, W2l, tid);
    __syncthreads();

    zero_acc(acc);
    mma_pass<128, 8, 16>(sb + S_A0, sb + S_B0, wid, lid, acc);
    mma_pass<128, 8, 16>(sb + S_A0, sb + S_B1, wid, lid, acc);
    mma_pass<128, 8, 16>(sb + S_A1, sb + S_B0, wid, lid, acc);

#pragma unroll
    for (int mf = 0; mf < 2; mf++) {
        int gr = row0 + m0w + mf * 16 + crow;
        float* C0 = Out + (size_t)gr * 128;
#pragma unroll
        for (int nf = 0; nf < 4; nf++) {
            int cn = n0w + nf * 8 + ccol;
            float2 bv = *(const float2*)(b2 + cn);
            *(float2*)(C0 + cn) = make_float2(acc[mf][nf][0] + bv.x, acc[mf][nf][1] + bv.y);
            *(float2*)(C0 + 8 * 128 + cn) = make_float2(acc[mf][nf][2] + bv.x,
                                                        acc[mf][nf][3] + bv.y);
        }
    }
}

// ---------------- edge count matrix ----------------
__global__ void k_edges(const int* __restrict__ ei, int* __restrict__ cntm) {
    int e = blockIdx.x * blockDim.x + threadIdx.x;
    int s = ei[e];
    int d = ei[EE + e];
    if ((unsigned)s >= NN || (unsigned)d >= NN) return;
    int g = s >> 6;
    atomicAdd(&cntm[(g << 12) | ((s & 63) << 6) | (d & 63)], 1);
}

// ---------------- per-graph attention + weighted pool (256 thr, 2 CTA/SM) ----------------
__global__ void __launch_bounds__(256) k_att(const float* __restrict__ h2,
                                             const float* __restrict__ aff,
                                             const float* __restrict__ vemb,
                                             const float* __restrict__ eweights,
                                             float* __restrict__ vn_out)
{
    extern __shared__ float sm[];
    float* hgs   = sm;
    float* affs  = sm + NPG*HH;
    float* vembT = sm + 2*NPG*HH;
    float* sew   = vembT + HH*33;

    const int g = blockIdx.x, tid = threadIdx.x;

    const float4* hg4 = (const float4*)(h2  + (size_t)g*NPG*HH);
    const float4* af4 = (const float4*)(aff + (size_t)g*NPG*HH);
    float4* hgs4  = (float4*)hgs;
    float4* affs4 = (float4*)affs;
    for (int i = tid; i < NPG*HH/4; i += 256) { hgs4[i] = hg4[i]; affs4[i] = af4[i]; }

    const float* vg = vemb + (size_t)g*VV*HH;
    for (int i = tid; i < VV*HH; i += 256) {
        int v = i >> 7, k = i & 127;
        vembT[k*33 + v] = vg[i];
    }
    __syncthreads();

    const int v  = tid & 31;
    const int ng = tid >> 5;
    const float* ew_g = eweights + (size_t)g*NPG*VV;
    const float scale = 0.08838834764831845f;

    for (int c = 0; c < 2; c++) {
        int n0 = ng*8 + c*4;
        float acc0 = 0.f, acc1 = 0.f, acc2 = 0.f, acc3 = 0.f;
#pragma unroll 4
        for (int kq = 0; kq < 32; kq++) {
            float4 a0 = affs4[(n0+0)*32 + kq];
            float4 a1 = affs4[(n0+1)*32 + kq];
            float4 a2 = affs4[(n0+2)*32 + kq];
            float4 a3 = affs4[(n0+3)*32 + kq];
            float w0 = vembT[(kq*4+0)*33 + v];
            float w1 = vembT[(kq*4+1)*33 + v];
            float w2 = vembT[(kq*4+2)*33 + v];
            float w3 = vembT[(kq*4+3)*33 + v];
            acc0 += a0.x*w0 + a0.y*w1 + a0.z*w2 + a0.w*w3;
            acc1 += a1.x*w0 + a1.y*w1 + a1.z*w2 + a1.w*w3;
            acc2 += a2.x*w0 + a2.y*w1 + a2.z*w2 + a2.w*w3;
            acc3 += a3.x*w0 + a3.y*w1 + a3.z*w2 + a3.w*w3;
        }
        float accs[4] = {acc0, acc1, acc2, acc3};
#pragma unroll
        for (int j = 0; j < 4; j++) {
            int n = n0 + j;
            float att = accs[j] * scale;
            float sg = 1.f / (1.f + expf(-att));
            sew[n*32 + v] = ew_g[n*32 + v] * (1.f + sg);
        }
    }
    __syncthreads();

    if (tid < NPG) {
        float rs = 0.f;
        for (int v2 = 0; v2 < VV; v2++) rs += sew[tid*32 + v2];
        float denom = (rs == 0.f) ? 1.f : rs;
        float ivr = 1.f / denom;
        for (int v2 = 0; v2 < VV; v2++) sew[tid*32 + v2] *= ivr;
    }
    __syncthreads();

    const int c4  = tid & 31;
    const int vgp = tid >> 5;
    {
        int vb = vgp*4;
        float4 acc[4];
#pragma unroll
        for (int u = 0; u < 4; u++) acc[u] = make_float4(0.f, 0.f, 0.f, 0.f);
        for (int n = 0; n < NPG; n++) {
            float4 hv = hgs4[n*32 + c4];
#pragma unroll
            for (int u = 0; u < 4; u++) {
                float w = sew[n*32 + vb + u];
                acc[u].x += w*hv.x; acc[u].y += w*hv.y;
                acc[u].z += w*hv.z; acc[u].w += w*hv.w;
            }
        }
#pragma unroll
        for (int u = 0; u < 4; u++)
            ((float4*)(vn_out + (size_t)(g*VV + vb + u)*HH))[c4] = acc[u];
    }
}

// ---------------- output head (128 -> 10) ----------------
__global__ void __launch_bounds__(128) k_head(const float* __restrict__ gf2,
                                              const float* __restrict__ W,
                                              const float* __restrict__ b,
                                              float* __restrict__ out) {
    __shared__ float row[HH];
    int g = blockIdx.x;
    row[threadIdx.x] = gf2[(size_t)g*HH + threadIdx.x];
    __syncthreads();
    if (threadIdx.x < NOUT) {
        float acc = b[threadIdx.x];
        for (int k = 0; k < HH; k++) acc += row[k] * W[k*NOUT + threadIdx.x];
        out[g*NOUT + threadIdx.x] = acc;
    }
}

// ---------------- launcher ----------------
extern "C" void kernel_launch(void* const* d_in, const int* in_sizes, int n_in,
                              void* d_out, int out_size)
{
    (void)in_sizes; (void)n_in; (void)out_size;
    const float* x        = (const float*)d_in[0];
    const int*   ei       = (const int*)d_in[1];
    const float* eweights = (const float*)d_in[3];
    const float* vemb     = (const float*)d_in[4];
    const float* W_emb  = (const float*)d_in[5];  const float* b_emb  = (const float*)d_in[6];
    const float* W_gcn  = (const float*)d_in[7];  const float* b_gcn  = (const float*)d_in[8];
    const float* aff_W1 = (const float*)d_in[9];  const float* aff_b1 = (const float*)d_in[10];
    const float* aff_W2 = (const float*)d_in[11]; const float* aff_b2 = (const float*)d_in[12];
    const float* vn_W1  = (const float*)d_in[13]; const float* vn_b1  = (const float*)d_in[14];
    const float* vn_W2  = (const float*)d_in[15]; const float* vn_b2  = (const float*)d_in[16];
    const float* mlp_W1 = (const float*)d_in[17]; const float* mlp_b1 = (const float*)d_in[18];
    const float* mlp_W2 = (const float*)d_in[19]; const float* mlp_b2 = (const float*)d_in[20];
    float* out = (float*)d_out;

    float *p_h2, *p_aff, *p_vn, *p_vn2, *p_gf2, *p_wc, *p_bc;
    int *p_cntm;
    __nv_bfloat16 *p_wt0, *p_wt1;
    cudaGetSymbolAddress((void**)&p_h2,   d_h2);
    cudaGetSymbolAddress((void**)&p_aff,  d_aff);
    cudaGetSymbolAddress((void**)&p_cntm, d_cntm);
    cudaGetSymbolAddress((void**)&p_vn,   d_vn);
    cudaGetSymbolAddress((void**)&p_vn2,  d_vn2);
    cudaGetSymbolAddress((void**)&p_gf2,  d_gf2);
    cudaGetSymbolAddress((void**)&p_wc,   d_wc);
    cudaGetSymbolAddress((void**)&p_bc,   d_bc);
    cudaGetSymbolAddress((void**)&p_wt0,  d_wt0);
    cudaGetSymbolAddress((void**)&p_wt1,  d_wt1);

    const int ATT_SMEM = (2*NPG*HH + HH*33 + NPG*VV) * (int)sizeof(float);
    cudaFuncSetAttribute(k_split,           cudaFuncAttributeMaxDynamicSharedMemorySize, 65536);
    cudaFuncSetAttribute(k_xgcn,            cudaFuncAttributeMaxDynamicSharedMemorySize, XG_SMEM);
    cudaFuncSetAttribute(k_mma_gemm<1,1,1>, cudaFuncAttributeMaxDynamicSharedMemorySize, MLP_SMEM);
    cudaFuncSetAttribute(k_mlp2,            cudaFuncAttributeMaxDynamicSharedMemorySize, MLP_SMEM);
    cudaFuncSetAttribute(k_att,             cudaFuncAttributeMaxDynamicSharedMemorySize, ATT_SMEM);

    #define WT0(i) (p_wt0 + (size_t)(i) * 16384)
    #define WT1(i) (p_wt1 + (size_t)(i) * 16384)

    // 0) combined weight + splits (slots: 0=Wc, 1=aff1, 2=aff2, 3=vn1, 4=vn2, 5=mlp1)
    k_combine<<<16, 256>>>(W_emb, W_gcn, b_emb, p_wc, p_bc);
    k_split<<<6, 128, 65536>>>(p_wc, aff_W1, aff_W2, vn_W1, vn_W2, mlp_W1, p_wt0, p_wt1);

    // 1) edge count matrix
    cudaMemsetAsync(p_cntm, 0, (size_t)GG * NPG * NPG * sizeof(int));
    k_edges<<<EE/256, 256>>>(ei, p_cntm);

    // 2) fused x-GEMM + GCN -> h2 (1 graph per block)
    k_xgcn<<<GG, NT2, XG_SMEM>>>(x, WT0(0), WT1(0), p_bc, b_gcn, p_cntm, p_h2);

    // 3) affinity MLP (fused 2-layer)
    k_mlp2<<<NN/64, NT2, MLP_SMEM>>>(p_h2, WT0(1), WT1(1), aff_b1,
                                     WT0(2), WT1(2), aff_b2, p_aff);

    // 4) attention vs virtual nodes + weighted pool
    k_att<<<GG, 256, ATT_SMEM>>>(p_h2, p_aff, vemb, eweights, p_vn);

    // 5) virtual-node MLP (fused 2-layer)
    k_mlp2<<<GG*VV/64, NT2, MLP_SMEM>>>(p_vn, WT0(3), WT1(3), vn_b1,
                                        WT0(4), WT1(4), vn_b2, p_vn2);

    // 6) gf = mean over V (fused into A-load) -> relu(gf@mlp_W1+b1) -> head
    k_mma_gemm<1,1,1><<<GG/64, NT2, MLP_SMEM>>>(p_vn2, WT0(5), WT1(5), mlp_b1, p_gf2);
    k_head<<<GG, 128>>>(p_gf2, mlp_W2, mlp_b2, out);
}

// round 11
// speedup vs baseline: 1.2311x; 1.1159x over previous
#include <cuda_runtime.h>
#include <cuda_fp16.h>
#include <math.h>
#include <stdint.h>

#define NN   65536
#define GG   1024
#define NPG  64
#define VV   32
#define HH   128
#define EE   1048576
#define NOUT 10

// ---------------- scratch ----------------
__device__ float d_h2  [NN*HH];
__device__ float d_aff [NN*HH];
__device__ int   d_cntm[GG*NPG*NPG];
__device__ float d_vn  [GG*VV*HH];
__device__ float d_vn2 [GG*VV*HH];
__device__ float d_gf2 [GG*HH];
__device__ float d_wc  [HH*HH];
__device__ float d_bc  [HH];
__device__ __half d_wt0[6*HH*HH];   // weight hi (transposed [n][k], fp16)
__device__ __half d_wt1[6*HH*HH];   // weight lo residual

// ================= helpers =================
__device__ __forceinline__ uint32_t smem_u32(const void* p) {
    uint32_t a;
    asm("{ .reg .u64 t; cvta.to.shared.u64 t, %1; cvt.u32.u64 %0, t; }" : "=r"(a) : "l"(p));
    return a;
}
__device__ __forceinline__ uint32_t pack_h2(__half lo, __half hi) {
    return (uint32_t)__half_as_ushort(lo) | ((uint32_t)__half_as_ushort(hi) << 16);
}
// compact blocked K-major tile, AR = atom-rows (rows/8); atom = 8r x 64 h (1KB), SW128
__device__ __forceinline__ uint32_t toff(int r, int k, int AR) {
    uint32_t base = ((((uint32_t)k >> 6) * (uint32_t)AR + ((uint32_t)r >> 3)) << 10)
                  + (((uint32_t)r & 7) << 7) + (((uint32_t)k & 63) << 1);
    return base ^ ((base >> 3) & 0x70);
}
__device__ __forceinline__ uint32_t faddr(uint32_t base, int r, int k, int AR) {
    return base + ((((uint32_t)k >> 6) * (uint32_t)AR + ((uint32_t)r >> 3)) << 10)
         + (((uint32_t)r & 7) << 7) + ((((uint32_t)k & 63) << 1) ^ (((uint32_t)r & 7) << 4));
}
__device__ __forceinline__ void ldsm4(uint32_t* r, uint32_t addr) {
    asm volatile("ldmatrix.sync.aligned.m8n8.x4.shared.b16 {%0,%1,%2,%3}, [%4];"
        : "=r"(r[0]), "=r"(r[1]), "=r"(r[2]), "=r"(r[3]) : "r"(addr));
}
__device__ __forceinline__ void mma16816(float* c, const uint32_t* a, const uint32_t* b) {
    asm volatile("mma.sync.aligned.m16n8k16.row.col.f32.f16.f16.f32 "
        "{%0,%1,%2,%3}, {%4,%5,%6,%7}, {%8,%9}, {%0,%1,%2,%3};"
        : "+f"(c[0]), "+f"(c[1]), "+f"(c[2]), "+f"(c[3])
        : "r"(a[0]), "r"(a[1]), "r"(a[2]), "r"(a[3]), "r"(b[0]), "r"(b[1]));
}

// smem layout: A tile 16KB (64x128 fp16), B tiles 32KB (128x128 fp16)
#define S_A0 0
#define S_B0 16384
#define S_B1 49152
#define MLP_SMEM 81920
#define XG_SINV 81920
#define XG_SMEM 82176
#define NT2 256

// stage fp32 64x128 A tile -> single fp16 (AR=8)
__device__ __forceinline__ void stage_A64(char* smem, const float* __restrict__ A,
                                          int row0, int tid) {
    const float4* A4 = (const float4*)(A + (size_t)row0 * 128);
#pragma unroll
    for (int i = tid; i < 2048; i += NT2) {
        int r = i >> 5, k = (i & 31) << 2;
        float4 a = A4[i];
        uint32_t sw = toff(r, k, 8);
        *(uint2*)(smem + S_A0 + sw) = make_uint2(
            pack_h2(__float2half_rn(a.x), __float2half_rn(a.y)),
            pack_h2(__float2half_rn(a.z), __float2half_rn(a.w)));
    }
}
// stage pre-split 128x128 weights into B0/B1 (AR=16)
__device__ __forceinline__ void stage_W(char* smem, const __half* __restrict__ Wh,
                                        const __half* __restrict__ Wl, int tid) {
    const uint2* H = (const uint2*)Wh;
    const uint2* L = (const uint2*)Wl;
#pragma unroll
    for (int i = tid; i < 4096; i += NT2) {
        int n = i >> 5, k = (i & 31) << 2;
        uint32_t sw = toff(n, k, 16);
        *(uint2*)(smem + S_B0 + sw) = H[i];
        *(uint2*)(smem + S_B1 + sw) = L[i];
    }
}
// one accumulating MMA pass; 8 warps: grid 2(M,32) x 4(N,32)
template<int KMAX, int ARA, int ARB>
__device__ __forceinline__ void mma_pass(uint32_t ab, uint32_t bb, int wid, int lid,
                                         float acc[2][4][4]) {
    const int m0w = (wid >> 2) * 32;
    const int n0w = (wid & 3) * 32;
    const int arow = m0w + (lid & 7) + ((lid >> 3) & 1) * 8;
    const int akad = (lid >> 4) * 8;
    const int brow0 = n0w + (lid & 7) + (lid >> 4) * 8;
    const int bkad = ((lid >> 3) & 1) * 8;
#pragma unroll
    for (int k0 = 0; k0 < KMAX; k0 += 16) {
        uint32_t a[2][4], b[2][4];
        ldsm4(a[0], faddr(ab, arow,      k0 + akad, ARA));
        ldsm4(a[1], faddr(ab, arow + 16, k0 + akad, ARA));
        ldsm4(b[0], faddr(bb, brow0,      k0 + bkad, ARB));
        ldsm4(b[1], faddr(bb, brow0 + 16, k0 + bkad, ARB));
#pragma unroll
        for (int mf = 0; mf < 2; mf++)
#pragma unroll
            for (int nf = 0; nf < 4; nf++)
                mma16816(acc[mf][nf], a[mf], &b[nf >> 1][(nf & 1) * 2]);
    }
}
__device__ __forceinline__ void zero_acc(float acc[2][4][4]) {
#pragma unroll
    for (int mf = 0; mf < 2; mf++)
#pragma unroll
        for (int nf = 0; nf < 4; nf++)
#pragma unroll
            for (int j = 0; j < 4; j++) acc[mf][nf][j] = 0.f;
}

// ---------------- weight combine ----------------
__global__ void __launch_bounds__(256) k_combine(const float* __restrict__ We,
                                                 const float* __restrict__ Wg,
                                                 const float* __restrict__ be,
                                                 float* __restrict__ Wc,
                                                 float* __restrict__ bc) {
    const int col = threadIdx.x & 127;
    const int rr  = threadIdx.x >> 7;
    for (int p = 0; p < 4; p++) {
        int row = blockIdx.x * 8 + p * 2 + rr;
        float s = 0.f;
#pragma unroll 8
        for (int k = 0; k < 128; k++) s += We[row * 128 + k] * Wg[k * 128 + col];
        Wc[row * 128 + col] = s;
    }
    if (blockIdx.x == 0 && threadIdx.x < 128) {
        float s = 0.f;
        for (int k = 0; k < 128; k++) s += be[k] * Wg[k * 128 + col];
        bc[col] = s;
    }
}

// ---------------- weight prep: transpose + fp16 hi/lo split ----------------
__global__ void __launch_bounds__(128) k_split(
    const float* W0, const float* W1, const float* W2, const float* W3,
    const float* W4, const float* W5,
    __half* wt0, __half* wt1)
{
    extern __shared__ float s[];
    const float* Ws[6] = {W0, W1, W2, W3, W4, W5};
    const float* W = Ws[blockIdx.x];
    for (int i = threadIdx.x; i < 16384; i += 128) s[i] = W[i];
    __syncthreads();
    const int n = threadIdx.x;
    uint32_t* o0 = (uint32_t*)(wt0 + (size_t)blockIdx.x * 16384 + n * 128);
    uint32_t* o1 = (uint32_t*)(wt1 + (size_t)blockIdx.x * 16384 + n * 128);
    for (int k = 0; k < 128; k += 2) {
        float v0 = s[k * 128 + n], v1 = s[(k + 1) * 128 + n];
        __half h0 = __float2half_rn(v0), h1 = __float2half_rn(v1);
        __half l0 = __float2half_rn(v0 - __half2float(h0));
        __half l1 = __float2half_rn(v1 - __half2float(h1));
        o0[k >> 1] = pack_h2(h0, h1);
        o1[k >> 1] = pack_h2(l0, l1);
    }
}

// ------------- fused x-GEMM + GCN (1 graph per block, 64 rows) -------------
__global__ void __launch_bounds__(NT2, 2) k_xgcn(
    const float* __restrict__ x,
    const __half* __restrict__ Wch, const __half* __restrict__ Wcl,
    const float* __restrict__ bc, const float* __restrict__ b_gcn,
    const int* __restrict__ cntm,
    float* __restrict__ h2)
{
    extern __shared__ char smem[];
    const uint32_t sb = smem_u32(smem);
    const int tid = threadIdx.x, wid = tid >> 5, lid = tid & 31;
    const int g = blockIdx.x;
    const int row0 = g * 64;
    const int* cg = cntm + ((size_t)g << 12);
    float* sinv = (float*)(smem + XG_SINV);

    stage_A64(smem, x, row0, tid);
    stage_W(smem, Wch, Wcl, tid);
    if (tid < 64) {
        int deg = 0;
#pragma unroll 8
        for (int s = 0; s < 64; s++) deg += cg[(s << 6) + tid];
        sinv[tid] = rsqrtf((float)deg + 1.f);
    }
    __syncthreads();

    // phase 1: hw = x @ Wc (2-pass: A0*(B0+B1))
    float acc[2][4][4];
    zero_acc(acc);
    mma_pass<128, 8, 16>(sb + S_A0, sb + S_B0, wid, lid, acc);
    mma_pass<128, 8, 16>(sb + S_A0, sb + S_B1, wid, lid, acc);

    const int m0w = (wid >> 2) * 32;
    const int n0w = (wid & 3) * 32;
    const int crow = lid >> 2;
    const int ccol = (lid & 3) * 2;

    __syncthreads();   // all reads of A/B done

    // restage ssrc^T = ((hw+bc)*inv[s])^T as [h][s] fp16, hi->B0, lo->B0+16K (AR=16)
#pragma unroll
    for (int mf = 0; mf < 2; mf++) {
        int r = m0w + mf * 16 + crow;
        float iv0 = sinv[r], iv1 = sinv[r + 8];
#pragma unroll
        for (int nf = 0; nf < 4; nf++) {
            int cn = n0w + nf * 8 + ccol;
            float2 bv = *(const float2*)(bc + cn);
            float v00 = (acc[mf][nf][0] + bv.x) * iv0;
            float v01 = (acc[mf][nf][1] + bv.y) * iv0;
            float v10 = (acc[mf][nf][2] + bv.x) * iv1;
            float v11 = (acc[mf][nf][3] + bv.y) * iv1;
            __half h00 = __float2half_rn(v00), h01 = __float2half_rn(v01);
            __half h10 = __float2half_rn(v10), h11 = __float2half_rn(v11);
            *(__half*)(smem + S_B0 + toff(cn,     r,     16)) = h00;
            *(__half*)(smem + S_B0 + toff(cn + 1, r,     16)) = h01;
            *(__half*)(smem + S_B0 + toff(cn,     r + 8, 16)) = h10;
            *(__half*)(smem + S_B0 + toff(cn + 1, r + 8, 16)) = h11;
            *(__half*)(smem + S_B0 + 16384 + toff(cn,     r,     16)) =
                __float2half_rn(v00 - __half2float(h00));
            *(__half*)(smem + S_B0 + 16384 + toff(cn + 1, r,     16)) =
                __float2half_rn(v01 - __half2float(h01));
            *(__half*)(smem + S_B0 + 16384 + toff(cn,     r + 8, 16)) =
                __float2half_rn(v10 - __half2float(h10));
            *(__half*)(smem + S_B0 + 16384 + toff(cn + 1, r + 8, 16)) =
                __float2half_rn(v11 - __half2float(h11));
        }
    }
    // cnt tile (64x64, AR=8, 8KB) -> A0 slot; A[d][s] = cg[s][d] + diag (exact in fp16)
    for (int i = tid; i < 4096; i += NT2) {
        int s = i >> 6, d = i & 63;
        float v = (float)cg[i] + (s == d ? 1.f : 0.f);
        *(__half*)(smem + S_A0 + toff(d, s, 8)) = __float2half_rn(v);
    }
    __syncthreads();

    // phase 2: agg = cnt @ ssrc (2-pass hi/lo, K=64)
    zero_acc(acc);
    mma_pass<64, 8, 16>(sb + S_A0, sb + S_B0,         wid, lid, acc);
    mma_pass<64, 8, 16>(sb + S_A0, sb + S_B0 + 16384, wid, lid, acc);

    // epilogue: h2 = relu(inv[d]*agg + b_gcn)
#pragma unroll
    for (int mf = 0; mf < 2; mf++) {
        int r = m0w + mf * 16 + crow;
        float iv0 = sinv[r], iv1 = sinv[r + 8];
        float* C0 = h2 + (size_t)(row0 + r) * 128;
#pragma unroll
        for (int nf = 0; nf < 4; nf++) {
            int cn = n0w + nf * 8 + ccol;
            float2 bg = *(const float2*)(b_gcn + cn);
            float2 v0 = make_float2(fmaxf(acc[mf][nf][0] * iv0 + bg.x, 0.f),
                                    fmaxf(acc[mf][nf][1] * iv0 + bg.y, 0.f));
            float2 v1 = make_float2(fmaxf(acc[mf][nf][2] * iv1 + bg.x, 0.f),
                                    fmaxf(acc[mf][nf][3] * iv1 + bg.y, 0.f));
            *(float2*)(C0 + cn)           = v0;
            *(float2*)(C0 + 8 * 128 + cn) = v1;
        }
    }
}

// ---------------- single GEMM (64-row tiles): C = [relu](A @ W + b) ----------------
template<int RELU, int BIAS, int MEANV>
__global__ void __launch_bounds__(NT2, 2) k_mma_gemm(
    const float* __restrict__ A,
    const __half* __restrict__ Wt0,
    const __half* __restrict__ Wt1,
    const float* __restrict__ bias,
    float* __restrict__ C)
{
    extern __shared__ char smem[];
    const uint32_t sb = smem_u32(smem);
    const int tid = threadIdx.x, wid = tid >> 5, lid = tid & 31;
    const int row0 = blockIdx.x * 64;

    if (MEANV) {
        for (int i = tid; i < 2048; i += NT2) {
            int r = i >> 5, kq = i & 31;
            const float4* src = (const float4*)A + (size_t)(row0 + r) * VV * 32 + kq;
            float4 a = make_float4(0.f, 0.f, 0.f, 0.f);
#pragma unroll 8
            for (int v = 0; v < VV; v++) {
                float4 t = src[v * 32];
                a.x += t.x; a.y += t.y; a.z += t.z; a.w += t.w;
            }
            a.x *= (1.f/32.f); a.y *= (1.f/32.f); a.z *= (1.f/32.f); a.w *= (1.f/32.f);
            uint32_t sw = toff(r, kq << 2, 8);
            *(uint2*)(smem + S_A0 + sw) = make_uint2(
                pack_h2(__float2half_rn(a.x), __float2half_rn(a.y)),
                pack_h2(__float2half_rn(a.z), __float2half_rn(a.w)));
        }
    } else {
        stage_A64(smem, A, row0, tid);
    }
    stage_W(smem, Wt0, Wt1, tid);
    __syncthreads();

    float acc[2][4][4];
    zero_acc(acc);
    mma_pass<128, 8, 16>(sb + S_A0, sb + S_B0, wid, lid, acc);
    mma_pass<128, 8, 16>(sb + S_A0, sb + S_B1, wid, lid, acc);

    const int m0w = (wid >> 2) * 32;
    const int n0w = (wid & 3) * 32;
    const int crow = lid >> 2;
    const int ccol = (lid & 3) * 2;
#pragma unroll
    for (int mf = 0; mf < 2; mf++) {
        int gr = row0 + m0w + mf * 16 + crow;
        float* C0 = C + (size_t)gr * 128;
#pragma unroll
        for (int nf = 0; nf < 4; nf++) {
            int cn = n0w + nf * 8 + ccol;
            float2 bv = make_float2(0.f, 0.f);
            if (BIAS) bv = *(const float2*)(bias + cn);
            float2 v0 = make_float2(acc[mf][nf][0] + bv.x, acc[mf][nf][1] + bv.y);
            float2 v1 = make_float2(acc[mf][nf][2] + bv.x, acc[mf][nf][3] + bv.y);
            if (RELU) {
                v0.x = fmaxf(v0.x, 0.f); v0.y = fmaxf(v0.y, 0.f);
                v1.x = fmaxf(v1.x, 0.f); v1.y = fmaxf(v1.y, 0.f);
            }
            *(float2*)(C0 + cn)           = v0;
            *(float2*)(C0 + 8 * 128 + cn) = v1;
        }
    }
}

// ---------------- fused 2-layer MLP (64-row tiles) ----------------
__global__ void __launch_bounds__(NT2, 2) k_mlp2(
    const float* __restrict__ A,
    const __half* __restrict__ W1h, const __half* __restrict__ W1l,
    const float* __restrict__ b1,
    const __half* __restrict__ W2h, const __half* __restrict__ W2l,
    const float* __restrict__ b2,
    float* __restrict__ Out)
{
    extern __shared__ char smem[];
    const uint32_t sb = smem_u32(smem);
    const int tid = threadIdx.x, wid = tid >> 5, lid = tid & 31;
    const int row0 = blockIdx.x * 64;

    stage_A64(smem, A, row0, tid);
    stage_W(smem, W1h, W1l, tid);
    __syncthreads();

    float acc[2][4][4];
    zero_acc(acc);
    mma_pass<128, 8, 16>(sb + S_A0, sb + S_B0, wid, lid, acc);
    mma_pass<128, 8, 16>(sb + S_A0, sb + S_B1, wid, lid, acc);

    const int m0w = (wid >> 2) * 32;
    const int n0w = (wid & 3) * 32;
    const int crow = lid >> 2;
    const int ccol = (lid & 3) * 2;

    __syncthreads();

    // t = relu(acc + b1) -> restage single fp16 into A0
#pragma unroll
    for (int mf = 0; mf < 2; mf++) {
        int r = m0w + mf * 16 + crow;
#pragma unroll
        for (int nf = 0; nf < 4; nf++) {
            int cn = n0w + nf * 8 + ccol;
            float2 bv = *(const float2*)(b1 + cn);
            float tx = fmaxf(acc[mf][nf][0] + bv.x, 0.f);
            float ty = fmaxf(acc[mf][nf][1] + bv.y, 0.f);
            float ux = fmaxf(acc[mf][nf][2] + bv.x, 0.f);
            float uy = fmaxf(acc[mf][nf][3] + bv.y, 0.f);
            *(uint32_t*)(smem + S_A0 + toff(r,     cn, 8)) =
                pack_h2(__float2half_rn(tx), __float2half_rn(ty));
            *(uint32_t*)(smem + S_A0 + toff(r + 8, cn, 8)) =
                pack_h2(__float2half_rn(ux), __float2half_rn(uy));
        }
    }
    stage_W(smem, W2h, W2l, tid);
    __syncthreads();

    zero_acc(acc);
    mma_pass<128, 8, 16>(sb + S_A0, sb + S_B0, wid, lid, acc);
    mma_pass<128, 8, 16>(sb + S_A0, sb + S_B1, wid, lid, acc);

#pragma unroll
    for (int mf = 0; mf < 2; mf++) {
        int gr = row0 + m0w + mf * 16 + crow;
        float* C0 = Out + (size_t)gr * 128;
#pragma unroll
        for (int nf = 0; nf < 4; nf++) {
            int cn = n0w + nf * 8 + ccol;
            float2 bv = *(const float2*)(b2 + cn);
            *(float2*)(C0 + cn) = make_float2(acc[mf][nf][0] + bv.x, acc[mf][nf][1] + bv.y);
            *(float2*)(C0 + 8 * 128 + cn) = make_float2(acc[mf][nf][2] + bv.x,
                                                        acc[mf][nf][3] + bv.y);
        }
    }
}

// ---------------- edge count matrix ----------------
__global__ void k_edges(const int* __restrict__ ei, int* __restrict__ cntm) {
    int e = blockIdx.x * blockDim.x + threadIdx.x;
    int s = ei[e];
    int d = ei[EE + e];
    if ((unsigned)s >= NN || (unsigned)d >= NN) return;
    int g = s >> 6;
    atomicAdd(&cntm[(g << 12) | ((s & 63) << 6) | (d & 63)], 1);
}

// ---------------- per-graph attention + weighted pool (256 thr) ----------------
__global__ void __launch_bounds__(256) k_att(const float* __restrict__ h2,
                                             const float* __restrict__ aff,
                                             const float* __restrict__ vemb,
                                             const float* __restrict__ eweights,
                                             float* __restrict__ vn_out)
{
    extern __shared__ float sm[];
    float* hgs   = sm;
    float* affs  = sm + NPG*HH;
    float* vembT = sm + 2*NPG*HH;
    float* sew   = vembT + HH*33;

    const int g = blockIdx.x, tid = threadIdx.x;

    const float4* hg4 = (const float4*)(h2  + (size_t)g*NPG*HH);
    const float4* af4 = (const float4*)(aff + (size_t)g*NPG*HH);
    float4* hgs4  = (float4*)hgs;
    float4* affs4 = (float4*)affs;
    for (int i = tid; i < NPG*HH/4; i += 256) { hgs4[i] = hg4[i]; affs4[i] = af4[i]; }

    const float* vg = vemb + (size_t)g*VV*HH;
    for (int i = tid; i < VV*HH; i += 256) {
        int v = i >> 7, k = i & 127;
        vembT[k*33 + v] = vg[i];
    }
    __syncthreads();

    const int v  = tid & 31;
    const int ng = tid >> 5;
    const float* ew_g = eweights + (size_t)g*NPG*VV;
    const float scale = 0.08838834764831845f;

    for (int c = 0; c < 2; c++) {
        int n0 = ng*8 + c*4;
        float acc0 = 0.f, acc1 = 0.f, acc2 = 0.f, acc3 = 0.f;
#pragma unroll 4
        for (int kq = 0; kq < 32; kq++) {
            float4 a0 = affs4[(n0+0)*32 + kq];
            float4 a1 = affs4[(n0+1)*32 + kq];
            float4 a2 = affs4[(n0+2)*32 + kq];
            float4 a3 = affs4[(n0+3)*32 + kq];
            float w0 = vembT[(kq*4+0)*33 + v];
            float w1 = vembT[(kq*4+1)*33 + v];
            float w2 = vembT[(kq*4+2)*33 + v];
            float w3 = vembT[(kq*4+3)*33 + v];
            acc0 += a0.x*w0 + a0.y*w1 + a0.z*w2 + a0.w*w3;
            acc1 += a1.x*w0 + a1.y*w1 + a1.z*w2 + a1.w*w3;
            acc2 += a2.x*w0 + a2.y*w1 + a2.z*w2 + a2.w*w3;
            acc3 += a3.x*w0 + a3.y*w1 + a3.z*w2 + a3.w*w3;
        }
        float accs[4] = {acc0, acc1, acc2, acc3};
#pragma unroll
        for (int j = 0; j < 4; j++) {
            int n = n0 + j;
            float att = accs[j] * scale;
            float sg = 1.f / (1.f + expf(-att));
            sew[n*32 + v] = ew_g[n*32 + v] * (1.f + sg);
        }
    }
    __syncthreads();

    if (tid < NPG) {
        float rs = 0.f;
        for (int v2 = 0; v2 < VV; v2++) rs += sew[tid*32 + v2];
        float denom = (rs == 0.f) ? 1.f : rs;
        float ivr = 1.f / denom;
        for (int v2 = 0; v2 < VV; v2++) sew[tid*32 + v2] *= ivr;
    }
    __syncthreads();

    const int c4  = tid & 31;
    const int vgp = tid >> 5;
    {
        int vb = vgp*4;
        float4 acc[4];
#pragma unroll
        for (int u = 0; u < 4; u++) acc[u] = make_float4(0.f, 0.f, 0.f, 0.f);
        for (int n = 0; n < NPG; n++) {
            float4 hv = hgs4[n*32 + c4];
#pragma unroll
            for (int u = 0; u < 4; u++) {
                float w = sew[n*32 + vb + u];
                acc[u].x += w*hv.x; acc[u].y += w*hv.y;
                acc[u].z += w*hv.z; acc[u].w += w*hv.w;
            }
        }
#pragma unroll
        for (int u = 0; u < 4; u++)
            ((float4*)(vn_out + (size_t)(g*VV + vb + u)*HH))[c4] = acc[u];
    }
}

// ---------------- output head (128 -> 10) ----------------
__global__ void __launch_bounds__(128) k_head(const float* __restrict__ gf2,
                                              const float* __restrict__ W,
                                              const float* __restrict__ b,
                                              float* __restrict__ out) {
    __shared__ float row[HH];
    int g = blockIdx.x;
    row[threadIdx.x] = gf2[(size_t)g*HH + threadIdx.x];
    __syncthreads();
    if (threadIdx.x < NOUT) {
        float acc = b[threadIdx.x];
        for (int k = 0; k < HH; k++) acc += row[k] * W[k*NOUT + threadIdx.x];
        out[g*NOUT + threadIdx.x] = acc;
    }
}

// ---------------- launcher ----------------
extern "C" void kernel_launch(void* const* d_in, const int* in_sizes, int n_in,
                              void* d_out, int out_size)
{
    (void)in_sizes; (void)n_in; (void)out_size;
    const float* x        = (const float*)d_in[0];
    const int*   ei       = (const int*)d_in[1];
    const float* eweights = (const float*)d_in[3];
    const float* vemb     = (const float*)d_in[4];
    const float* W_emb  = (const float*)d_in[5];  const float* b_emb  = (const float*)d_in[6];
    const float* W_gcn  = (const float*)d_in[7];  const float* b_gcn  = (const float*)d_in[8];
    const float* aff_W1 = (const float*)d_in[9];  const float* aff_b1 = (const float*)d_in[10];
    const float* aff_W2 = (const float*)d_in[11]; const float* aff_b2 = (const float*)d_in[12];
    const float* vn_W1  = (const float*)d_in[13]; const float* vn_b1  = (const float*)d_in[14];
    const float* vn_W2  = (const float*)d_in[15]; const float* vn_b2  = (const float*)d_in[16];
    const float* mlp_W1 = (const float*)d_in[17]; const float* mlp_b1 = (const float*)d_in[18];
    const float* mlp_W2 = (const float*)d_in[19]; const float* mlp_b2 = (const float*)d_in[20];
    float* out = (float*)d_out;

    float *p_h2, *p_aff, *p_vn, *p_vn2, *p_gf2, *p_wc, *p_bc;
    int *p_cntm;
    __half *p_wt0, *p_wt1;
    cudaGetSymbolAddress((void**)&p_h2,   d_h2);
    cudaGetSymbolAddress((void**)&p_aff,  d_aff);
    cudaGetSymbolAddress((void**)&p_cntm, d_cntm);
    cudaGetSymbolAddress((void**)&p_vn,   d_vn);
    cudaGetSymbolAddress((void**)&p_vn2,  d_vn2);
    cudaGetSymbolAddress((void**)&p_gf2,  d_gf2);
    cudaGetSymbolAddress((void**)&p_wc,   d_wc);
    cudaGetSymbolAddress((void**)&p_bc,   d_bc);
    cudaGetSymbolAddress((void**)&p_wt0,  d_wt0);
    cudaGetSymbolAddress((void**)&p_wt1,  d_wt1);

    const int ATT_SMEM = (2*NPG*HH + HH*33 + NPG*VV) * (int)sizeof(float);
    cudaFuncSetAttribute(k_split,           cudaFuncAttributeMaxDynamicSharedMemorySize, 65536);
    cudaFuncSetAttribute(k_xgcn,            cudaFuncAttributeMaxDynamicSharedMemorySize, XG_SMEM);
    cudaFuncSetAttribute(k_mma_gemm<1,1,1>, cudaFuncAttributeMaxDynamicSharedMemorySize, MLP_SMEM);
    cudaFuncSetAttribute(k_mlp2,            cudaFuncAttributeMaxDynamicSharedMemorySize, MLP_SMEM);
    cudaFuncSetAttribute(k_att,             cudaFuncAttributeMaxDynamicSharedMemorySize, ATT_SMEM);

    #define WT0(i) (p_wt0 + (size_t)(i) * 16384)
    #define WT1(i) (p_wt1 + (size_t)(i) * 16384)

    // 0) combined weight + splits (slots: 0=Wc, 1=aff1, 2=aff2, 3=vn1, 4=vn2, 5=mlp1)
    k_combine<<<16, 256>>>(W_emb, W_gcn, b_emb, p_wc, p_bc);
    k_split<<<6, 128, 65536>>>(p_wc, aff_W1, aff_W2, vn_W1, vn_W2, mlp_W1, p_wt0, p_wt1);

    // 1) edge count matrix
    cudaMemsetAsync(p_cntm, 0, (size_t)GG * NPG * NPG * sizeof(int));
    k_edges<<<EE/256, 256>>>(ei, p_cntm);

    // 2) fused x-GEMM + GCN -> h2 (1 graph per block)
    k_xgcn<<<GG, NT2, XG_SMEM>>>(x, WT0(0), WT1(0), p_bc, b_gcn, p_cntm, p_h2);

    // 3) affinity MLP (fused 2-layer)
    k_mlp2<<<NN/64, NT2, MLP_SMEM>>>(p_h2, WT0(1), WT1(1), aff_b1,
                                     WT0(2), WT1(2), aff_b2, p_aff);

    // 4) attention vs virtual nodes + weighted pool
    k_att<<<GG, 256, ATT_SMEM>>>(p_h2, p_aff, vemb, eweights, p_vn);

    // 5) virtual-node MLP (fused 2-layer)
    k_mlp2<<<GG*VV/64, NT2, MLP_SMEM>>>(p_vn, WT0(3), WT1(3), vn_b1,
                                        WT0(4), WT1(4), vn_b2, p_vn2);

    // 6) gf = mean over V (fused into A-load) -> relu(gf@mlp_W1+b1) -> head
    k_mma_gemm<1,1,1><<<GG/64, NT2, MLP_SMEM>>>(p_vn2, WT0(5), WT1(5), mlp_b1, p_gf2);
    k_head<<<GG, 128>>>(p_gf2, mlp_W2, mlp_b2, out);
}

// round 12
// speedup vs baseline: 1.3239x; 1.0753x over previous
#include <cuda_runtime.h>
#include <cuda_fp16.h>
#include <math.h>
#include <stdint.h>

#define NN   65536
#define GG   1024
#define NPG  64
#define VV   32
#define HH   128
#define EE   1048576
#define NOUT 10

// ---------------- scratch ----------------
__device__ float d_h2  [NN*HH];
__device__ float d_aff [NN*HH];
__device__ int   d_cntm[GG*NPG*NPG];
__device__ float d_vn  [GG*VV*HH];
__device__ float d_vn2 [GG*VV*HH];
__device__ float d_gf2 [GG*HH];
__device__ float d_wc  [HH*HH];
__device__ float d_bc  [HH];
__device__ __half d_wt0[6*HH*HH];   // weights (transposed [n][k], fp16)

// ================= helpers =================
__device__ __forceinline__ uint32_t smem_u32(const void* p) {
    uint32_t a;
    asm("{ .reg .u64 t; cvta.to.shared.u64 t, %1; cvt.u32.u64 %0, t; }" : "=r"(a) : "l"(p));
    return a;
}
__device__ __forceinline__ uint32_t pack_h2(__half lo, __half hi) {
    return (uint32_t)__half_as_ushort(lo) | ((uint32_t)__half_as_ushort(hi) << 16);
}
// compact blocked K-major tile, AR = atom-rows (rows/8); atom = 8r x 64 h (1KB), SW128
__device__ __forceinline__ uint32_t toff(int r, int k, int AR) {
    uint32_t base = ((((uint32_t)k >> 6) * (uint32_t)AR + ((uint32_t)r >> 3)) << 10)
                  + (((uint32_t)r & 7) << 7) + (((uint32_t)k & 63) << 1);
    return base ^ ((base >> 3) & 0x70);
}
__device__ __forceinline__ uint32_t faddr(uint32_t base, int r, int k, int AR) {
    return base + ((((uint32_t)k >> 6) * (uint32_t)AR + ((uint32_t)r >> 3)) << 10)
         + (((uint32_t)r & 7) << 7) + ((((uint32_t)k & 63) << 1) ^ (((uint32_t)r & 7) << 4));
}
__device__ __forceinline__ void ldsm4(uint32_t* r, uint32_t addr) {
    asm volatile("ldmatrix.sync.aligned.m8n8.x4.shared.b16 {%0,%1,%2,%3}, [%4];"
        : "=r"(r[0]), "=r"(r[1]), "=r"(r[2]), "=r"(r[3]) : "r"(addr));
}
__device__ __forceinline__ void mma16816(float* c, const uint32_t* a, const uint32_t* b) {
    asm volatile("mma.sync.aligned.m16n8k16.row.col.f32.f16.f16.f32 "
        "{%0,%1,%2,%3}, {%4,%5,%6,%7}, {%8,%9}, {%0,%1,%2,%3};"
        : "+f"(c[0]), "+f"(c[1]), "+f"(c[2]), "+f"(c[3])
        : "r"(a[0]), "r"(a[1]), "r"(a[2]), "r"(a[3]), "r"(b[0]), "r"(b[1]));
}

// smem layout: A tile 16KB (64x128 fp16), B tile 32KB (128x128 fp16)
#define S_A0 0
#define S_B0 16384
#define MLP_SMEM 49152
#define XG_SINV 49152
#define XG_SMEM 49408
#define NT2 256

// stage fp32 64x128 A tile -> fp16 (AR=8)
__device__ __forceinline__ void stage_A64(char* smem, const float* __restrict__ A,
                                          int row0, int tid) {
    const float4* A4 = (const float4*)(A + (size_t)row0 * 128);
#pragma unroll
    for (int i = tid; i < 2048; i += NT2) {
        int r = i >> 5, k = (i & 31) << 2;
        float4 a = A4[i];
        uint32_t sw = toff(r, k, 8);
        *(uint2*)(smem + S_A0 + sw) = make_uint2(
            pack_h2(__float2half_rn(a.x), __float2half_rn(a.y)),
            pack_h2(__float2half_rn(a.z), __float2half_rn(a.w)));
    }
}
// stage 128x128 fp16 weights into B0 (AR=16)
__device__ __forceinline__ void stage_W(char* smem, const __half* __restrict__ Wh, int tid) {
    const uint2* H = (const uint2*)Wh;
#pragma unroll
    for (int i = tid; i < 4096; i += NT2) {
        int n = i >> 5, k = (i & 31) << 2;
        *(uint2*)(smem + S_B0 + toff(n, k, 16)) = H[i];
    }
}
// one accumulating MMA pass; 8 warps: grid 2(M,32) x 4(N,32)
template<int KMAX, int ARA, int ARB>
__device__ __forceinline__ void mma_pass(uint32_t ab, uint32_t bb, int wid, int lid,
                                         float acc[2][4][4]) {
    const int m0w = (wid >> 2) * 32;
    const int n0w = (wid & 3) * 32;
    const int arow = m0w + (lid & 7) + ((lid >> 3) & 1) * 8;
    const int akad = (lid >> 4) * 8;
    const int brow0 = n0w + (lid & 7) + (lid >> 4) * 8;
    const int bkad = ((lid >> 3) & 1) * 8;
#pragma unroll
    for (int k0 = 0; k0 < KMAX; k0 += 16) {
        uint32_t a[2][4], b[2][4];
        ldsm4(a[0], faddr(ab, arow,      k0 + akad, ARA));
        ldsm4(a[1], faddr(ab, arow + 16, k0 + akad, ARA));
        ldsm4(b[0], faddr(bb, brow0,      k0 + bkad, ARB));
        ldsm4(b[1], faddr(bb, brow0 + 16, k0 + bkad, ARB));
#pragma unroll
        for (int mf = 0; mf < 2; mf++)
#pragma unroll
            for (int nf = 0; nf < 4; nf++)
                mma16816(acc[mf][nf], a[mf], &b[nf >> 1][(nf & 1) * 2]);
    }
}
__device__ __forceinline__ void zero_acc(float acc[2][4][4]) {
#pragma unroll
    for (int mf = 0; mf < 2; mf++)
#pragma unroll
        for (int nf = 0; nf < 4; nf++)
#pragma unroll
            for (int j = 0; j < 4; j++) acc[mf][nf][j] = 0.f;
}

// ---------------- weight combine ----------------
__global__ void __launch_bounds__(256) k_combine(const float* __restrict__ We,
                                                 const float* __restrict__ Wg,
                                                 const float* __restrict__ be,
                                                 float* __restrict__ Wc,
                                                 float* __restrict__ bc) {
    const int col = threadIdx.x & 127;
    const int rr  = threadIdx.x >> 7;
    for (int p = 0; p < 4; p++) {
        int row = blockIdx.x * 8 + p * 2 + rr;
        float s = 0.f;
#pragma unroll 8
        for (int k = 0; k < 128; k++) s += We[row * 128 + k] * Wg[k * 128 + col];
        Wc[row * 128 + col] = s;
    }
    if (blockIdx.x == 0 && threadIdx.x < 128) {
        float s = 0.f;
        for (int k = 0; k < 128; k++) s += be[k] * Wg[k * 128 + col];
        bc[col] = s;
    }
}

// ---------------- weight prep: transpose + fp16 round ----------------
__global__ void __launch_bounds__(128) k_split(
    const float* W0, const float* W1, const float* W2, const float* W3,
    const float* W4, const float* W5,
    __half* wt0)
{
    extern __shared__ float s[];
    const float* Ws[6] = {W0, W1, W2, W3, W4, W5};
    const float* W = Ws[blockIdx.x];
    for (int i = threadIdx.x; i < 16384; i += 128) s[i] = W[i];
    __syncthreads();
    const int n = threadIdx.x;
    uint32_t* o0 = (uint32_t*)(wt0 + (size_t)blockIdx.x * 16384 + n * 128);
    for (int k = 0; k < 128; k += 2) {
        float v0 = s[k * 128 + n], v1 = s[(k + 1) * 128 + n];
        o0[k >> 1] = pack_h2(__float2half_rn(v0), __float2half_rn(v1));
    }
}

// ------------- fused x-GEMM + GCN (1 graph per block, 64 rows) -------------
__global__ void __launch_bounds__(NT2, 3) k_xgcn(
    const float* __restrict__ x,
    const __half* __restrict__ Wch,
    const float* __restrict__ bc, const float* __restrict__ b_gcn,
    const int* __restrict__ cntm,
    float* __restrict__ h2)
{
    extern __shared__ char smem[];
    const uint32_t sb = smem_u32(smem);
    const int tid = threadIdx.x, wid = tid >> 5, lid = tid & 31;
    const int g = blockIdx.x;
    const int row0 = g * 64;
    const int* cg = cntm + ((size_t)g << 12);
    float* sinv = (float*)(smem + XG_SINV);

    stage_A64(smem, x, row0, tid);
    stage_W(smem, Wch, tid);
    if (tid < 64) {
        int deg = 0;
#pragma unroll 8
        for (int s = 0; s < 64; s++) deg += cg[(s << 6) + tid];
        sinv[tid] = rsqrtf((float)deg + 1.f);
    }
    __syncthreads();

    // phase 1: hw = x @ Wc (single pass)
    float acc[2][4][4];
    zero_acc(acc);
    mma_pass<128, 8, 16>(sb + S_A0, sb + S_B0, wid, lid, acc);

    const int m0w = (wid >> 2) * 32;
    const int n0w = (wid & 3) * 32;
    const int crow = lid >> 2;
    const int ccol = (lid & 3) * 2;

    __syncthreads();   // all reads of A/B done

    // restage ssrc^T = ((hw+bc)*inv[s])^T as [h][s] fp16 -> B0 (128 rows x 64 k, AR=16)
#pragma unroll
    for (int mf = 0; mf < 2; mf++) {
        int r = m0w + mf * 16 + crow;
        float iv0 = sinv[r], iv1 = sinv[r + 8];
#pragma unroll
        for (int nf = 0; nf < 4; nf++) {
            int cn = n0w + nf * 8 + ccol;
            float2 bv = *(const float2*)(bc + cn);
            float v00 = (acc[mf][nf][0] + bv.x) * iv0;
            float v01 = (acc[mf][nf][1] + bv.y) * iv0;
            float v10 = (acc[mf][nf][2] + bv.x) * iv1;
            float v11 = (acc[mf][nf][3] + bv.y) * iv1;
            *(__half*)(smem + S_B0 + toff(cn,     r,     16)) = __float2half_rn(v00);
            *(__half*)(smem + S_B0 + toff(cn + 1, r,     16)) = __float2half_rn(v01);
            *(__half*)(smem + S_B0 + toff(cn,     r + 8, 16)) = __float2half_rn(v10);
            *(__half*)(smem + S_B0 + toff(cn + 1, r + 8, 16)) = __float2half_rn(v11);
        }
    }
    // cnt tile (64x64, AR=8, 8KB) -> A0 slot; A[d][s] = cg[s][d] + diag (exact in fp16)
    for (int i = tid; i < 4096; i += NT2) {
        int s = i >> 6, d = i & 63;
        float v = (float)cg[i] + (s == d ? 1.f : 0.f);
        *(__half*)(smem + S_A0 + toff(d, s, 8)) = __float2half_rn(v);
    }
    __syncthreads();

    // phase 2: agg = cnt @ ssrc (single pass, K=64)
    zero_acc(acc);
    mma_pass<64, 8, 16>(sb + S_A0, sb + S_B0, wid, lid, acc);

    // epilogue: h2 = relu(inv[d]*agg + b_gcn)
#pragma unroll
    for (int mf = 0; mf < 2; mf++) {
        int r = m0w + mf * 16 + crow;
        float iv0 = sinv[r], iv1 = sinv[r + 8];
        float* C0 = h2 + (size_t)(row0 + r) * 128;
#pragma unroll
        for (int nf = 0; nf < 4; nf++) {
            int cn = n0w + nf * 8 + ccol;
            float2 bg = *(const float2*)(b_gcn + cn);
            float2 v0 = make_float2(fmaxf(acc[mf][nf][0] * iv0 + bg.x, 0.f),
                                    fmaxf(acc[mf][nf][1] * iv0 + bg.y, 0.f));
            float2 v1 = make_float2(fmaxf(acc[mf][nf][2] * iv1 + bg.x, 0.f),
                                    fmaxf(acc[mf][nf][3] * iv1 + bg.y, 0.f));
            *(float2*)(C0 + cn)           = v0;
            *(float2*)(C0 + 8 * 128 + cn) = v1;
        }
    }
}

// ---------------- single GEMM (64-row tiles): C = [relu](A @ W + b) ----------------
template<int RELU, int BIAS, int MEANV>
__global__ void __launch_bounds__(NT2, 3) k_mma_gemm(
    const float* __restrict__ A,
    const __half* __restrict__ Wt0,
    const float* __restrict__ bias,
    float* __restrict__ C)
{
    extern __shared__ char smem[];
    const uint32_t sb = smem_u32(smem);
    const int tid = threadIdx.x, wid = tid >> 5, lid = tid & 31;
    const int row0 = blockIdx.x * 64;

    if (MEANV) {
        for (int i = tid; i < 2048; i += NT2) {
            int r = i >> 5, kq = i & 31;
            const float4* src = (const float4*)A + (size_t)(row0 + r) * VV * 32 + kq;
            float4 a = make_float4(0.f, 0.f, 0.f, 0.f);
#pragma unroll 8
            for (int v = 0; v < VV; v++) {
                float4 t = src[v * 32];
                a.x += t.x; a.y += t.y; a.z += t.z; a.w += t.w;
            }
            a.x *= (1.f/32.f); a.y *= (1.f/32.f); a.z *= (1.f/32.f); a.w *= (1.f/32.f);
            uint32_t sw = toff(r, kq << 2, 8);
            *(uint2*)(smem + S_A0 + sw) = make_uint2(
                pack_h2(__float2half_rn(a.x), __float2half_rn(a.y)),
                pack_h2(__float2half_rn(a.z), __float2half_rn(a.w)));
        }
    } else {
        stage_A64(smem, A, row0, tid);
    }
    stage_W(smem, Wt0, tid);
    __syncthreads();

    float acc[2][4][4];
    zero_acc(acc);
    mma_pass<128, 8, 16>(sb + S_A0, sb + S_B0, wid, lid, acc);

    const int m0w = (wid >> 2) * 32;
    const int n0w = (wid & 3) * 32;
    const int crow = lid >> 2;
    const int ccol = (lid & 3) * 2;
#pragma unroll
    for (int mf = 0; mf < 2; mf++) {
        int gr = row0 + m0w + mf * 16 + crow;
        float* C0 = C + (size_t)gr * 128;
#pragma unroll
        for (int nf = 0; nf < 4; nf++) {
            int cn = n0w + nf * 8 + ccol;
            float2 bv = make_float2(0.f, 0.f);
            if (BIAS) bv = *(const float2*)(bias + cn);
            float2 v0 = make_float2(acc[mf][nf][0] + bv.x, acc[mf][nf][1] + bv.y);
            float2 v1 = make_float2(acc[mf][nf][2] + bv.x, acc[mf][nf][3] + bv.y);
            if (RELU) {
                v0.x = fmaxf(v0.x, 0.f); v0.y = fmaxf(v0.y, 0.f);
                v1.x = fmaxf(v1.x, 0.f); v1.y = fmaxf(v1.y, 0.f);
            }
            *(float2*)(C0 + cn)           = v0;
            *(float2*)(C0 + 8 * 128 + cn) = v1;
        }
    }
}

// ---------------- fused 2-layer MLP (64-row tiles) ----------------
__global__ void __launch_bounds__(NT2, 3) k_mlp2(
    const float* __restrict__ A,
    const __half* __restrict__ W1h, const float* __restrict__ b1,
    const __half* __restrict__ W2h, const float* __restrict__ b2,
    float* __restrict__ Out)
{
    extern __shared__ char smem[];
    const uint32_t sb = smem_u32(smem);
    const int tid = threadIdx.x, wid = tid >> 5, lid = tid & 31;
    const int row0 = blockIdx.x * 64;

    stage_A64(smem, A, row0, tid);
    stage_W(smem, W1h, tid);
    __syncthreads();

    float acc[2][4][4];
    zero_acc(acc);
    mma_pass<128, 8, 16>(sb + S_A0, sb + S_B0, wid, lid, acc);

    const int m0w = (wid >> 2) * 32;
    const int n0w = (wid & 3) * 32;
    const int crow = lid >> 2;
    const int ccol = (lid & 3) * 2;

    __syncthreads();

    // t = relu(acc + b1) -> restage fp16 into A0
#pragma unroll
    for (int mf = 0; mf < 2; mf++) {
        int r = m0w + mf * 16 + crow;
#pragma unroll
        for (int nf = 0; nf < 4; nf++) {
            int cn = n0w + nf * 8 + ccol;
            float2 bv = *(const float2*)(b1 + cn);
            float tx = fmaxf(acc[mf][nf][0] + bv.x, 0.f);
            float ty = fmaxf(acc[mf][nf][1] + bv.y, 0.f);
            float ux = fmaxf(acc[mf][nf][2] + bv.x, 0.f);
            float uy = fmaxf(acc[mf][nf][3] + bv.y, 0.f);
            *(uint32_t*)(smem + S_A0 + toff(r,     cn, 8)) =
                pack_h2(__float2half_rn(tx), __float2half_rn(ty));
            *(uint32_t*)(smem + S_A0 + toff(r + 8, cn, 8)) =
                pack_h2(__float2half_rn(ux), __float2half_rn(uy));
        }
    }
    stage_W(smem, W2h, tid);
    __syncthreads();

    zero_acc(acc);
    mma_pass<128, 8, 16>(sb + S_A0, sb + S_B0, wid, lid, acc);

#pragma unroll
    for (int mf = 0; mf < 2; mf++) {
        int gr = row0 + m0w + mf * 16 + crow;
        float* C0 = Out + (size_t)gr * 128;
#pragma unroll
        for (int nf = 0; nf < 4; nf++) {
            int cn = n0w + nf * 8 + ccol;
            float2 bv = *(const float2*)(b2 + cn);
            *(float2*)(C0 + cn) = make_float2(acc[mf][nf][0] + bv.x, acc[mf][nf][1] + bv.y);
            *(float2*)(C0 + 8 * 128 + cn) = make_float2(acc[mf][nf][2] + bv.x,
                                                        acc[mf][nf][3] + bv.y);
        }
    }
}

// ---------------- edge count matrix ----------------
__global__ void k_edges(const int* __restrict__ ei, int* __restrict__ cntm) {
    int e = blockIdx.x * blockDim.x + threadIdx.x;
    int s = ei[e];
    int d = ei[EE + e];
    if ((unsigned)s >= NN || (unsigned)d >= NN) return;
    int g = s >> 6;
    atomicAdd(&cntm[(g << 12) | ((s & 63) << 6) | (d & 63)], 1);
}

// ---------------- per-graph attention + weighted pool (256 thr) ----------------
__global__ void __launch_bounds__(256) k_att(const float* __restrict__ h2,
                                             const float* __restrict__ aff,
                                             const float* __restrict__ vemb,
                                             const float* __restrict__ eweights,
                                             float* __restrict__ vn_out)
{
    extern __shared__ float sm[];
    float* hgs   = sm;
    float* affs  = sm + NPG*HH;
    float* vembT = sm + 2*NPG*HH;
    float* sew   = vembT + HH*33;

    const int g = blockIdx.x, tid = threadIdx.x;

    const float4* hg4 = (const float4*)(h2  + (size_t)g*NPG*HH);
    const float4* af4 = (const float4*)(aff + (size_t)g*NPG*HH);
    float4* hgs4  = (float4*)hgs;
    float4* affs4 = (float4*)affs;
    for (int i = tid; i < NPG*HH/4; i += 256) { hgs4[i] = hg4[i]; affs4[i] = af4[i]; }

    const float* vg = vemb + (size_t)g*VV*HH;
    for (int i = tid; i < VV*HH; i += 256) {
        int v = i >> 7, k = i & 127;
        vembT[k*33 + v] = vg[i];
    }
    __syncthreads();

    const int v  = tid & 31;
    const int ng = tid >> 5;
    const float* ew_g = eweights + (size_t)g*NPG*VV;
    const float scale = 0.08838834764831845f;

    for (int c = 0; c < 2; c++) {
        int n0 = ng*8 + c*4;
        float acc0 = 0.f, acc1 = 0.f, acc2 = 0.f, acc3 = 0.f;
#pragma unroll 4
        for (int kq = 0; kq < 32; kq++) {
            float4 a0 = affs4[(n0+0)*32 + kq];
            float4 a1 = affs4[(n0+1)*32 + kq];
            float4 a2 = affs4[(n0+2)*32 + kq];
            float4 a3 = affs4[(n0+3)*32 + kq];
            float w0 = vembT[(kq*4+0)*33 + v];
            float w1 = vembT[(kq*4+1)*33 + v];
            float w2 = vembT[(kq*4+2)*33 + v];
            float w3 = vembT[(kq*4+3)*33 + v];
            acc0 += a0.x*w0 + a0.y*w1 + a0.z*w2 + a0.w*w3;
            acc1 += a1.x*w0 + a1.y*w1 + a1.z*w2 + a1.w*w3;
            acc2 += a2.x*w0 + a2.y*w1 + a2.z*w2 + a2.w*w3;
            acc3 += a3.x*w0 + a3.y*w1 + a3.z*w2 + a3.w*w3;
        }
        float accs[4] = {acc0, acc1, acc2, acc3};
#pragma unroll
        for (int j = 0; j < 4; j++) {
            int n = n0 + j;
            float att = accs[j] * scale;
            float sg = 1.f / (1.f + expf(-att));
            sew[n*32 + v] = ew_g[n*32 + v] * (1.f + sg);
        }
    }
    __syncthreads();

    if (tid < NPG) {
        float rs = 0.f;
        for (int v2 = 0; v2 < VV; v2++) rs += sew[tid*32 + v2];
        float denom = (rs == 0.f) ? 1.f : rs;
        float ivr = 1.f / denom;
        for (int v2 = 0; v2 < VV; v2++) sew[tid*32 + v2] *= ivr;
    }
    __syncthreads();

    const int c4  = tid & 31;
    const int vgp = tid >> 5;
    {
        int vb = vgp*4;
        float4 acc[4];
#pragma unroll
        for (int u = 0; u < 4; u++) acc[u] = make_float4(0.f, 0.f, 0.f, 0.f);
        for (int n = 0; n < NPG; n++) {
            float4 hv = hgs4[n*32 + c4];
#pragma unroll
            for (int u = 0; u < 4; u++) {
                float w = sew[n*32 + vb + u];
                acc[u].x += w*hv.x; acc[u].y += w*hv.y;
                acc[u].z += w*hv.z; acc[u].w += w*hv.w;
            }
        }
#pragma unroll
        for (int u = 0; u < 4; u++)
            ((float4*)(vn_out + (size_t)(g*VV + vb + u)*HH))[c4] = acc[u];
    }
}

// ---------------- output head (128 -> 10) ----------------
__global__ void __launch_bounds__(128) k_head(const float* __restrict__ gf2,
                                              const float* __restrict__ W,
                                              const float* __restrict__ b,
                                              float* __restrict__ out) {
    __shared__ float row[HH];
    int g = blockIdx.x;
    row[threadIdx.x] = gf2[(size_t)g*HH + threadIdx.x];
    __syncthreads();
    if (threadIdx.x < NOUT) {
        float acc = b[threadIdx.x];
        for (int k = 0; k < HH; k++) acc += row[k] * W[k*NOUT + threadIdx.x];
        out[g*NOUT + threadIdx.x] = acc;
    }
}

// ---------------- launcher ----------------
extern "C" void kernel_launch(void* const* d_in, const int* in_sizes, int n_in,
                              void* d_out, int out_size)
{
    (void)in_sizes; (void)n_in; (void)out_size;
    const float* x        = (const float*)d_in[0];
    const int*   ei       = (const int*)d_in[1];
    const float* eweights = (const float*)d_in[3];
    const float* vemb     = (const float*)d_in[4];
    const float* W_emb  = (const float*)d_in[5];  const float* b_emb  = (const float*)d_in[6];
    const float* W_gcn  = (const float*)d_in[7];  const float* b_gcn  = (const float*)d_in[8];
    const float* aff_W1 = (const float*)d_in[9];  const float* aff_b1 = (const float*)d_in[10];
    const float* aff_W2 = (const float*)d_in[11]; const float* aff_b2 = (const float*)d_in[12];
    const float* vn_W1  = (const float*)d_in[13]; const float* vn_b1  = (const float*)d_in[14];
    const float* vn_W2  = (const float*)d_in[15]; const float* vn_b2  = (const float*)d_in[16];
    const float* mlp_W1 = (const float*)d_in[17]; const float* mlp_b1 = (const float*)d_in[18];
    const float* mlp_W2 = (const float*)d_in[19]; const float* mlp_b2 = (const float*)d_in[20];
    float* out = (float*)d_out;

    float *p_h2, *p_aff, *p_vn, *p_vn2, *p_gf2, *p_wc, *p_bc;
    int *p_cntm;
    __half *p_wt0;
    cudaGetSymbolAddress((void**)&p_h2,   d_h2);
    cudaGetSymbolAddress((void**)&p_aff,  d_aff);
    cudaGetSymbolAddress((void**)&p_cntm, d_cntm);
    cudaGetSymbolAddress((void**)&p_vn,   d_vn);
    cudaGetSymbolAddress((void**)&p_vn2,  d_vn2);
    cudaGetSymbolAddress((void**)&p_gf2,  d_gf2);
    cudaGetSymbolAddress((void**)&p_wc,   d_wc);
    cudaGetSymbolAddress((void**)&p_bc,   d_bc);
    cudaGetSymbolAddress((void**)&p_wt0,  d_wt0);

    const int ATT_SMEM = (2*NPG*HH + HH*33 + NPG*VV) * (int)sizeof(float);
    cudaFuncSetAttribute(k_split,           cudaFuncAttributeMaxDynamicSharedMemorySize, 65536);
    cudaFuncSetAttribute(k_xgcn,            cudaFuncAttributeMaxDynamicSharedMemorySize, XG_SMEM);
    cudaFuncSetAttribute(k_mma_gemm<1,1,1>, cudaFuncAttributeMaxDynamicSharedMemorySize, MLP_SMEM);
    cudaFuncSetAttribute(k_mlp2,            cudaFuncAttributeMaxDynamicSharedMemorySize, MLP_SMEM);
    cudaFuncSetAttribute(k_att,             cudaFuncAttributeMaxDynamicSharedMemorySize, ATT_SMEM);

    #define WT0(i) (p_wt0 + (size_t)(i) * 16384)

    // 0) combined weight + fp16 weight prep (slots: 0=Wc, 1=aff1, 2=aff2, 3=vn1, 4=vn2, 5=mlp1)
    k_combine<<<16, 256>>>(W_emb, W_gcn, b_emb, p_wc, p_bc);
    k_split<<<6, 128, 65536>>>(p_wc, aff_W1, aff_W2, vn_W1, vn_W2, mlp_W1, p_wt0);

    // 1) edge count matrix
    cudaMemsetAsync(p_cntm, 0, (size_t)GG * NPG * NPG * sizeof(int));
    k_edges<<<EE/256, 256>>>(ei, p_cntm);

    // 2) fused x-GEMM + GCN -> h2 (1 graph per block)
    k_xgcn<<<GG, NT2, XG_SMEM>>>(x, WT0(0), p_bc, b_gcn, p_cntm, p_h2);

    // 3) affinity MLP (fused 2-layer)
    k_mlp2<<<NN/64, NT2, MLP_SMEM>>>(p_h2, WT0(1), aff_b1, WT0(2), aff_b2, p_aff);

    // 4) attention vs virtual nodes + weighted pool
    k_att<<<GG, 256, ATT_SMEM>>>(p_h2, p_aff, vemb, eweights, p_vn);

    // 5) virtual-node MLP (fused 2-layer)
    k_mlp2<<<GG*VV/64, NT2, MLP_SMEM>>>(p_vn, WT0(3), vn_b1, WT0(4), vn_b2, p_vn2);

    // 6) gf = mean over V (fused into A-load) -> relu(gf@mlp_W1+b1) -> head
    k_mma_gemm<1,1,1><<<GG/64, NT2, MLP_SMEM>>>(p_vn2, WT0(5), mlp_b1, p_gf2);
    k_head<<<GG, 128>>>(p_gf2, mlp_W2, mlp_b2, out);
}

// round 13
// speedup vs baseline: 1.3688x; 1.0340x over previous
#include <cuda_runtime.h>
#include <cuda_fp16.h>
#include <math.h>
#include <stdint.h>

#define NN   65536
#define GG   1024
#define NPG  64
#define VV   32
#define HH   128
#define EE   1048576
#define NOUT 10

// ---------------- scratch ----------------
__device__ __half d_h2 [NN*HH];
__device__ __half d_aff[NN*HH];
__device__ int    d_cntm[GG*NPG*NPG];
__device__ __half d_vn [GG*VV*HH];
__device__ __half d_vn2[GG*VV*HH];
__device__ float  d_wc [HH*HH];
__device__ float  d_bc [HH];
__device__ __half d_wt0[6*HH*HH];   // weights (transposed [n][k], fp16)

// ================= helpers =================
__device__ __forceinline__ uint32_t smem_u32(const void* p) {
    uint32_t a;
    asm("{ .reg .u64 t; cvta.to.shared.u64 t, %1; cvt.u32.u64 %0, t; }" : "=r"(a) : "l"(p));
    return a;
}
__device__ __forceinline__ uint32_t pack_h2(__half lo, __half hi) {
    return (uint32_t)__half_as_ushort(lo) | ((uint32_t)__half_as_ushort(hi) << 16);
}
// compact blocked K-major tile, AR = atom-rows (rows/8); atom = 8r x 64 h (1KB), SW128
__device__ __forceinline__ uint32_t toff(int r, int k, int AR) {
    uint32_t base = ((((uint32_t)k >> 6) * (uint32_t)AR + ((uint32_t)r >> 3)) << 10)
                  + (((uint32_t)r & 7) << 7) + (((uint32_t)k & 63) << 1);
    return base ^ ((base >> 3) & 0x70);
}
__device__ __forceinline__ uint32_t faddr(uint32_t base, int r, int k, int AR) {
    return base + ((((uint32_t)k >> 6) * (uint32_t)AR + ((uint32_t)r >> 3)) << 10)
         + (((uint32_t)r & 7) << 7) + ((((uint32_t)k & 63) << 1) ^ (((uint32_t)r & 7) << 4));
}
__device__ __forceinline__ void ldsm4(uint32_t* r, uint32_t addr) {
    asm volatile("ldmatrix.sync.aligned.m8n8.x4.shared.b16 {%0,%1,%2,%3}, [%4];"
        : "=r"(r[0]), "=r"(r[1]), "=r"(r[2]), "=r"(r[3]) : "r"(addr));
}
__device__ __forceinline__ void mma16816(float* c, const uint32_t* a, const uint32_t* b) {
    asm volatile("mma.sync.aligned.m16n8k16.row.col.f32.f16.f16.f32 "
        "{%0,%1,%2,%3}, {%4,%5,%6,%7}, {%8,%9}, {%0,%1,%2,%3};"
        : "+f"(c[0]), "+f"(c[1]), "+f"(c[2]), "+f"(c[3])
        : "r"(a[0]), "r"(a[1]), "r"(a[2]), "r"(a[3]), "r"(b[0]), "r"(b[1]));
}

// smem layout: A tile 16KB (64x128 fp16), B tile 32KB (128x128 fp16)
#define S_A0 0
#define S_B0 16384
#define MLP_SMEM 49152
#define XG_SINV 49152
#define XG_SMEM 49408
#define NT2 256

// stage fp32 64x128 A tile -> fp16 (AR=8)
__device__ __forceinline__ void stage_A64f(char* smem, const float* __restrict__ A,
                                           int row0, int tid) {
    const float4* A4 = (const float4*)(A + (size_t)row0 * 128);
#pragma unroll
    for (int i = tid; i < 2048; i += NT2) {
        int r = i >> 5, k = (i & 31) << 2;
        float4 a = A4[i];
        *(uint2*)(smem + S_A0 + toff(r, k, 8)) = make_uint2(
            pack_h2(__float2half_rn(a.x), __float2half_rn(a.y)),
            pack_h2(__float2half_rn(a.z), __float2half_rn(a.w)));
    }
}
// stage fp16 64x128 A tile -> direct copy (AR=8)
__device__ __forceinline__ void stage_A64h(char* smem, const __half* __restrict__ A,
                                           int row0, int tid) {
    const uint2* A2 = (const uint2*)(A + (size_t)row0 * 128);
#pragma unroll
    for (int i = tid; i < 2048; i += NT2) {
        int r = i >> 5, k = (i & 31) << 2;
        *(uint2*)(smem + S_A0 + toff(r, k, 8)) = A2[i];
    }
}
// stage 128x128 fp16 weights into B0 (AR=16)
__device__ __forceinline__ void stage_W(char* smem, const __half* __restrict__ Wh, int tid) {
    const uint2* H = (const uint2*)Wh;
#pragma unroll
    for (int i = tid; i < 4096; i += NT2) {
        int n = i >> 5, k = (i & 31) << 2;
        *(uint2*)(smem + S_B0 + toff(n, k, 16)) = H[i];
    }
}
// one accumulating MMA pass; 8 warps: grid 2(M,32) x 4(N,32)
template<int KMAX, int ARA, int ARB>
__device__ __forceinline__ void mma_pass(uint32_t ab, uint32_t bb, int wid, int lid,
                                         float acc[2][4][4]) {
    const int m0w = (wid >> 2) * 32;
    const int n0w = (wid & 3) * 32;
    const int arow = m0w + (lid & 7) + ((lid >> 3) & 1) * 8;
    const int akad = (lid >> 4) * 8;
    const int brow0 = n0w + (lid & 7) + (lid >> 4) * 8;
    const int bkad = ((lid >> 3) & 1) * 8;
#pragma unroll
    for (int k0 = 0; k0 < KMAX; k0 += 16) {
        uint32_t a[2][4], b[2][4];
        ldsm4(a[0], faddr(ab, arow,      k0 + akad, ARA));
        ldsm4(a[1], faddr(ab, arow + 16, k0 + akad, ARA));
        ldsm4(b[0], faddr(bb, brow0,      k0 + bkad, ARB));
        ldsm4(b[1], faddr(bb, brow0 + 16, k0 + bkad, ARB));
#pragma unroll
        for (int mf = 0; mf < 2; mf++)
#pragma unroll
            for (int nf = 0; nf < 4; nf++)
                mma16816(acc[mf][nf], a[mf], &b[nf >> 1][(nf & 1) * 2]);
    }
}
__device__ __forceinline__ void zero_acc(float acc[2][4][4]) {
#pragma unroll
    for (int mf = 0; mf < 2; mf++)
#pragma unroll
        for (int nf = 0; nf < 4; nf++)
#pragma unroll
            for (int j = 0; j < 4; j++) acc[mf][nf][j] = 0.f;
}

// ---------------- weight combine ----------------
__global__ void __launch_bounds__(256) k_combine(const float* __restrict__ We,
                                                 const float* __restrict__ Wg,
                                                 const float* __restrict__ be,
                                                 float* __restrict__ Wc,
                                                 float* __restrict__ bc) {
    const int col = threadIdx.x & 127;
    const int rr  = threadIdx.x >> 7;
    for (int p = 0; p < 4; p++) {
        int row = blockIdx.x * 8 + p * 2 + rr;
        float s = 0.f;
#pragma unroll 8
        for (int k = 0; k < 128; k++) s += We[row * 128 + k] * Wg[k * 128 + col];
        Wc[row * 128 + col] = s;
    }
    if (blockIdx.x == 0 && threadIdx.x < 128) {
        float s = 0.f;
        for (int k = 0; k < 128; k++) s += be[k] * Wg[k * 128 + col];
        bc[col] = s;
    }
}

// ---------------- weight prep: transpose + fp16 round ----------------
__global__ void __launch_bounds__(128) k_split(
    const float* W0, const float* W1, const float* W2, const float* W3,
    const float* W4, const float* W5,
    __half* wt0)
{
    extern __shared__ float s[];
    const float* Ws[6] = {W0, W1, W2, W3, W4, W5};
    const float* W = Ws[blockIdx.x];
    for (int i = threadIdx.x; i < 16384; i += 128) s[i] = W[i];
    __syncthreads();
    const int n = threadIdx.x;
    uint32_t* o0 = (uint32_t*)(wt0 + (size_t)blockIdx.x * 16384 + n * 128);
    for (int k = 0; k < 128; k += 2) {
        float v0 = s[k * 128 + n], v1 = s[(k + 1) * 128 + n];
        o0[k >> 1] = pack_h2(__float2half_rn(v0), __float2half_rn(v1));
    }
}

// ------------- fused x-GEMM + GCN (1 graph per block, 64 rows) -------------
__global__ void __launch_bounds__(NT2, 3) k_xgcn(
    const float* __restrict__ x,
    const __half* __restrict__ Wch,
    const float* __restrict__ bc, const float* __restrict__ b_gcn,
    const int* __restrict__ cntm,
    __half* __restrict__ h2)
{
    extern __shared__ char smem[];
    const uint32_t sb = smem_u32(smem);
    const int tid = threadIdx.x, wid = tid >> 5, lid = tid & 31;
    const int g = blockIdx.x;
    const int row0 = g * 64;
    const int* cg = cntm + ((size_t)g << 12);
    float* sinv = (float*)(smem + XG_SINV);

    stage_A64f(smem, x, row0, tid);
    stage_W(smem, Wch, tid);
    if (tid < 64) {
        int deg = 0;
#pragma unroll 8
        for (int s = 0; s < 64; s++) deg += cg[(s << 6) + tid];
        sinv[tid] = rsqrtf((float)deg + 1.f);
    }
    __syncthreads();

    // phase 1: hw = x @ Wc
    float acc[2][4][4];
    zero_acc(acc);
    mma_pass<128, 8, 16>(sb + S_A0, sb + S_B0, wid, lid, acc);

    const int m0w = (wid >> 2) * 32;
    const int n0w = (wid & 3) * 32;
    const int crow = lid >> 2;
    const int ccol = (lid & 3) * 2;

    __syncthreads();

    // restage ssrc^T = ((hw+bc)*inv[s])^T as [h][s] fp16 -> B0 (AR=16)
#pragma unroll
    for (int mf = 0; mf < 2; mf++) {
        int r = m0w + mf * 16 + crow;
        float iv0 = sinv[r], iv1 = sinv[r + 8];
#pragma unroll
        for (int nf = 0; nf < 4; nf++) {
            int cn = n0w + nf * 8 + ccol;
            float2 bv = *(const float2*)(bc + cn);
            *(__half*)(smem + S_B0 + toff(cn,     r,     16)) =
                __float2half_rn((acc[mf][nf][0] + bv.x) * iv0);
            *(__half*)(smem + S_B0 + toff(cn + 1, r,     16)) =
                __float2half_rn((acc[mf][nf][1] + bv.y) * iv0);
            *(__half*)(smem + S_B0 + toff(cn,     r + 8, 16)) =
                __float2half_rn((acc[mf][nf][2] + bv.x) * iv1);
            *(__half*)(smem + S_B0 + toff(cn + 1, r + 8, 16)) =
                __float2half_rn((acc[mf][nf][3] + bv.y) * iv1);
        }
    }
    // cnt tile (64x64, AR=8) -> A0 slot; A[d][s] = cg[s][d] + diag (exact in fp16)
    for (int i = tid; i < 4096; i += NT2) {
        int s = i >> 6, d = i & 63;
        float v = (float)cg[i] + (s == d ? 1.f : 0.f);
        *(__half*)(smem + S_A0 + toff(d, s, 8)) = __float2half_rn(v);
    }
    __syncthreads();

    // phase 2: agg = cnt @ ssrc (K=64)
    zero_acc(acc);
    mma_pass<64, 8, 16>(sb + S_A0, sb + S_B0, wid, lid, acc);

    // epilogue: h2 = relu(inv[d]*agg + b_gcn) -> fp16
#pragma unroll
    for (int mf = 0; mf < 2; mf++) {
        int r = m0w + mf * 16 + crow;
        float iv0 = sinv[r], iv1 = sinv[r + 8];
        __half* C0 = h2 + (size_t)(row0 + r) * 128;
#pragma unroll
        for (int nf = 0; nf < 4; nf++) {
            int cn = n0w + nf * 8 + ccol;
            float2 bg = *(const float2*)(b_gcn + cn);
            *(uint32_t*)(C0 + cn) = pack_h2(
                __float2half_rn(fmaxf(acc[mf][nf][0] * iv0 + bg.x, 0.f)),
                __float2half_rn(fmaxf(acc[mf][nf][1] * iv0 + bg.y, 0.f)));
            *(uint32_t*)(C0 + 8 * 128 + cn) = pack_h2(
                __float2half_rn(fmaxf(acc[mf][nf][2] * iv1 + bg.x, 0.f)),
                __float2half_rn(fmaxf(acc[mf][nf][3] * iv1 + bg.y, 0.f)));
        }
    }
}

// ---------------- fused 2-layer MLP (64-row tiles, fp16 in/out) ----------------
__global__ void __launch_bounds__(NT2, 3) k_mlp2(
    const __half* __restrict__ A,
    const __half* __restrict__ W1h, const float* __restrict__ b1,
    const __half* __restrict__ W2h, const float* __restrict__ b2,
    __half* __restrict__ Out)
{
    extern __shared__ char smem[];
    const uint32_t sb = smem_u32(smem);
    const int tid = threadIdx.x, wid = tid >> 5, lid = tid & 31;
    const int row0 = blockIdx.x * 64;

    stage_A64h(smem, A, row0, tid);
    stage_W(smem, W1h, tid);
    __syncthreads();

    float acc[2][4][4];
    zero_acc(acc);
    mma_pass<128, 8, 16>(sb + S_A0, sb + S_B0, wid, lid, acc);

    const int m0w = (wid >> 2) * 32;
    const int n0w = (wid & 3) * 32;
    const int crow = lid >> 2;
    const int ccol = (lid & 3) * 2;

    __syncthreads();

    // t = relu(acc + b1) -> restage fp16 into A0
#pragma unroll
    for (int mf = 0; mf < 2; mf++) {
        int r = m0w + mf * 16 + crow;
#pragma unroll
        for (int nf = 0; nf < 4; nf++) {
            int cn = n0w + nf * 8 + ccol;
            float2 bv = *(const float2*)(b1 + cn);
            *(uint32_t*)(smem + S_A0 + toff(r,     cn, 8)) = pack_h2(
                __float2half_rn(fmaxf(acc[mf][nf][0] + bv.x, 0.f)),
                __float2half_rn(fmaxf(acc[mf][nf][1] + bv.y, 0.f)));
            *(uint32_t*)(smem + S_A0 + toff(r + 8, cn, 8)) = pack_h2(
                __float2half_rn(fmaxf(acc[mf][nf][2] + bv.x, 0.f)),
                __float2half_rn(fmaxf(acc[mf][nf][3] + bv.y, 0.f)));
        }
    }
    stage_W(smem, W2h, tid);
    __syncthreads();

    zero_acc(acc);
    mma_pass<128, 8, 16>(sb + S_A0, sb + S_B0, wid, lid, acc);

#pragma unroll
    for (int mf = 0; mf < 2; mf++) {
        int gr = row0 + m0w + mf * 16 + crow;
        __half* C0 = Out + (size_t)gr * 128;
#pragma unroll
        for (int nf = 0; nf < 4; nf++) {
            int cn = n0w + nf * 8 + ccol;
            float2 bv = *(const float2*)(b2 + cn);
            *(uint32_t*)(C0 + cn) = pack_h2(
                __float2half_rn(acc[mf][nf][0] + bv.x),
                __float2half_rn(acc[mf][nf][1] + bv.y));
            *(uint32_t*)(C0 + 8 * 128 + cn) = pack_h2(
                __float2half_rn(acc[mf][nf][2] + bv.x),
                __float2half_rn(acc[mf][nf][3] + bv.y));
        }
    }
}

// ---------------- edge count matrix ----------------
__global__ void k_edges(const int* __restrict__ ei, int* __restrict__ cntm) {
    int e = blockIdx.x * blockDim.x + threadIdx.x;
    int s = ei[e];
    int d = ei[EE + e];
    if ((unsigned)s >= NN || (unsigned)d >= NN) return;
    int g = s >> 6;
    atomicAdd(&cntm[(g << 12) | ((s & 63) << 6) | (d & 63)], 1);
}

// ---------------- per-graph attention + weighted pool (256 thr, fp16 in/out) ------------
__global__ void __launch_bounds__(256) k_att(const __half* __restrict__ h2,
                                             const __half* __restrict__ aff,
                                             const float* __restrict__ vemb,
                                             const float* __restrict__ eweights,
                                             __half* __restrict__ vn_out)
{
    extern __shared__ float sm[];
    float* hgs   = sm;
    float* affs  = sm + NPG*HH;
    float* vembT = sm + 2*NPG*HH;
    float* sew   = vembT + HH*33;

    const int g = blockIdx.x, tid = threadIdx.x;

    const uint2* hg2 = (const uint2*)(h2  + (size_t)g*NPG*HH);
    const uint2* af2 = (const uint2*)(aff + (size_t)g*NPG*HH);
    float4* hgs4  = (float4*)hgs;
    float4* affs4 = (float4*)affs;
    for (int i = tid; i < NPG*HH/4; i += 256) {
        uint2 th = hg2[i];
        float2 h0 = __half22float2(*(__half2*)&th.x);
        float2 h1 = __half22float2(*(__half2*)&th.y);
        hgs4[i] = make_float4(h0.x, h0.y, h1.x, h1.y);
        uint2 ta = af2[i];
        float2 a0 = __half22float2(*(__half2*)&ta.x);
        float2 a1 = __half22float2(*(__half2*)&ta.y);
        affs4[i] = make_float4(a0.x, a0.y, a1.x, a1.y);
    }

    const float* vg = vemb + (size_t)g*VV*HH;
    for (int i = tid; i < VV*HH; i += 256) {
        int v = i >> 7, k = i & 127;
        vembT[k*33 + v] = vg[i];
    }
    __syncthreads();

    const int v  = tid & 31;
    const int ng = tid >> 5;
    const float* ew_g = eweights + (size_t)g*NPG*VV;
    const float scale = 0.08838834764831845f;

    for (int c = 0; c < 2; c++) {
        int n0 = ng*8 + c*4;
        float acc0 = 0.f, acc1 = 0.f, acc2 = 0.f, acc3 = 0.f;
#pragma unroll 4
        for (int kq = 0; kq < 32; kq++) {
            float4 a0 = affs4[(n0+0)*32 + kq];
            float4 a1 = affs4[(n0+1)*32 + kq];
            float4 a2 = affs4[(n0+2)*32 + kq];
            float4 a3 = affs4[(n0+3)*32 + kq];
            float w0 = vembT[(kq*4+0)*33 + v];
            float w1 = vembT[(kq*4+1)*33 + v];
            float w2 = vembT[(kq*4+2)*33 + v];
            float w3 = vembT[(kq*4+3)*33 + v];
            acc0 += a0.x*w0 + a0.y*w1 + a0.z*w2 + a0.w*w3;
            acc1 += a1.x*w0 + a1.y*w1 + a1.z*w2 + a1.w*w3;
            acc2 += a2.x*w0 + a2.y*w1 + a2.z*w2 + a2.w*w3;
            acc3 += a3.x*w0 + a3.y*w1 + a3.z*w2 + a3.w*w3;
        }
        float accs[4] = {acc0, acc1, acc2, acc3};
#pragma unroll
        for (int j = 0; j < 4; j++) {
            int n = n0 + j;
            float att = accs[j] * scale;
            float sg = 1.f / (1.f + expf(-att));
            sew[n*32 + v] = ew_g[n*32 + v] * (1.f + sg);
        }
    }
    __syncthreads();

    if (tid < NPG) {
        float rs = 0.f;
        for (int v2 = 0; v2 < VV; v2++) rs += sew[tid*32 + v2];
        float denom = (rs == 0.f) ? 1.f : rs;
        float ivr = 1.f / denom;
        for (int v2 = 0; v2 < VV; v2++) sew[tid*32 + v2] *= ivr;
    }
    __syncthreads();

    const int c4  = tid & 31;
    const int vgp = tid >> 5;
    {
        int vb = vgp*4;
        float4 acc[4];
#pragma unroll
        for (int u = 0; u < 4; u++) acc[u] = make_float4(0.f, 0.f, 0.f, 0.f);
        for (int n = 0; n < NPG; n++) {
            float4 hv = hgs4[n*32 + c4];
#pragma unroll
            for (int u = 0; u < 4; u++) {
                float w = sew[n*32 + vb + u];
                acc[u].x += w*hv.x; acc[u].y += w*hv.y;
                acc[u].z += w*hv.z; acc[u].w += w*hv.w;
            }
        }
#pragma unroll
        for (int u = 0; u < 4; u++) {
            uint2 o = make_uint2(
                pack_h2(__float2half_rn(acc[u].x), __float2half_rn(acc[u].y)),
                pack_h2(__float2half_rn(acc[u].z), __float2half_rn(acc[u].w)));
            ((uint2*)(vn_out + (size_t)(g*VV + vb + u)*HH))[c4] = o;
        }
    }
}

// -------- fused tail: gf = meanV(vn2); out = relu(gf@W1+b1)@W2 + b2 --------
__global__ void __launch_bounds__(NT2, 3) k_gfhead(
    const __half* __restrict__ vn2,
    const __half* __restrict__ W1h, const float* __restrict__ b1,
    const float* __restrict__ W2, const float* __restrict__ b2,
    float* __restrict__ out)
{
    extern __shared__ char smem[];
    const uint32_t sb = smem_u32(smem);
    const int tid = threadIdx.x, wid = tid >> 5, lid = tid & 31;
    const int row0 = blockIdx.x * 64;   // graph index base

    // stage A: mean over V of vn2[g][v][:] -> fp16 A0
    for (int i = tid; i < 2048; i += NT2) {
        int r = i >> 5, kq = i & 31;
        const uint2* src = (const uint2*)vn2 + (size_t)(row0 + r) * VV * 32 + kq;
        float4 a = make_float4(0.f, 0.f, 0.f, 0.f);
#pragma unroll 8
        for (int v = 0; v < VV; v++) {
            uint2 t = src[v * 32];
            float2 f0 = __half22float2(*(__half2*)&t.x);
            float2 f1 = __half22float2(*(__half2*)&t.y);
            a.x += f0.x; a.y += f0.y; a.z += f1.x; a.w += f1.y;
        }
        a.x *= (1.f/32.f); a.y *= (1.f/32.f); a.z *= (1.f/32.f); a.w *= (1.f/32.f);
        *(uint2*)(smem + S_A0 + toff(r, kq << 2, 8)) = make_uint2(
            pack_h2(__float2half_rn(a.x), __float2half_rn(a.y)),
            pack_h2(__float2half_rn(a.z), __float2half_rn(a.w)));
    }
    stage_W(smem, W1h, tid);
    __syncthreads();

    float acc[2][4][4];
    zero_acc(acc);
    mma_pass<128, 8, 16>(sb + S_A0, sb + S_B0, wid, lid, acc);

    const int m0w = (wid >> 2) * 32;
    const int n0w = (wid & 3) * 32;
    const int crow = lid >> 2;
    const int ccol = (lid & 3) * 2;

    __syncthreads();   // MMA reads done; repurpose B0 as fp32 gf buffer

    float* gfs = (float*)(smem + S_B0);      // 64 x 128 fp32 (32 KB)
#pragma unroll
    for (int mf = 0; mf < 2; mf++) {
        int r = m0w + mf * 16 + crow;
#pragma unroll
        for (int nf = 0; nf < 4; nf++) {
            int cn = n0w + nf * 8 + ccol;
            float2 bv = *(const float2*)(b1 + cn);
            gfs[r * 128 + cn]           = fmaxf(acc[mf][nf][0] + bv.x, 0.f);
            gfs[r * 128 + cn + 1]       = fmaxf(acc[mf][nf][1] + bv.y, 0.f);
            gfs[(r + 8) * 128 + cn]     = fmaxf(acc[mf][nf][2] + bv.x, 0.f);
            gfs[(r + 8) * 128 + cn + 1] = fmaxf(acc[mf][nf][3] + bv.y, 0.f);
        }
    }
    // stage W2 (128x10) + b2 into A0 region as fp32
    float* w2s = (float*)(smem + S_A0);      // 1280 floats
    float* b2s = w2s + 1280;
    for (int i = tid; i < 1280; i += NT2) w2s[i] = W2[i];
    if (tid < NOUT) b2s[tid] = b2[tid];
    __syncthreads();

    // head: out[row][o] = b2[o] + sum_k gf[row][k]*W2[k][o]
    for (int t = tid; t < 64 * NOUT; t += NT2) {
        int row = t / NOUT, o = t - row * NOUT;
        const float* gr = gfs + row * 128;
        float s = b2s[o];
#pragma unroll 8
        for (int k = 0; k < 128; k++) s += gr[k] * w2s[k * NOUT + o];
        out[(size_t)(row0 + row) * NOUT + o] = s;
    }
}

// ---------------- launcher ----------------
extern "C" void kernel_launch(void* const* d_in, const int* in_sizes, int n_in,
                              void* d_out, int out_size)
{
    (void)in_sizes; (void)n_in; (void)out_size;
    const float* x        = (const float*)d_in[0];
    const int*   ei       = (const int*)d_in[1];
    const float* eweights = (const float*)d_in[3];
    const float* vemb     = (const float*)d_in[4];
    const float* W_emb  = (const float*)d_in[5];  const float* b_emb  = (const float*)d_in[6];
    const float* W_gcn  = (const float*)d_in[7];  const float* b_gcn  = (const float*)d_in[8];
    const float* aff_W1 = (const float*)d_in[9];  const float* aff_b1 = (const float*)d_in[10];
    const float* aff_W2 = (const float*)d_in[11]; const float* aff_b2 = (const float*)d_in[12];
    const float* vn_W1  = (const float*)d_in[13]; const float* vn_b1  = (const float*)d_in[14];
    const float* vn_W2  = (const float*)d_in[15]; const float* vn_b2  = (const float*)d_in[16];
    const float* mlp_W1 = (const float*)d_in[17]; const float* mlp_b1 = (const float*)d_in[18];
    const float* mlp_W2 = (const float*)d_in[19]; const float* mlp_b2 = (const float*)d_in[20];
    float* out = (float*)d_out;

    __half *p_h2, *p_aff, *p_vn, *p_vn2, *p_wt0;
    float *p_wc, *p_bc;
    int *p_cntm;
    cudaGetSymbolAddress((void**)&p_h2,   d_h2);
    cudaGetSymbolAddress((void**)&p_aff,  d_aff);
    cudaGetSymbolAddress((void**)&p_cntm, d_cntm);
    cudaGetSymbolAddress((void**)&p_vn,   d_vn);
    cudaGetSymbolAddress((void**)&p_vn2,  d_vn2);
    cudaGetSymbolAddress((void**)&p_wc,   d_wc);
    cudaGetSymbolAddress((void**)&p_bc,   d_bc);
    cudaGetSymbolAddress((void**)&p_wt0,  d_wt0);

    const int ATT_SMEM = (2*NPG*HH + HH*33 + NPG*VV) * (int)sizeof(float);
    cudaFuncSetAttribute(k_split,  cudaFuncAttributeMaxDynamicSharedMemorySize, 65536);
    cudaFuncSetAttribute(k_xgcn,   cudaFuncAttributeMaxDynamicSharedMemorySize, XG_SMEM);
    cudaFuncSetAttribute(k_mlp2,   cudaFuncAttributeMaxDynamicSharedMemorySize, MLP_SMEM);
    cudaFuncSetAttribute(k_gfhead, cudaFuncAttributeMaxDynamicSharedMemorySize, MLP_SMEM);
    cudaFuncSetAttribute(k_att,    cudaFuncAttributeMaxDynamicSharedMemorySize, ATT_SMEM);

    #define WT0(i) (p_wt0 + (size_t)(i) * 16384)

    // 0) combined weight + fp16 weight prep (slots: 0=Wc, 1=aff1, 2=aff2, 3=vn1, 4=vn2, 5=mlp1)
    k_combine<<<16, 256>>>(W_emb, W_gcn, b_emb, p_wc, p_bc);
    k_split<<<6, 128, 65536>>>(p_wc, aff_W1, aff_W2, vn_W1, vn_W2, mlp_W1, p_wt0);

    // 1) edge count matrix
    cudaMemsetAsync(p_cntm, 0, (size_t)GG * NPG * NPG * sizeof(int));
    k_edges<<<EE/256, 256>>>(ei, p_cntm);

    // 2) fused x-GEMM + GCN -> h2 (fp16)
    k_xgcn<<<GG, NT2, XG_SMEM>>>(x, WT0(0), p_bc, b_gcn, p_cntm, p_h2);

    // 3) affinity MLP
    k_mlp2<<<NN/64, NT2, MLP_SMEM>>>(p_h2, WT0(1), aff_b1, WT0(2), aff_b2, p_aff);

    // 4) attention vs virtual nodes + weighted pool
    k_att<<<GG, 256, ATT_SMEM>>>(p_h2, p_aff, vemb, eweights, p_vn);

    // 5) virtual-node MLP
    k_mlp2<<<GG*VV/64, NT2, MLP_SMEM>>>(p_vn, WT0(3), vn_b1, WT0(4), vn_b2, p_vn2);

    // 6) fused mean-over-V + final MLP + head
    k_gfhead<<<GG/64, NT2, MLP_SMEM>>>(p_vn2, WT0(5), mlp_b1, mlp_W2, mlp_b2, out);
}

// round 15
// speedup vs baseline: 1.5435x; 1.1276x over previous
#include <cuda_runtime.h>
#include <cuda_fp16.h>
#include <math.h>
#include <stdint.h>

#define NN   65536
#define GG   1024
#define NPG  64
#define VV   32
#define HH   128
#define EE   1048576
#define NOUT 10

// ---------------- scratch ----------------
__device__ __half d_h2 [NN*HH];
__device__ __half d_aff[NN*HH];
__device__ int    d_cntm[GG*NPG*NPG];
__device__ __half d_vn [GG*VV*HH];
__device__ __half d_vn2[GG*VV*HH];
__device__ float  d_wc [HH*HH];
__device__ float  d_bc [HH];
__device__ __half d_wt0[6*HH*HH];   // weights (transposed [n][k], fp16)

// ================= helpers =================
__device__ __forceinline__ uint32_t smem_u32(const void* p) {
    uint32_t a;
    asm("{ .reg .u64 t; cvta.to.shared.u64 t, %1; cvt.u32.u64 %0, t; }" : "=r"(a) : "l"(p));
    return a;
}
__device__ __forceinline__ uint32_t pack_h2(__half lo, __half hi) {
    return (uint32_t)__half_as_ushort(lo) | ((uint32_t)__half_as_ushort(hi) << 16);
}
// compact blocked K-major tile, AR = atom-rows (rows/8); atom = 8r x 64 h (1KB), SW128
__device__ __forceinline__ uint32_t toff(int r, int k, int AR) {
    uint32_t base = ((((uint32_t)k >> 6) * (uint32_t)AR + ((uint32_t)r >> 3)) << 10)
                  + (((uint32_t)r & 7) << 7) + (((uint32_t)k & 63) << 1);
    return base ^ ((base >> 3) & 0x70);
}
__device__ __forceinline__ uint32_t faddr(uint32_t base, int r, int k, int AR) {
    return base + ((((uint32_t)k >> 6) * (uint32_t)AR + ((uint32_t)r >> 3)) << 10)
         + (((uint32_t)r & 7) << 7) + ((((uint32_t)k & 63) << 1) ^ (((uint32_t)r & 7) << 4));
}
__device__ __forceinline__ void ldsm4(uint32_t* r, uint32_t addr) {
    asm volatile("ldmatrix.sync.aligned.m8n8.x4.shared.b16 {%0,%1,%2,%3}, [%4];"
        : "=r"(r[0]), "=r"(r[1]), "=r"(r[2]), "=r"(r[3]) : "r"(addr));
}
__device__ __forceinline__ void mma16816(float* c, const uint32_t* a, const uint32_t* b) {
    asm volatile("mma.sync.aligned.m16n8k16.row.col.f32.f16.f16.f32 "
        "{%0,%1,%2,%3}, {%4,%5,%6,%7}, {%8,%9}, {%0,%1,%2,%3};"
        : "+f"(c[0]), "+f"(c[1]), "+f"(c[2]), "+f"(c[3])
        : "r"(a[0]), "r"(a[1]), "r"(a[2]), "r"(a[3]), "r"(b[0]), "r"(b[1]));
}

// smem layout: A tile 16KB (64x128 fp16), B tile 32KB (128x128 fp16)
#define S_A0 0
#define S_B0 16384
#define MLP_SMEM 49152
#define XG_SINV 49152
#define XG_SMEM 49408
#define NT2 256

// k_att layout
#define ATT_A0 0        // aff tile (AR=8); later ewT (AR=4)
#define ATT_B0 16384    // vemb B tile region (rows 0-31 staged, AR=16)
#define ATT_HT 49152    // hgT (AR=16, K=64) 16KB
#define ATT_SEW 65536   // ew fp32, stride 33
#define ATT_SMEM (65536 + 64*33*4)

// stage fp32 64x128 A tile -> fp16 (AR=8)
__device__ __forceinline__ void stage_A64f(char* smem, const float* __restrict__ A,
                                           int row0, int tid) {
    const float4* A4 = (const float4*)(A + (size_t)row0 * 128);
#pragma unroll
    for (int i = tid; i < 2048; i += NT2) {
        int r = i >> 5, k = (i & 31) << 2;
        float4 a = A4[i];
        *(uint2*)(smem + S_A0 + toff(r, k, 8)) = make_uint2(
            pack_h2(__float2half_rn(a.x), __float2half_rn(a.y)),
            pack_h2(__float2half_rn(a.z), __float2half_rn(a.w)));
    }
}
// stage fp16 64x128 A tile -> direct copy (AR=8)
__device__ __forceinline__ void stage_A64h(char* smem, const __half* __restrict__ A,
                                           int row0, int tid) {
    const uint2* A2 = (const uint2*)(A + (size_t)row0 * 128);
#pragma unroll
    for (int i = tid; i < 2048; i += NT2) {
        int r = i >> 5, k = (i & 31) << 2;
        *(uint2*)(smem + S_A0 + toff(r, k, 8)) = A2[i];
    }
}
// stage 128x128 fp16 weights into B0 (AR=16)
__device__ __forceinline__ void stage_W(char* smem, const __half* __restrict__ Wh, int tid) {
    const uint2* H = (const uint2*)Wh;
#pragma unroll
    for (int i = tid; i < 4096; i += NT2) {
        int n = i >> 5, k = (i & 31) << 2;
        *(uint2*)(smem + S_B0 + toff(n, k, 16)) = H[i];
    }
}
// one accumulating MMA pass; 8 warps: grid 2(M,32) x 4(N,32)
template<int KMAX, int ARA, int ARB>
__device__ __forceinline__ void mma_pass(uint32_t ab, uint32_t bb, int wid, int lid,
                                         float acc[2][4][4]) {
    const int m0w = (wid >> 2) * 32;
    const int n0w = (wid & 3) * 32;
    const int arow = m0w + (lid & 7) + ((lid >> 3) & 1) * 8;
    const int akad = (lid >> 4) * 8;
    const int brow0 = n0w + (lid & 7) + (lid >> 4) * 8;
    const int bkad = ((lid >> 3) & 1) * 8;
#pragma unroll
    for (int k0 = 0; k0 < KMAX; k0 += 16) {
        uint32_t a[2][4], b[2][4];
        ldsm4(a[0], faddr(ab, arow,      k0 + akad, ARA));
        ldsm4(a[1], faddr(ab, arow + 16, k0 + akad, ARA));
        ldsm4(b[0], faddr(bb, brow0,      k0 + bkad, ARB));
        ldsm4(b[1], faddr(bb, brow0 + 16, k0 + bkad, ARB));
#pragma unroll
        for (int mf = 0; mf < 2; mf++)
#pragma unroll
            for (int nf = 0; nf < 4; nf++)
                mma16816(acc[mf][nf], a[mf], &b[nf >> 1][(nf & 1) * 2]);
    }
}
__device__ __forceinline__ void zero_acc(float acc[2][4][4]) {
#pragma unroll
    for (int mf = 0; mf < 2; mf++)
#pragma unroll
        for (int nf = 0; nf < 4; nf++)
#pragma unroll
            for (int j = 0; j < 4; j++) acc[mf][nf][j] = 0.f;
}

// ---------------- weight combine ----------------
__global__ void __launch_bounds__(256) k_combine(const float* __restrict__ We,
                                                 const float* __restrict__ Wg,
                                                 const float* __restrict__ be,
                                                 float* __restrict__ Wc,
                                                 float* __restrict__ bc) {
    const int col = threadIdx.x & 127;
    const int rr  = threadIdx.x >> 7;
    for (int p = 0; p < 4; p++) {
        int row = blockIdx.x * 8 + p * 2 + rr;
        float s = 0.f;
#pragma unroll 8
        for (int k = 0; k < 128; k++) s += We[row * 128 + k] * Wg[k * 128 + col];
        Wc[row * 128 + col] = s;
    }
    if (blockIdx.x == 0 && threadIdx.x < 128) {
        float s = 0.f;
        for (int k = 0; k < 128; k++) s += be[k] * Wg[k * 128 + col];
        bc[col] = s;
    }
}

// ---------------- weight prep: transpose + fp16 round ----------------
__global__ void __launch_bounds__(128) k_split(
    const float* W0, const float* W1, const float* W2, const float* W3,
    const float* W4, const float* W5,
    __half* wt0)
{
    extern __shared__ float s[];
    const float* Ws[6] = {W0, W1, W2, W3, W4, W5};
    const float* W = Ws[blockIdx.x];
    for (int i = threadIdx.x; i < 16384; i += 128) s[i] = W[i];
    __syncthreads();
    const int n = threadIdx.x;
    uint32_t* o0 = (uint32_t*)(wt0 + (size_t)blockIdx.x * 16384 + n * 128);
    for (int k = 0; k < 128; k += 2) {
        float v0 = s[k * 128 + n], v1 = s[(k + 1) * 128 + n];
        o0[k >> 1] = pack_h2(__float2half_rn(v0), __float2half_rn(v1));
    }
}

// ------------- fused x-GEMM + GCN (1 graph per block, 64 rows) -------------
__global__ void __launch_bounds__(NT2, 3) k_xgcn(
    const float* __restrict__ x,
    const __half* __restrict__ Wch,
    const float* __restrict__ bc, const float* __restrict__ b_gcn,
    const int* __restrict__ cntm,
    __half* __restrict__ h2)
{
    extern __shared__ char smem[];
    const uint32_t sb = smem_u32(smem);
    const int tid = threadIdx.x, wid = tid >> 5, lid = tid & 31;
    const int g = blockIdx.x;
    const int row0 = g * 64;
    const int* cg = cntm + ((size_t)g << 12);
    float* sinv = (float*)(smem + XG_SINV);

    stage_A64f(smem, x, row0, tid);
    stage_W(smem, Wch, tid);
    if (tid < 64) {
        int deg = 0;
#pragma unroll 8
        for (int s = 0; s < 64; s++) deg += cg[(s << 6) + tid];
        sinv[tid] = rsqrtf((float)deg + 1.f);
    }
    __syncthreads();

    float acc[2][4][4];
    zero_acc(acc);
    mma_pass<128, 8, 16>(sb + S_A0, sb + S_B0, wid, lid, acc);

    const int m0w = (wid >> 2) * 32;
    const int n0w = (wid & 3) * 32;
    const int crow = lid >> 2;
    const int ccol = (lid & 3) * 2;

    __syncthreads();

#pragma unroll
    for (int mf = 0; mf < 2; mf++) {
        int r = m0w + mf * 16 + crow;
        float iv0 = sinv[r], iv1 = sinv[r + 8];
#pragma unroll
        for (int nf = 0; nf < 4; nf++) {
            int cn = n0w + nf * 8 + ccol;
            float2 bv = *(const float2*)(bc + cn);
            *(__half*)(smem + S_B0 + toff(cn,     r,     16)) =
                __float2half_rn((acc[mf][nf][0] + bv.x) * iv0);
            *(__half*)(smem + S_B0 + toff(cn + 1, r,     16)) =
                __float2half_rn((acc[mf][nf][1] + bv.y) * iv0);
            *(__half*)(smem + S_B0 + toff(cn,     r + 8, 16)) =
                __float2half_rn((acc[mf][nf][2] + bv.x) * iv1);
            *(__half*)(smem + S_B0 + toff(cn + 1, r + 8, 16)) =
                __float2half_rn((acc[mf][nf][3] + bv.y) * iv1);
        }
    }
    for (int i = tid; i < 4096; i += NT2) {
        int s = i >> 6, d = i & 63;
        float v = (float)cg[i] + (s == d ? 1.f : 0.f);
        *(__half*)(smem + S_A0 + toff(d, s, 8)) = __float2half_rn(v);
    }
    __syncthreads();

    zero_acc(acc);
    mma_pass<64, 8, 16>(sb + S_A0, sb + S_B0, wid, lid, acc);

#pragma unroll
    for (int mf = 0; mf < 2; mf++) {
        int r = m0w + mf * 16 + crow;
        float iv0 = sinv[r], iv1 = sinv[r + 8];
        __half* C0 = h2 + (size_t)(row0 + r) * 128;
#pragma unroll
        for (int nf = 0; nf < 4; nf++) {
            int cn = n0w + nf * 8 + ccol;
            float2 bg = *(const float2*)(b_gcn + cn);
            *(uint32_t*)(C0 + cn) = pack_h2(
                __float2half_rn(fmaxf(acc[mf][nf][0] * iv0 + bg.x, 0.f)),
                __float2half_rn(fmaxf(acc[mf][nf][1] * iv0 + bg.y, 0.f)));
            *(uint32_t*)(C0 + 8 * 128 + cn) = pack_h2(
                __float2half_rn(fmaxf(acc[mf][nf][2] * iv1 + bg.x, 0.f)),
                __float2half_rn(fmaxf(acc[mf][nf][3] * iv1 + bg.y, 0.f)));
        }
    }
}

// ---------------- fused 2-layer MLP (64-row tiles, fp16 in/out) ----------------
__global__ void __launch_bounds__(NT2, 3) k_mlp2(
    const __half* __restrict__ A,
    const __half* __restrict__ W1h, const float* __restrict__ b1,
    const __half* __restrict__ W2h, const float* __restrict__ b2,
    __half* __restrict__ Out)
{
    extern __shared__ char smem[];
    const uint32_t sb = smem_u32(smem);
    const int tid = threadIdx.x, wid = tid >> 5, lid = tid & 31;
    const int row0 = blockIdx.x * 64;

    stage_A64h(smem, A, row0, tid);
    stage_W(smem, W1h, tid);
    __syncthreads();

    float acc[2][4][4];
    zero_acc(acc);
    mma_pass<128, 8, 16>(sb + S_A0, sb + S_B0, wid, lid, acc);

    const int m0w = (wid >> 2) * 32;
    const int n0w = (wid & 3) * 32;
    const int crow = lid >> 2;
    const int ccol = (lid & 3) * 2;

    __syncthreads();

#pragma unroll
    for (int mf = 0; mf < 2; mf++) {
        int r = m0w + mf * 16 + crow;
#pragma unroll
        for (int nf = 0; nf < 4; nf++) {
            int cn = n0w + nf * 8 + ccol;
            float2 bv = *(const float2*)(b1 + cn);
            *(uint32_t*)(smem + S_A0 + toff(r,     cn, 8)) = pack_h2(
                __float2half_rn(fmaxf(acc[mf][nf][0] + bv.x, 0.f)),
                __float2half_rn(fmaxf(acc[mf][nf][1] + bv.y, 0.f)));
            *(uint32_t*)(smem + S_A0 + toff(r + 8, cn, 8)) = pack_h2(
                __float2half_rn(fmaxf(acc[mf][nf][2] + bv.x, 0.f)),
                __float2half_rn(fmaxf(acc[mf][nf][3] + bv.y, 0.f)));
        }
    }
    stage_W(smem, W2h, tid);
    __syncthreads();

    zero_acc(acc);
    mma_pass<128, 8, 16>(sb + S_A0, sb + S_B0, wid, lid, acc);

#pragma unroll
    for (int mf = 0; mf < 2; mf++) {
        int gr = row0 + m0w + mf * 16 + crow;
        __half* C0 = Out + (size_t)gr * 128;
#pragma unroll
        for (int nf = 0; nf < 4; nf++) {
            int cn = n0w + nf * 8 + ccol;
            float2 bv = *(const float2*)(b2 + cn);
            *(uint32_t*)(C0 + cn) = pack_h2(
                __float2half_rn(acc[mf][nf][0] + bv.x),
                __float2half_rn(acc[mf][nf][1] + bv.y));
            *(uint32_t*)(C0 + 8 * 128 + cn) = pack_h2(
                __float2half_rn(acc[mf][nf][2] + bv.x),
                __float2half_rn(acc[mf][nf][3] + bv.y));
        }
    }
}

// ---------------- edge count matrix ----------------
__global__ void k_edges(const int* __restrict__ ei, int* __restrict__ cntm) {
    int e = blockIdx.x * blockDim.x + threadIdx.x;
    int s = ei[e];
    int d = ei[EE + e];
    if ((unsigned)s >= NN || (unsigned)d >= NN) return;
    int g = s >> 6;
    atomicAdd(&cntm[(g << 12) | ((s & 63) << 6) | (d & 63)], 1);
}

// -------- per-graph attention + pool via HMMA (1 graph per block) --------
__global__ void __launch_bounds__(NT2, 2) k_att(
    const __half* __restrict__ h2,
    const __half* __restrict__ aff,
    const float* __restrict__ vemb,
    const float* __restrict__ eweights,
    __half* __restrict__ vn_out)
{
    extern __shared__ char smem[];
    const uint32_t sb = smem_u32(smem);
    const int tid = threadIdx.x, wid = tid >> 5, lid = tid & 31;
    const int g = blockIdx.x;
    float* sew = (float*)(smem + ATT_SEW);      // [n][v] stride 33

    // stage aff as A tile (fp16 direct)
    stage_A64h(smem + ATT_A0, aff, g * 64, tid);
    // stage vemb rows 0-31 as B tile [v][k=h] fp16 (AR=16; rows 32+ garbage/unused)
    {
        const float4* vg4 = (const float4*)(vemb + (size_t)g * VV * HH);
        for (int i = tid; i < 1024; i += NT2) {
            int v = i >> 5, k = (i & 31) << 2;
            float4 a = vg4[i];
            *(uint2*)(smem + ATT_B0 + toff(v, k, 16)) = make_uint2(
                pack_h2(__float2half_rn(a.x), __float2half_rn(a.y)),
                pack_h2(__float2half_rn(a.z), __float2half_rn(a.w)));
        }
    }
    // stage hgT: h2[n][h] -> smem [h][n] fp16 (AR=16, K=64)
    {
        const uint2* hg2 = (const uint2*)(h2 + (size_t)g * NPG * HH);
        for (int i = tid; i < 2048; i += NT2) {
            int n = i >> 5, h4 = (i & 31) << 2;
            uint2 t = hg2[i];
            __half2 p0 = *(__half2*)&t.x;
            __half2 p1 = *(__half2*)&t.y;
            *(__half*)(smem + ATT_HT + toff(h4,     n, 16)) = __low2half(p0);
            *(__half*)(smem + ATT_HT + toff(h4 + 1, n, 16)) = __high2half(p0);
            *(__half*)(smem + ATT_HT + toff(h4 + 2, n, 16)) = __low2half(p1);
            *(__half*)(smem + ATT_HT + toff(h4 + 3, n, 16)) = __high2half(p1);
        }
    }
    __syncthreads();

    // score MMA: att[64][32] (useful in warps with n0w==0)
    float acc[2][4][4];
    zero_acc(acc);
    mma_pass<128, 8, 16>(sb + ATT_A0, sb + ATT_B0, wid, lid, acc);

    const int m0w = (wid >> 2) * 32;
    const int n0w = (wid & 3) * 32;
    const int crow = lid >> 2;
    const int ccol = (lid & 3) * 2;

    // ew = eweights * (1 + sigmoid(att/sqrt(128)))
    if (n0w == 0) {
        const float* ew_g = eweights + (size_t)g * NPG * VV;
        const float scale = 0.08838834764831845f;
#pragma unroll
        for (int mf = 0; mf < 2; mf++) {
            int n = m0w + mf * 16 + crow;
#pragma unroll
            for (int nf = 0; nf < 4; nf++) {
                int v = nf * 8 + ccol;
#pragma unroll
                for (int j = 0; j < 4; j++) {
                    int nn = n + (j >> 1) * 8;
                    int vv = v + (j & 1);
                    float att = acc[mf][nf][j] * scale;
                    float sg = 1.f / (1.f + expf(-att));
                    sew[nn * 33 + vv] = ew_g[nn * 32 + vv] * (1.f + sg);
                }
            }
        }
    }
    __syncthreads();

    // row-normalize (stride 33: conflict-free)
    if (tid < NPG) {
        float rs = 0.f;
#pragma unroll 8
        for (int v = 0; v < VV; v++) rs += sew[tid * 33 + v];
        float ivr = 1.f / ((rs == 0.f) ? 1.f : rs);
#pragma unroll 8
        for (int v = 0; v < VV; v++) sew[tid * 33 + v] *= ivr;
    }
    __syncthreads();

    // restage ewT [v][n] fp16 into A0 (AR=4)
    for (int i = tid; i < 2048; i += NT2) {
        int v = i >> 6, n = i & 63;
        *(__half*)(smem + ATT_A0 + toff(v, n, 4)) = __float2half_rn(sew[n * 33 + v]);
    }
    __syncthreads();

    // pooling MMA: vn[32][128] = ewT @ hgT (warps 0-3 useful)
    zero_acc(acc);
    mma_pass<64, 4, 16>(sb + ATT_A0, sb + ATT_HT, wid, lid, acc);

    if (m0w == 0) {
#pragma unroll
        for (int mf = 0; mf < 2; mf++) {
            int v = mf * 16 + crow;
            __half* C0 = vn_out + (size_t)(g * VV + v) * 128;
            __half* C8 = vn_out + (size_t)(g * VV + v + 8) * 128;
#pragma unroll
            for (int nf = 0; nf < 4; nf++) {
                int cn = n0w + nf * 8 + ccol;
                *(uint32_t*)(C0 + cn) = pack_h2(
                    __float2half_rn(acc[mf][nf][0]), __float2half_rn(acc[mf][nf][1]));
                *(uint32_t*)(C8 + cn) = pack_h2(
                    __float2half_rn(acc[mf][nf][2]), __float2half_rn(acc[mf][nf][3]));
            }
        }
    }
}

// -------- fused tail: gf = meanV(vn2); out = relu(gf@W1+b1)@W2 + b2 --------
__global__ void __launch_bounds__(NT2, 3) k_gfhead(
    const __half* __restrict__ vn2,
    const __half* __restrict__ W1h, const float* __restrict__ b1,
    const float* __restrict__ W2, const float* __restrict__ b2,
    float* __restrict__ out)
{
    extern __shared__ char smem[];
    const uint32_t sb = smem_u32(smem);
    const int tid = threadIdx.x, wid = tid >> 5, lid = tid & 31;
    const int row0 = blockIdx.x * 64;

    for (int i = tid; i < 2048; i += NT2) {
        int r = i >> 5, kq = i & 31;
        const uint2* src = (const uint2*)vn2 + (size_t)(row0 + r) * VV * 32 + kq;
        float4 a = make_float4(0.f, 0.f, 0.f, 0.f);
#pragma unroll 8
        for (int v = 0; v < VV; v++) {
            uint2 t = src[v * 32];
            float2 f0 = __half22float2(*(__half2*)&t.x);
            float2 f1 = __half22float2(*(__half2*)&t.y);
            a.x += f0.x; a.y += f0.y; a.z += f1.x; a.w += f1.y;
        }
        a.x *= (1.f/32.f); a.y *= (1.f/32.f); a.z *= (1.f/32.f); a.w *= (1.f/32.f);
        *(uint2*)(smem + S_A0 + toff(r, kq << 2, 8)) = make_uint2(
            pack_h2(__float2half_rn(a.x), __float2half_rn(a.y)),
            pack_h2(__float2half_rn(a.z), __float2half_rn(a.w)));
    }
    stage_W(smem, W1h, tid);
    __syncthreads();

    float acc[2][4][4];
    zero_acc(acc);
    mma_pass<128, 8, 16>(sb + S_A0, sb + S_B0, wid, lid, acc);

    const int m0w = (wid >> 2) * 32;
    const int n0w = (wid & 3) * 32;
    const int crow = lid >> 2;
    const int ccol = (lid & 3) * 2;

    __syncthreads();

    float* gfs = (float*)(smem + S_B0);
#pragma unroll
    for (int mf = 0; mf < 2; mf++) {
        int r = m0w + mf * 16 + crow;
#pragma unroll
        for (int nf = 0; nf < 4; nf++) {
            int cn = n0w + nf * 8 + ccol;
            float2 bv = *(const float2*)(b1 + cn);
            gfs[r * 128 + cn]           = fmaxf(acc[mf][nf][0] + bv.x, 0.f);
            gfs[r * 128 + cn + 1]       = fmaxf(acc[mf][nf][1] + bv.y, 0.f);
            gfs[(r + 8) * 128 + cn]     = fmaxf(acc[mf][nf][2] + bv.x, 0.f);
            gfs[(r + 8) * 128 + cn + 1] = fmaxf(acc[mf][nf][3] + bv.y, 0.f);
        }
    }
    float* w2s = (float*)(smem + S_A0);
    float* b2s = w2s + 1280;
    for (int i = tid; i < 1280; i += NT2) w2s[i] = W2[i];
    if (tid < NOUT) b2s[tid] = b2[tid];
    __syncthreads();

    for (int t = tid; t < 64 * NOUT; t += NT2) {
        int row = t / NOUT, o = t - row * NOUT;
        const float* gr = gfs + row * 128;
        float s = b2s[o];
#pragma unroll 8
        for (int k = 0; k < 128; k++) s += gr[k] * w2s[k * NOUT + o];
        out[(size_t)(row0 + row) * NOUT + o] = s;
    }
}

// ---------------- launcher ----------------
extern "C" void kernel_launch(void* const* d_in, const int* in_sizes, int n_in,
                              void* d_out, int out_size)
{
    (void)in_sizes; (void)n_in; (void)out_size;
    const float* x        = (const float*)d_in[0];
    const int*   ei       = (const int*)d_in[1];
    const float* eweights = (const float*)d_in[3];
    const float* vemb     = (const float*)d_in[4];
    const float* W_emb  = (const float*)d_in[5];  const float* b_emb  = (const float*)d_in[6];
    const float* W_gcn  = (const float*)d_in[7];  const float* b_gcn  = (const float*)d_in[8];
    const float* aff_W1 = (const float*)d_in[9];  const float* aff_b1 = (const float*)d_in[10];
    const float* aff_W2 = (const float*)d_in[11]; const float* aff_b2 = (const float*)d_in[12];
    const float* vn_W1  = (const float*)d_in[13]; const float* vn_b1  = (const float*)d_in[14];
    const float* vn_W2  = (const float*)d_in[15]; const float* vn_b2  = (const float*)d_in[16];
    const float* mlp_W1 = (const float*)d_in[17]; const float* mlp_b1 = (const float*)d_in[18];
    const float* mlp_W2 = (const float*)d_in[19]; const float* mlp_b2 = (const float*)d_in[20];
    float* out = (float*)d_out;

    __half *p_h2, *p_aff, *p_vn, *p_vn2, *p_wt0;
    float *p_wc, *p_bc;
    int *p_cntm;
    cudaGetSymbolAddress((void**)&p_h2,   d_h2);
    cudaGetSymbolAddress((void**)&p_aff,  d_aff);
    cudaGetSymbolAddress((void**)&p_cntm, d_cntm);
    cudaGetSymbolAddress((void**)&p_vn,   d_vn);
    cudaGetSymbolAddress((void**)&p_vn2,  d_vn2);
    cudaGetSymbolAddress((void**)&p_wc,   d_wc);
    cudaGetSymbolAddress((void**)&p_bc,   d_bc);
    cudaGetSymbolAddress((void**)&p_wt0,  d_wt0);

    cudaFuncSetAttribute(k_split,  cudaFuncAttributeMaxDynamicSharedMemorySize, 65536);
    cudaFuncSetAttribute(k_xgcn,   cudaFuncAttributeMaxDynamicSharedMemorySize, XG_SMEM);
    cudaFuncSetAttribute(k_mlp2,   cudaFuncAttributeMaxDynamicSharedMemorySize, MLP_SMEM);
    cudaFuncSetAttribute(k_gfhead, cudaFuncAttributeMaxDynamicSharedMemorySize, MLP_SMEM);
    cudaFuncSetAttribute(k_att,    cudaFuncAttributeMaxDynamicSharedMemorySize, ATT_SMEM);

    #define WT0(i) (p_wt0 + (size_t)(i) * 16384)

    // 0) combined weight + fp16 weight prep (slots: 0=Wc, 1=aff1, 2=aff2, 3=vn1, 4=vn2, 5=mlp1)
    k_combine<<<16, 256>>>(W_emb, W_gcn, b_emb, p_wc, p_bc);
    k_split<<<6, 128, 65536>>>(p_wc, aff_W1, aff_W2, vn_W1, vn_W2, mlp_W1, p_wt0);

    // 1) edge count matrix
    cudaMemsetAsync(p_cntm, 0, (size_t)GG * NPG * NPG * sizeof(int));
    k_edges<<<EE/256, 256>>>(ei, p_cntm);

    // 2) fused x-GEMM + GCN -> h2 (fp16)
    k_xgcn<<<GG, NT2, XG_SMEM>>>(x, WT0(0), p_bc, b_gcn, p_cntm, p_h2);

    // 3) affinity MLP
    k_mlp2<<<NN/64, NT2, MLP_SMEM>>>(p_h2, WT0(1), aff_b1, WT0(2), aff_b2, p_aff);

    // 4) attention + pool (HMMA)
    k_att<<<GG, NT2, ATT_SMEM>>>(p_h2, p_aff, vemb, eweights, p_vn);

    // 5) virtual-node MLP
    k_mlp2<<<GG*VV/64, NT2, MLP_SMEM>>>(p_vn, WT0(3), vn_b1, WT0(4), vn_b2, p_vn2);

    // 6) fused mean-over-V + final MLP + head
    k_gfhead<<<GG/64, NT2, MLP_SMEM>>>(p_vn2, WT0(5), mlp_b1, mlp_W2, mlp_b2, out);
}

// round 16
// speedup vs baseline: 1.5752x; 1.0205x over previous
#include <cuda_runtime.h>
#include <cuda_fp16.h>
#include <math.h>
#include <stdint.h>

#define NN   65536
#define GG   1024
#define NPG  64
#define VV   32
#define HH   128
#define EE   1048576
#define NOUT 10

// ---------------- scratch ----------------
__device__ __half d_h2 [NN*HH];
__device__ int    d_cntm[GG*NPG*NPG];
__device__ __half d_vn [GG*VV*HH];
__device__ __half d_vn2[GG*VV*HH];
__device__ float  d_wc [HH*HH];
__device__ float  d_bc [HH];
__device__ __half d_wt0[6*HH*HH];   // weights (transposed [n][k], fp16)

// ================= helpers =================
__device__ __forceinline__ uint32_t smem_u32(const void* p) {
    uint32_t a;
    asm("{ .reg .u64 t; cvta.to.shared.u64 t, %1; cvt.u32.u64 %0, t; }" : "=r"(a) : "l"(p));
    return a;
}
__device__ __forceinline__ uint32_t pack_h2(__half lo, __half hi) {
    return (uint32_t)__half_as_ushort(lo) | ((uint32_t)__half_as_ushort(hi) << 16);
}
// compact blocked K-major tile, AR = atom-rows (rows/8); atom = 8r x 64 h (1KB), SW128
__device__ __forceinline__ uint32_t toff(int r, int k, int AR) {
    uint32_t base = ((((uint32_t)k >> 6) * (uint32_t)AR + ((uint32_t)r >> 3)) << 10)
                  + (((uint32_t)r & 7) << 7) + (((uint32_t)k & 63) << 1);
    return base ^ ((base >> 3) & 0x70);
}
__device__ __forceinline__ uint32_t faddr(uint32_t base, int r, int k, int AR) {
    return base + ((((uint32_t)k >> 6) * (uint32_t)AR + ((uint32_t)r >> 3)) << 10)
         + (((uint32_t)r & 7) << 7) + ((((uint32_t)k & 63) << 1) ^ (((uint32_t)r & 7) << 4));
}
__device__ __forceinline__ void ldsm4(uint32_t* r, uint32_t addr) {
    asm volatile("ldmatrix.sync.aligned.m8n8.x4.shared.b16 {%0,%1,%2,%3}, [%4];"
        : "=r"(r[0]), "=r"(r[1]), "=r"(r[2]), "=r"(r[3]) : "r"(addr));
}
__device__ __forceinline__ void mma16816(float* c, const uint32_t* a, const uint32_t* b) {
    asm volatile("mma.sync.aligned.m16n8k16.row.col.f32.f16.f16.f32 "
        "{%0,%1,%2,%3}, {%4,%5,%6,%7}, {%8,%9}, {%0,%1,%2,%3};"
        : "+f"(c[0]), "+f"(c[1]), "+f"(c[2]), "+f"(c[3])
        : "r"(a[0]), "r"(a[1]), "r"(a[2]), "r"(a[3]), "r"(b[0]), "r"(b[1]));
}

// smem layout: A tile 16KB (64x128 fp16), B tile 32KB (128x128 fp16)
#define S_A0 0
#define S_B0 16384
#define MLP_SMEM 49152
#define XG_SINV 49152
#define XG_SMEM 49408
#define NT2 256

// fused aff-mlp + att layout
#define FA_HT  49152    // hgT (AR=16, K=64) 16KB
#define FA_SEW 65536    // ew fp32, stride 33
#define FA_SMEM (65536 + 64*33*4)

// stage fp32 64x128 A tile -> fp16 (AR=8)
__device__ __forceinline__ void stage_A64f(char* smem, const float* __restrict__ A,
                                           int row0, int tid) {
    const float4* A4 = (const float4*)(A + (size_t)row0 * 128);
#pragma unroll
    for (int i = tid; i < 2048; i += NT2) {
        int r = i >> 5, k = (i & 31) << 2;
        float4 a = A4[i];
        *(uint2*)(smem + S_A0 + toff(r, k, 8)) = make_uint2(
            pack_h2(__float2half_rn(a.x), __float2half_rn(a.y)),
            pack_h2(__float2half_rn(a.z), __float2half_rn(a.w)));
    }
}
// stage fp16 64x128 A tile -> direct copy (AR=8)
__device__ __forceinline__ void stage_A64h(char* smem, const __half* __restrict__ A,
                                           int row0, int tid) {
    const uint2* A2 = (const uint2*)(A + (size_t)row0 * 128);
#pragma unroll
    for (int i = tid; i < 2048; i += NT2) {
        int r = i >> 5, k = (i & 31) << 2;
        *(uint2*)(smem + S_A0 + toff(r, k, 8)) = A2[i];
    }
}
// stage 128x128 fp16 weights into B0 (AR=16)
__device__ __forceinline__ void stage_W(char* smem, const __half* __restrict__ Wh, int tid) {
    const uint2* H = (const uint2*)Wh;
#pragma unroll
    for (int i = tid; i < 4096; i += NT2) {
        int n = i >> 5, k = (i & 31) << 2;
        *(uint2*)(smem + S_B0 + toff(n, k, 16)) = H[i];
    }
}
// one accumulating MMA pass; 8 warps: grid 2(M,32) x 4(N,32)
template<int KMAX, int ARA, int ARB>
__device__ __forceinline__ void mma_pass(uint32_t ab, uint32_t bb, int wid, int lid,
                                         float acc[2][4][4]) {
    const int m0w = (wid >> 2) * 32;
    const int n0w = (wid & 3) * 32;
    const int arow = m0w + (lid & 7) + ((lid >> 3) & 1) * 8;
    const int akad = (lid >> 4) * 8;
    const int brow0 = n0w + (lid & 7) + (lid >> 4) * 8;
    const int bkad = ((lid >> 3) & 1) * 8;
#pragma unroll
    for (int k0 = 0; k0 < KMAX; k0 += 16) {
        uint32_t a[2][4], b[2][4];
        ldsm4(a[0], faddr(ab, arow,      k0 + akad, ARA));
        ldsm4(a[1], faddr(ab, arow + 16, k0 + akad, ARA));
        ldsm4(b[0], faddr(bb, brow0,      k0 + bkad, ARB));
        ldsm4(b[1], faddr(bb, brow0 + 16, k0 + bkad, ARB));
#pragma unroll
        for (int mf = 0; mf < 2; mf++)
#pragma unroll
            for (int nf = 0; nf < 4; nf++)
                mma16816(acc[mf][nf], a[mf], &b[nf >> 1][(nf & 1) * 2]);
    }
}
__device__ __forceinline__ void zero_acc(float acc[2][4][4]) {
#pragma unroll
    for (int mf = 0; mf < 2; mf++)
#pragma unroll
        for (int nf = 0; nf < 4; nf++)
#pragma unroll
            for (int j = 0; j < 4; j++) acc[mf][nf][j] = 0.f;
}

// ---------------- weight combine ----------------
__global__ void __launch_bounds__(256) k_combine(const float* __restrict__ We,
                                                 const float* __restrict__ Wg,
                                                 const float* __restrict__ be,
                                                 float* __restrict__ Wc,
                                                 float* __restrict__ bc) {
    const int col = threadIdx.x & 127;
    const int rr  = threadIdx.x >> 7;
    for (int p = 0; p < 4; p++) {
        int row = blockIdx.x * 8 + p * 2 + rr;
        float s = 0.f;
#pragma unroll 8
        for (int k = 0; k < 128; k++) s += We[row * 128 + k] * Wg[k * 128 + col];
        Wc[row * 128 + col] = s;
    }
    if (blockIdx.x == 0 && threadIdx.x < 128) {
        float s = 0.f;
        for (int k = 0; k < 128; k++) s += be[k] * Wg[k * 128 + col];
        bc[col] = s;
    }
}

// ---------------- weight prep: transpose + fp16 round ----------------
__global__ void __launch_bounds__(128) k_split(
    const float* W0, const float* W1, const float* W2, const float* W3,
    const float* W4, const float* W5,
    __half* wt0)
{
    extern __shared__ float s[];
    const float* Ws[6] = {W0, W1, W2, W3, W4, W5};
    const float* W = Ws[blockIdx.x];
    for (int i = threadIdx.x; i < 16384; i += 128) s[i] = W[i];
    __syncthreads();
    const int n = threadIdx.x;
    uint32_t* o0 = (uint32_t*)(wt0 + (size_t)blockIdx.x * 16384 + n * 128);
    for (int k = 0; k < 128; k += 2) {
        float v0 = s[k * 128 + n], v1 = s[(k + 1) * 128 + n];
        o0[k >> 1] = pack_h2(__float2half_rn(v0), __float2half_rn(v1));
    }
}

// ------------- fused x-GEMM + GCN (1 graph per block, 64 rows) -------------
__global__ void __launch_bounds__(NT2, 3) k_xgcn(
    const float* __restrict__ x,
    const __half* __restrict__ Wch,
    const float* __restrict__ bc, const float* __restrict__ b_gcn,
    const int* __restrict__ cntm,
    __half* __restrict__ h2)
{
    extern __shared__ char smem[];
    const uint32_t sb = smem_u32(smem);
    const int tid = threadIdx.x, wid = tid >> 5, lid = tid & 31;
    const int g = blockIdx.x;
    const int row0 = g * 64;
    const int* cg = cntm + ((size_t)g << 12);
    float* sinv = (float*)(smem + XG_SINV);

    stage_A64f(smem, x, row0, tid);
    stage_W(smem, Wch, tid);
    if (tid < 64) {
        int deg = 0;
#pragma unroll 8
        for (int s = 0; s < 64; s++) deg += cg[(s << 6) + tid];
        sinv[tid] = rsqrtf((float)deg + 1.f);
    }
    __syncthreads();

    float acc[2][4][4];
    zero_acc(acc);
    mma_pass<128, 8, 16>(sb + S_A0, sb + S_B0, wid, lid, acc);

    const int m0w = (wid >> 2) * 32;
    const int n0w = (wid & 3) * 32;
    const int crow = lid >> 2;
    const int ccol = (lid & 3) * 2;

    __syncthreads();

#pragma unroll
    for (int mf = 0; mf < 2; mf++) {
        int r = m0w + mf * 16 + crow;
        float iv0 = sinv[r], iv1 = sinv[r + 8];
#pragma unroll
        for (int nf = 0; nf < 4; nf++) {
            int cn = n0w + nf * 8 + ccol;
            float2 bv = *(const float2*)(bc + cn);
            *(__half*)(smem + S_B0 + toff(cn,     r,     16)) =
                __float2half_rn((acc[mf][nf][0] + bv.x) * iv0);
            *(__half*)(smem + S_B0 + toff(cn + 1, r,     16)) =
                __float2half_rn((acc[mf][nf][1] + bv.y) * iv0);
            *(__half*)(smem + S_B0 + toff(cn,     r + 8, 16)) =
                __float2half_rn((acc[mf][nf][2] + bv.x) * iv1);
            *(__half*)(smem + S_B0 + toff(cn + 1, r + 8, 16)) =
                __float2half_rn((acc[mf][nf][3] + bv.y) * iv1);
        }
    }
    for (int i = tid; i < 4096; i += NT2) {
        int s = i >> 6, d = i & 63;
        float v = (float)cg[i] + (s == d ? 1.f : 0.f);
        *(__half*)(smem + S_A0 + toff(d, s, 8)) = __float2half_rn(v);
    }
    __syncthreads();

    zero_acc(acc);
    mma_pass<64, 8, 16>(sb + S_A0, sb + S_B0, wid, lid, acc);

#pragma unroll
    for (int mf = 0; mf < 2; mf++) {
        int r = m0w + mf * 16 + crow;
        float iv0 = sinv[r], iv1 = sinv[r + 8];
        __half* C0 = h2 + (size_t)(row0 + r) * 128;
#pragma unroll
        for (int nf = 0; nf < 4; nf++) {
            int cn = n0w + nf * 8 + ccol;
            float2 bg = *(const float2*)(b_gcn + cn);
            *(uint32_t*)(C0 + cn) = pack_h2(
                __float2half_rn(fmaxf(acc[mf][nf][0] * iv0 + bg.x, 0.f)),
                __float2half_rn(fmaxf(acc[mf][nf][1] * iv0 + bg.y, 0.f)));
            *(uint32_t*)(C0 + 8 * 128 + cn) = pack_h2(
                __float2half_rn(fmaxf(acc[mf][nf][2] * iv1 + bg.x, 0.f)),
                __float2half_rn(fmaxf(acc[mf][nf][3] * iv1 + bg.y, 0.f)));
        }
    }
}

// ---------------- fused 2-layer MLP (64-row tiles, fp16 in/out) ----------------
__global__ void __launch_bounds__(NT2, 3) k_mlp2(
    const __half* __restrict__ A,
    const __half* __restrict__ W1h, const float* __restrict__ b1,
    const __half* __restrict__ W2h, const float* __restrict__ b2,
    __half* __restrict__ Out)
{
    extern __shared__ char smem[];
    const uint32_t sb = smem_u32(smem);
    const int tid = threadIdx.x, wid = tid >> 5, lid = tid & 31;
    const int row0 = blockIdx.x * 64;

    stage_A64h(smem, A, row0, tid);
    stage_W(smem, W1h, tid);
    __syncthreads();

    float acc[2][4][4];
    zero_acc(acc);
    mma_pass<128, 8, 16>(sb + S_A0, sb + S_B0, wid, lid, acc);

    const int m0w = (wid >> 2) * 32;
    const int n0w = (wid & 3) * 32;
    const int crow = lid >> 2;
    const int ccol = (lid & 3) * 2;

    __syncthreads();

#pragma unroll
    for (int mf = 0; mf < 2; mf++) {
        int r = m0w + mf * 16 + crow;
#pragma unroll
        for (int nf = 0; nf < 4; nf++) {
            int cn = n0w + nf * 8 + ccol;
            float2 bv = *(const float2*)(b1 + cn);
            *(uint32_t*)(smem + S_A0 + toff(r,     cn, 8)) = pack_h2(
                __float2half_rn(fmaxf(acc[mf][nf][0] + bv.x, 0.f)),
                __float2half_rn(fmaxf(acc[mf][nf][1] + bv.y, 0.f)));
            *(uint32_t*)(smem + S_A0 + toff(r + 8, cn, 8)) = pack_h2(
                __float2half_rn(fmaxf(acc[mf][nf][2] + bv.x, 0.f)),
                __float2half_rn(fmaxf(acc[mf][nf][3] + bv.y, 0.f)));
        }
    }
    stage_W(smem, W2h, tid);
    __syncthreads();

    zero_acc(acc);
    mma_pass<128, 8, 16>(sb + S_A0, sb + S_B0, wid, lid, acc);

#pragma unroll
    for (int mf = 0; mf < 2; mf++) {
        int gr = row0 + m0w + mf * 16 + crow;
        __half* C0 = Out + (size_t)gr * 128;
#pragma unroll
        for (int nf = 0; nf < 4; nf++) {
            int cn = n0w + nf * 8 + ccol;
            float2 bv = *(const float2*)(b2 + cn);
            *(uint32_t*)(C0 + cn) = pack_h2(
                __float2half_rn(acc[mf][nf][0] + bv.x),
                __float2half_rn(acc[mf][nf][1] + bv.y));
            *(uint32_t*)(C0 + 8 * 128 + cn) = pack_h2(
                __float2half_rn(acc[mf][nf][2] + bv.x),
                __float2half_rn(acc[mf][nf][3] + bv.y));
        }
    }
}

// ---------------- edge count matrix ----------------
__global__ void k_edges(const int* __restrict__ ei, int* __restrict__ cntm) {
    int e = blockIdx.x * blockDim.x + threadIdx.x;
    int s = ei[e];
    int d = ei[EE + e];
    if ((unsigned)s >= NN || (unsigned)d >= NN) return;
    int g = s >> 6;
    atomicAdd(&cntm[(g << 12) | ((s & 63) << 6) | (d & 63)], 1);
}

// -------- fused affinity MLP + attention + pool (1 graph per block) --------
__global__ void __launch_bounds__(NT2, 2) k_affatt(
    const __half* __restrict__ h2,
    const __half* __restrict__ W1h, const float* __restrict__ b1,
    const __half* __restrict__ W2h, const float* __restrict__ b2,
    const float* __restrict__ vemb,
    const float* __restrict__ eweights,
    __half* __restrict__ vn_out)
{
    extern __shared__ char smem[];
    const uint32_t sb = smem_u32(smem);
    const int tid = threadIdx.x, wid = tid >> 5, lid = tid & 31;
    const int g = blockIdx.x;
    float* sew = (float*)(smem + FA_SEW);      // [n][v] stride 33

    // stage h2 ONCE: A tile (AR=8) for MLP + transposed hgT (AR=16,K=64) for pooling
    {
        const uint2* hg2 = (const uint2*)(h2 + (size_t)g * NPG * HH);
        for (int i = tid; i < 2048; i += NT2) {
            int n = i >> 5, h4 = (i & 31) << 2;
            uint2 t = hg2[i];
            *(uint2*)(smem + S_A0 + toff(n, h4, 8)) = t;
            __half2 p0 = *(__half2*)&t.x;
            __half2 p1 = *(__half2*)&t.y;
            *(__half*)(smem + FA_HT + toff(h4,     n, 16)) = __low2half(p0);
            *(__half*)(smem + FA_HT + toff(h4 + 1, n, 16)) = __high2half(p0);
            *(__half*)(smem + FA_HT + toff(h4 + 2, n, 16)) = __low2half(p1);
            *(__half*)(smem + FA_HT + toff(h4 + 3, n, 16)) = __high2half(p1);
        }
    }
    stage_W(smem, W1h, tid);
    __syncthreads();

    // MLP phase 1
    float acc[2][4][4];
    zero_acc(acc);
    mma_pass<128, 8, 16>(sb + S_A0, sb + S_B0, wid, lid, acc);

    const int m0w = (wid >> 2) * 32;
    const int n0w = (wid & 3) * 32;
    const int crow = lid >> 2;
    const int ccol = (lid & 3) * 2;

    __syncthreads();

    // relu(t1) restage into A0
#pragma unroll
    for (int mf = 0; mf < 2; mf++) {
        int r = m0w + mf * 16 + crow;
#pragma unroll
        for (int nf = 0; nf < 4; nf++) {
            int cn = n0w + nf * 8 + ccol;
            float2 bv = *(const float2*)(b1 + cn);
            *(uint32_t*)(smem + S_A0 + toff(r,     cn, 8)) = pack_h2(
                __float2half_rn(fmaxf(acc[mf][nf][0] + bv.x, 0.f)),
                __float2half_rn(fmaxf(acc[mf][nf][1] + bv.y, 0.f)));
            *(uint32_t*)(smem + S_A0 + toff(r + 8, cn, 8)) = pack_h2(
                __float2half_rn(fmaxf(acc[mf][nf][2] + bv.x, 0.f)),
                __float2half_rn(fmaxf(acc[mf][nf][3] + bv.y, 0.f)));
        }
    }
    stage_W(smem, W2h, tid);
    __syncthreads();

    // MLP phase 2 -> aff in regs
    zero_acc(acc);
    mma_pass<128, 8, 16>(sb + S_A0, sb + S_B0, wid, lid, acc);
    __syncthreads();

    // aff (+b2) -> A0 fp16 tile; vemb -> B0 rows 0-31 (fp16)
#pragma unroll
    for (int mf = 0; mf < 2; mf++) {
        int r = m0w + mf * 16 + crow;
#pragma unroll
        for (int nf = 0; nf < 4; nf++) {
            int cn = n0w + nf * 8 + ccol;
            float2 bv = *(const float2*)(b2 + cn);
            *(uint32_t*)(smem + S_A0 + toff(r,     cn, 8)) = pack_h2(
                __float2half_rn(acc[mf][nf][0] + bv.x),
                __float2half_rn(acc[mf][nf][1] + bv.y));
            *(uint32_t*)(smem + S_A0 + toff(r + 8, cn, 8)) = pack_h2(
                __float2half_rn(acc[mf][nf][2] + bv.x),
                __float2half_rn(acc[mf][nf][3] + bv.y));
        }
    }
    {
        const float4* vg4 = (const float4*)(vemb + (size_t)g * VV * HH);
        for (int i = tid; i < 1024; i += NT2) {
            int v = i >> 5, k = (i & 31) << 2;
            float4 a = vg4[i];
            *(uint2*)(smem + S_B0 + toff(v, k, 16)) = make_uint2(
                pack_h2(__float2half_rn(a.x), __float2half_rn(a.y)),
                pack_h2(__float2half_rn(a.z), __float2half_rn(a.w)));
        }
    }
    __syncthreads();

    // score MMA: att[64][32] (useful in warps with n0w==0)
    zero_acc(acc);
    mma_pass<128, 8, 16>(sb + S_A0, sb + S_B0, wid, lid, acc);

    if (n0w == 0) {
        const float* ew_g = eweights + (size_t)g * NPG * VV;
        const float scale = 0.08838834764831845f;
#pragma unroll
        for (int mf = 0; mf < 2; mf++) {
            int n = m0w + mf * 16 + crow;
#pragma unroll
            for (int nf = 0; nf < 4; nf++) {
                int v = nf * 8 + ccol;
#pragma unroll
                for (int j = 0; j < 4; j++) {
                    int nn = n + (j >> 1) * 8;
                    int vv = v + (j & 1);
                    float att = acc[mf][nf][j] * scale;
                    float sg = 1.f / (1.f + expf(-att));
                    sew[nn * 33 + vv] = ew_g[nn * 32 + vv] * (1.f + sg);
                }
            }
        }
    }
    __syncthreads();

    // row-normalize (stride 33: conflict-free)
    if (tid < NPG) {
        float rs = 0.f;
#pragma unroll 8
        for (int v = 0; v < VV; v++) rs += sew[tid * 33 + v];
        float ivr = 1.f / ((rs == 0.f) ? 1.f : rs);
#pragma unroll 8
        for (int v = 0; v < VV; v++) sew[tid * 33 + v] *= ivr;
    }
    __syncthreads();

    // restage ewT [v][n] fp16 into A0 (AR=4)
    for (int i = tid; i < 2048; i += NT2) {
        int v = i >> 6, n = i & 63;
        *(__half*)(smem + S_A0 + toff(v, n, 4)) = __float2half_rn(sew[n * 33 + v]);
    }
    __syncthreads();

    // pooling MMA: vn[32][128] = ewT @ hgT (warps with m0w==0 useful)
    zero_acc(acc);
    mma_pass<64, 4, 16>(sb + S_A0, sb + FA_HT, wid, lid, acc);

    if (m0w == 0) {
#pragma unroll
        for (int mf = 0; mf < 2; mf++) {
            int v = mf * 16 + crow;
            __half* C0 = vn_out + (size_t)(g * VV + v) * 128;
            __half* C8 = vn_out + (size_t)(g * VV + v + 8) * 128;
#pragma unroll
            for (int nf = 0; nf < 4; nf++) {
                int cn = n0w + nf * 8 + ccol;
                *(uint32_t*)(C0 + cn) = pack_h2(
                    __float2half_rn(acc[mf][nf][0]), __float2half_rn(acc[mf][nf][1]));
                *(uint32_t*)(C8 + cn) = pack_h2(
                    __float2half_rn(acc[mf][nf][2]), __float2half_rn(acc[mf][nf][3]));
            }
        }
    }
}

// -------- fused tail: gf = meanV(vn2); out = relu(gf@W1+b1)@W2 + b2 --------
__global__ void __launch_bounds__(NT2, 3) k_gfhead(
    const __half* __restrict__ vn2,
    const __half* __restrict__ W1h, const float* __restrict__ b1,
    const float* __restrict__ W2, const float* __restrict__ b2,
    float* __restrict__ out)
{
    extern __shared__ char smem[];
    const uint32_t sb = smem_u32(smem);
    const int tid = threadIdx.x, wid = tid >> 5, lid = tid & 31;
    const int row0 = blockIdx.x * 64;

    for (int i = tid; i < 2048; i += NT2) {
        int r = i >> 5, kq = i & 31;
        const uint2* src = (const uint2*)vn2 + (size_t)(row0 + r) * VV * 32 + kq;
        float4 a = make_float4(0.f, 0.f, 0.f, 0.f);
#pragma unroll 8
        for (int v = 0; v < VV; v++) {
            uint2 t = src[v * 32];
            float2 f0 = __half22float2(*(__half2*)&t.x);
            float2 f1 = __half22float2(*(__half2*)&t.y);
            a.x += f0.x; a.y += f0.y; a.z += f1.x; a.w += f1.y;
        }
        a.x *= (1.f/32.f); a.y *= (1.f/32.f); a.z *= (1.f/32.f); a.w *= (1.f/32.f);
        *(uint2*)(smem + S_A0 + toff(r, kq << 2, 8)) = make_uint2(
            pack_h2(__float2half_rn(a.x), __float2half_rn(a.y)),
            pack_h2(__float2half_rn(a.z), __float2half_rn(a.w)));
    }
    stage_W(smem, W1h, tid);
    __syncthreads();

    float acc[2][4][4];
    zero_acc(acc);
    mma_pass<128, 8, 16>(sb + S_A0, sb + S_B0, wid, lid, acc);

    const int m0w = (wid >> 2) * 32;
    const int n0w = (wid & 3) * 32;
    const int crow = lid >> 2;
    const int ccol = (lid & 3) * 2;

    __syncthreads();

    float* gfs = (float*)(smem + S_B0);
#pragma unroll
    for (int mf = 0; mf < 2; mf++) {
        int r = m0w + mf * 16 + crow;
#pragma unroll
        for (int nf = 0; nf < 4; nf++) {
            int cn = n0w + nf * 8 + ccol;
            float2 bv = *(const float2*)(b1 + cn);
            gfs[r * 128 + cn]           = fmaxf(acc[mf][nf][0] + bv.x, 0.f);
            gfs[r * 128 + cn + 1]       = fmaxf(acc[mf][nf][1] + bv.y, 0.f);
            gfs[(r + 8) * 128 + cn]     = fmaxf(acc[mf][nf][2] + bv.x, 0.f);
            gfs[(r + 8) * 128 + cn + 1] = fmaxf(acc[mf][nf][3] + bv.y, 0.f);
        }
    }
    float* w2s = (float*)(smem + S_A0);
    float* b2s = w2s + 1280;
    for (int i = tid; i < 1280; i += NT2) w2s[i] = W2[i];
    if (tid < NOUT) b2s[tid] = b2[tid];
    __syncthreads();

    for (int t = tid; t < 64 * NOUT; t += NT2) {
        int row = t / NOUT, o = t - row * NOUT;
        const float* gr = gfs + row * 128;
        float s = b2s[o];
#pragma unroll 8
        for (int k = 0; k < 128; k++) s += gr[k] * w2s[k * NOUT + o];
        out[(size_t)(row0 + row) * NOUT + o] = s;
    }
}

// ---------------- launcher ----------------
extern "C" void kernel_launch(void* const* d_in, const int* in_sizes, int n_in,
                              void* d_out, int out_size)
{
    (void)in_sizes; (void)n_in; (void)out_size;
    const float* x        = (const float*)d_in[0];
    const int*   ei       = (const int*)d_in[1];
    const float* eweights = (const float*)d_in[3];
    const float* vemb     = (const float*)d_in[4];
    const float* W_emb  = (const float*)d_in[5];  const float* b_emb  = (const float*)d_in[6];
    const float* W_gcn  = (const float*)d_in[7];  const float* b_gcn  = (const float*)d_in[8];
    const float* aff_W1 = (const float*)d_in[9];  const float* aff_b1 = (const float*)d_in[10];
    const float* aff_W2 = (const float*)d_in[11]; const float* aff_b2 = (const float*)d_in[12];
    const float* vn_W1  = (const float*)d_in[13]; const float* vn_b1  = (const float*)d_in[14];
    const float* vn_W2  = (const float*)d_in[15]; const float* vn_b2  = (const float*)d_in[16];
    const float* mlp_W1 = (const float*)d_in[17]; const float* mlp_b1 = (const float*)d_in[18];
    const float* mlp_W2 = (const float*)d_in[19]; const float* mlp_b2 = (const float*)d_in[20];
    float* out = (float*)d_out;

    __half *p_h2, *p_vn, *p_vn2, *p_wt0;
    float *p_wc, *p_bc;
    int *p_cntm;
    cudaGetSymbolAddress((void**)&p_h2,   d_h2);
    cudaGetSymbolAddress((void**)&p_cntm, d_cntm);
    cudaGetSymbolAddress((void**)&p_vn,   d_vn);
    cudaGetSymbolAddress((void**)&p_vn2,  d_vn2);
    cudaGetSymbolAddress((void**)&p_wc,   d_wc);
    cudaGetSymbolAddress((void**)&p_bc,   d_bc);
    cudaGetSymbolAddress((void**)&p_wt0,  d_wt0);

    cudaFuncSetAttribute(k_split,  cudaFuncAttributeMaxDynamicSharedMemorySize, 65536);
    cudaFuncSetAttribute(k_xgcn,   cudaFuncAttributeMaxDynamicSharedMemorySize, XG_SMEM);
    cudaFuncSetAttribute(k_mlp2,   cudaFuncAttributeMaxDynamicSharedMemorySize, MLP_SMEM);
    cudaFuncSetAttribute(k_gfhead, cudaFuncAttributeMaxDynamicSharedMemorySize, MLP_SMEM);
    cudaFuncSetAttribute(k_affatt, cudaFuncAttributeMaxDynamicSharedMemorySize, FA_SMEM);

    #define WT0(i) (p_wt0 + (size_t)(i) * 16384)

    // 0) combined weight + fp16 weight prep (slots: 0=Wc, 1=aff1, 2=aff2, 3=vn1, 4=vn2, 5=mlp1)
    k_combine<<<16, 256>>>(W_emb, W_gcn, b_emb, p_wc, p_bc);
    k_split<<<6, 128, 65536>>>(p_wc, aff_W1, aff_W2, vn_W1, vn_W2, mlp_W1, p_wt0);

    // 1) edge count matrix
    cudaMemsetAsync(p_cntm, 0, (size_t)GG * NPG * NPG * sizeof(int));
    k_edges<<<EE/256, 256>>>(ei, p_cntm);

    // 2) fused x-GEMM + GCN -> h2 (fp16)
    k_xgcn<<<GG, NT2, XG_SMEM>>>(x, WT0(0), p_bc, b_gcn, p_cntm, p_h2);

    // 3) fused affinity MLP + attention + pool -> vn
    k_affatt<<<GG, NT2, FA_SMEM>>>(p_h2, WT0(1), aff_b1, WT0(2), aff_b2,
                                   vemb, eweights, p_vn);

    // 4) virtual-node MLP
    k_mlp2<<<GG*VV/64, NT2, MLP_SMEM>>>(p_vn, WT0(3), vn_b1, WT0(4), vn_b2, p_vn2);

    // 5) fused mean-over-V + final MLP + head
    k_gfhead<<<GG/64, NT2, MLP_SMEM>>>(p_vn2, WT0(5), mlp_b1, mlp_W2, mlp_b2, out);
}